// round 10
// baseline (speedup 1.0000x reference)
#include <cuda_runtime.h>
#include <cuda_bf16.h>
#include <math.h>
#include <stdint.h>

// ---------------------------------------------------------------------------
// Problem constants
// ---------------------------------------------------------------------------
namespace {
constexpr int cB   = 2;
constexpr int cS   = 2048;
constexpr int cHID = 2048;
constexpr int cNH  = 16;
constexpr int cNKV = 8;
constexpr int cHD  = 128;
constexpr float cEPS   = 1e-6f;
constexpr float cSCALE = 0.08838834764831845f;  // 128^-0.5
constexpr int cM   = cB * cS;        // 4096
constexpr int cNQKV = 4096;          // fused QKV output width
}

// ---------------------------------------------------------------------------
// Scratch (device globals -- no runtime allocation allowed)
// ---------------------------------------------------------------------------
__device__ float g_ahf [(size_t)cM * cHID];        // tf32-rounded hidden
__device__ float g_qkv [(size_t)cM * cNQKV];       // fused QKV projection out
__device__ float g_att [(size_t)cM * cNH * cHD];   // attn out pre-Wo (tf32-rounded)
__device__ float g_wt  [(size_t)cNQKV * cHID];     // [wq|wk|wv]^T tf32-rounded
__device__ float g_wot [(size_t)cHID * cHID];      // wo^T tf32-rounded
__device__ float g_vt  [(size_t)cB * cNKV * cHD * cS]; // V^T fp32 [b][kvh][d][s]

// bf16 hi/lo planes for attention QK, head-major layout [b][h][s][d]
__device__ __nv_bfloat16 g_q2hi[(size_t)cB * cNH  * cS * cHD];
__device__ __nv_bfloat16 g_q2lo[(size_t)cB * cNH  * cS * cHD];
__device__ __nv_bfloat16 g_k2hi[(size_t)cB * cNKV * cS * cHD];
__device__ __nv_bfloat16 g_k2lo[(size_t)cB * cNKV * cS * cHD];

// ---------------------------------------------------------------------------
// PTX helpers (portable: sm_80+)
// ---------------------------------------------------------------------------
__device__ __forceinline__ uint32_t smem_u32(const void* p) {
    uint32_t a;
    asm("{ .reg .u64 t; cvta.to.shared.u64 t, %1; cvt.u32.u64 %0, t; }"
        : "=r"(a) : "l"(p));
    return a;
}
__device__ __forceinline__ void cp_async16(uint32_t saddr, const void* gaddr) {
    asm volatile("cp.async.cg.shared.global [%0], [%1], 16;"
                 :: "r"(saddr), "l"(gaddr) : "memory");
}
#define CP_COMMIT()  asm volatile("cp.async.commit_group;" ::: "memory")
#define CP_WAIT(N)   asm volatile("cp.async.wait_group %0;" :: "n"(N) : "memory")

__device__ __forceinline__ void ldm_x4(uint32_t* r, uint32_t addr) {
    asm volatile("ldmatrix.sync.aligned.m8n8.x4.shared.b16 {%0,%1,%2,%3}, [%4];"
                 : "=r"(r[0]), "=r"(r[1]), "=r"(r[2]), "=r"(r[3]) : "r"(addr));
}
__device__ __forceinline__ void mma16816(float* d, const uint32_t* a,
                                         const uint32_t* b) {
    asm volatile(
        "mma.sync.aligned.m16n8k16.row.col.f32.bf16.bf16.f32 "
        "{%0,%1,%2,%3}, {%4,%5,%6,%7}, {%8,%9}, {%0,%1,%2,%3};"
        : "+f"(d[0]), "+f"(d[1]), "+f"(d[2]), "+f"(d[3])
        : "r"(a[0]), "r"(a[1]), "r"(a[2]), "r"(a[3]), "r"(b[0]), "r"(b[1]));
}
__device__ __forceinline__ void mma1688_tf32(float* d, const uint32_t* a,
                                             const uint32_t* b) {
    asm volatile(
        "mma.sync.aligned.m16n8k8.row.col.f32.tf32.tf32.f32 "
        "{%0,%1,%2,%3}, {%4,%5,%6,%7}, {%8,%9}, {%0,%1,%2,%3};"
        : "+f"(d[0]), "+f"(d[1]), "+f"(d[2]), "+f"(d[3])
        : "r"(a[0]), "r"(a[1]), "r"(a[2]), "r"(a[3]), "r"(b[0]), "r"(b[1]));
}
__device__ __forceinline__ uint32_t sw128(uint32_t off) {
    return off ^ ((off >> 3) & 0x70);
}
__device__ __forceinline__ float tf32r(float x) {
    uint32_t u;
    asm("cvt.rna.tf32.f32 %0, %1;" : "=r"(u) : "f"(x));
    return __uint_as_float(u);
}
__device__ __forceinline__ uint32_t tf32b(float x) {
    uint32_t u;
    asm("cvt.rna.tf32.f32 %0, %1;" : "=r"(u) : "f"(x));
    return u;
}

// ---------------------------------------------------------------------------
// Prep kernels
// ---------------------------------------------------------------------------
__global__ __launch_bounds__(256) void round_tf32_kernel(
    const float* __restrict__ X, float* __restrict__ Y)
{
    size_t e = ((size_t)blockIdx.x * 256 + threadIdx.x) * 4;
    float4 x = *(const float4*)(X + e);
    x.x = tf32r(x.x); x.y = tf32r(x.y); x.z = tf32r(x.z); x.w = tf32r(x.w);
    *(float4*)(Y + e) = x;
}

__global__ __launch_bounds__(256) void cvt_wT_kernel(
    const float* __restrict__ W, float* __restrict__ Y, int K, int N)
{
    __shared__ float t[32][33];
    int n0 = blockIdx.x * 32;
    int k0 = blockIdx.y * 32;
    int tx = threadIdx.x;
    int ty = threadIdx.y;
#pragma unroll
    for (int i = 0; i < 32; i += 8)
        t[ty + i][tx] = W[(size_t)(k0 + ty + i) * N + n0 + tx];
    __syncthreads();
#pragma unroll
    for (int i = 0; i < 32; i += 8) {
        int n = n0 + ty + i;
        int k = k0 + tx;
        Y[(size_t)n * K + k] = tf32r(t[tx][ty + i]);
    }
}

// V^T: g_qkv v-section [b][s][kvh*128+d] -> g_vt [b][kvh][d][s], tf32-rounded
__global__ __launch_bounds__(256) void vT_kernel(
    const float* __restrict__ qkv, float* __restrict__ vt)
{
    __shared__ float t[32][33];
    const int s0 = blockIdx.x * 32;
    const int d0 = blockIdx.y * 32;
    const int bk = blockIdx.z;           // b*8 + kvh
    const int b  = bk >> 3;
    const int kvh = bk & 7;
    const int tx = threadIdx.x;
    const int ty = threadIdx.y;
#pragma unroll
    for (int i = 0; i < 32; i += 8)
        t[ty + i][tx] = qkv[(size_t)(b * cS + s0 + ty + i) * cNQKV +
                            3072 + kvh * cHD + d0 + tx];
    __syncthreads();
#pragma unroll
    for (int i = 0; i < 32; i += 8)
        vt[((size_t)bk * cHD + d0 + ty + i) * cS + s0 + tx] =
            tf32r(t[tx][ty + i]);
}

// ---------------------------------------------------------------------------
// TF32 HMMA GEMM: C[M,N] = A[M,K] @ B[N,K]^T (row-major fp32, tf32-prerounded)
// CTA tile 128x256, BK=32, 4-stage cp.async, SW128, warp tile 64x64.
// ---------------------------------------------------------------------------
namespace {
constexpr int GBM = 128, GBN = 256, GBK = 32;
constexpr int NSTAGE = 4;
constexpr int A_BYTES = GBM * GBK * 4;              // 16KB
constexpr int B_BYTES = GBN * GBK * 4;              // 32KB
constexpr int STAGE_BYTES = A_BYTES + B_BYTES;      // 48KB
constexpr int GEMM_SMEM   = NSTAGE * STAGE_BYTES;   // 192KB
}

__device__ __forceinline__ void gemm_load_stage(
    const float* __restrict__ Ag, const float* __restrict__ Bg,
    int K, int it, uint32_t stage_base, int tid)
{
#pragma unroll
    for (int i = 0; i < 4; i++) {
        int idx = tid + (i << 8);
        int row = idx >> 3;
        int c4  = idx & 7;
        uint32_t sw = sw128((uint32_t)(row * 128 + c4 * 16));
        cp_async16(stage_base + sw,
                   Ag + (size_t)row * K + (size_t)it * GBK + c4 * 4);
    }
#pragma unroll
    for (int i = 0; i < 8; i++) {
        int idx = tid + (i << 8);
        int row = idx >> 3;
        int c4  = idx & 7;
        uint32_t sw = sw128((uint32_t)(row * 128 + c4 * 16));
        cp_async16(stage_base + A_BYTES + sw,
                   Bg + (size_t)row * K + (size_t)it * GBK + c4 * 4);
    }
}

__global__ __launch_bounds__(256, 1)
void gemm_tf32_kernel(const float* __restrict__ A,
                      const float* __restrict__ B,
                      float* __restrict__ C, int M, int N, int K)
{
    extern __shared__ char smraw[];
    const uint32_t sbase = smem_u32(smraw);

    const int tid  = threadIdx.x;
    const int wid  = tid >> 5;
    const int lane = tid & 31;
    const int m0 = blockIdx.y * GBM;
    const int n0 = blockIdx.x * GBN;
    const int mw = (wid >> 2) * 64;
    const int nw = (wid & 3) * 64;

    const float* Ag = A + (size_t)m0 * K;
    const float* Bg = B + (size_t)n0 * K;
    const int KITERS = K / GBK;

    float acc[4][8][4];
#pragma unroll
    for (int i = 0; i < 4; i++)
#pragma unroll
        for (int j = 0; j < 8; j++)
#pragma unroll
            for (int r = 0; r < 4; r++) acc[i][j][r] = 0.f;

    const int a_row = lane & 15;
    const int a_cb  = (lane >> 4) * 16;
    const int b_row = (lane & 7) + ((lane >> 4) & 1) * 8;
    const int b_cb  = ((lane >> 3) & 1) * 16;

#pragma unroll
    for (int s = 0; s < NSTAGE - 1; s++) {
        gemm_load_stage(Ag, Bg, K, s, sbase + s * STAGE_BYTES, tid);
        CP_COMMIT();
    }

    for (int it = 0; it < KITERS; ++it) {
        CP_WAIT(NSTAGE - 2);
        __syncthreads();

        int nx = it + NSTAGE - 1;
        if (nx < KITERS)
            gemm_load_stage(Ag, Bg, K, nx,
                            sbase + (nx % NSTAGE) * STAGE_BYTES, tid);
        CP_COMMIT();

        const uint32_t sa = sbase + (it % NSTAGE) * STAGE_BYTES;
        const uint32_t sb = sa + A_BYTES;

#pragma unroll
        for (int ks = 0; ks < 4; ks++) {
            uint32_t af[4][4], bf[4][4];
#pragma unroll
            for (int mi = 0; mi < 4; mi++) {
                uint32_t off = (uint32_t)((mw + 16 * mi + a_row) * 128 +
                                          ks * 32 + a_cb);
                ldm_x4(af[mi], sa + sw128(off));
            }
#pragma unroll
            for (int njp = 0; njp < 4; njp++) {
                uint32_t off = (uint32_t)((nw + 16 * njp + b_row) * 128 +
                                          ks * 32 + b_cb);
                ldm_x4(bf[njp], sb + sw128(off));
            }
#pragma unroll
            for (int mi = 0; mi < 4; mi++)
#pragma unroll
                for (int njp = 0; njp < 4; njp++) {
                    mma1688_tf32(acc[mi][2 * njp],     af[mi], bf[njp]);
                    mma1688_tf32(acc[mi][2 * njp + 1], af[mi], bf[njp] + 2);
                }
        }
    }

    const int g = lane >> 2;
    const int t = lane & 3;
#pragma unroll
    for (int mi = 0; mi < 4; mi++) {
#pragma unroll
        for (int nj = 0; nj < 8; nj++) {
            int r0 = m0 + mw + 16 * mi + g;
            int cc = n0 + nw + 8 * nj + t * 2;
            *(float2*)(C + (size_t)r0 * N + cc) =
                make_float2(acc[mi][nj][0], acc[mi][nj][1]);
            *(float2*)(C + (size_t)(r0 + 8) * N + cc) =
                make_float2(acc[mi][nj][2], acc[mi][nj][3]);
        }
    }
}

// ---------------------------------------------------------------------------
// RMSNorm + RoPE + hi/lo bf16 split for Q and K only (V handled by vT_kernel).
// ---------------------------------------------------------------------------
__global__ __launch_bounds__(128) void norm_rope_split_kernel(
    const float* __restrict__ cosp, const float* __restrict__ sinp,
    const float* __restrict__ qw,   const float* __restrict__ kw)
{
    const int slot = blockIdx.x;
    const int bs   = blockIdx.y;
    const int d    = threadIdx.x;
    const int b    = bs >> 11;
    const int s    = bs & 2047;

    const float* src;
    const float* w;
    __nv_bfloat16 *dhi, *dlo;
    if (slot < 16) {
        src = g_qkv + (size_t)bs * cNQKV + slot * cHD;
        w = qw;
        size_t dst = ((size_t)(b * cNH + slot) * cS + s) * cHD;
        dhi = g_q2hi + dst; dlo = g_q2lo + dst;
    } else {
        src = g_qkv + (size_t)bs * cNQKV + 2048 + (slot - 16) * cHD;
        w = kw;
        size_t dst = ((size_t)(b * cNKV + (slot - 16)) * cS + s) * cHD;
        dhi = g_k2hi + dst; dlo = g_k2lo + dst;
    }
    float x = src[d];
    float v = x * x;
#pragma unroll
    for (int o = 16; o; o >>= 1) v += __shfl_xor_sync(0xffffffffu, v, o);
    __shared__ float wsum[4];
    if ((d & 31) == 0) wsum[d >> 5] = v;
    __syncthreads();
    float var = (wsum[0] + wsum[1] + wsum[2] + wsum[3]) * (1.f / cHD);
    float rs  = rsqrtf(var + cEPS);
    float xn  = x * rs * w[d];

    __shared__ float buf[cHD];
    buf[d] = xn;
    __syncthreads();
    float other = (d < cHD / 2) ? -buf[d + cHD / 2] : buf[d - cHD / 2];
    float cv = cosp[(size_t)bs * cHD + d];
    float sv = sinp[(size_t)bs * cHD + d];
    float val = xn * cv + other * sv;

    __nv_bfloat16 hi = __float2bfloat16(val);
    __nv_bfloat16 lo = __float2bfloat16(val - __bfloat162float(hi));
    dhi[d] = hi;
    dlo[d] = lo;
}

// ---------------------------------------------------------------------------
// Single-pass MMA attention: QK bf16 3-term, PV tf32 via K-row-permute trick.
// Weight finalize: block-cooperative fully-coalesced rescale+zero sweep
// (inv values staged in smem; one float4 pass over the CTA's 128 rows).
// ---------------------------------------------------------------------------
namespace {
constexpr int KTB = 64 * 272;          // K tile bytes (64 rows x 272B)
constexpr int VTB = 128 * 272;         // V^T tile bytes
constexpr int KVSTAGE = 2 * KTB + VTB;
constexpr int ATTN_SMEM = 4 * KTB + 2 * KVSTAGE;   // 208896
__device__ __constant__ int c_kperm[8] = {0, 2, 4, 6, 1, 3, 5, 7};
}

__global__ __launch_bounds__(256, 1)
void attn_mma_kernel(const __nv_bfloat16* __restrict__ qhi_g,
                     const __nv_bfloat16* __restrict__ qlo_g,
                     const __nv_bfloat16* __restrict__ khi_g,
                     const __nv_bfloat16* __restrict__ klo_g,
                     const float* __restrict__ vt_g,
                     float* __restrict__ wout,
                     float* __restrict__ outp,
                     int write_w)
{
    extern __shared__ char smraw[];
    const uint32_t uQ  = smem_u32(smraw);
    const uint32_t uKV = uQ + 4 * KTB;
    float* sinv = (float*)smraw;          // reuses Q area after kt loop

    const int tid  = threadIdx.x;
    const int wid  = tid >> 5;
    const int lane = tid & 31;
    const int qt  = gridDim.y - 1 - blockIdx.y;    // heavy-first
    const int bkv = blockIdx.x;
    const int b   = bkv >> 3;
    const int kvh = bkv & 7;
    const int hs  = wid >> 2;
    const int h   = kvh * 2 + hs;
    const int wr  = (wid & 3) * 16;
    const int q0  = qt * 64;
    const int g   = lane >> 2;
    const int t   = lane & 3;

    // ---- Q tiles (4: h0hi, h0lo, h1hi, h1lo)
    {
        const size_t qrow = ((size_t)(b * cNH + kvh * 2) * cS + q0) * cHD;
        const int row = (tid >> 4);
        const int c   = tid & 15;
#pragma unroll
        for (int i = 0; i < 16; i++) {
            const int tile = i >> 2;
            const int rr = (i & 3) * 16 + row;
            const __nv_bfloat16* base = (tile & 1) ? qlo_g : qhi_g;
            const __nv_bfloat16* src = base + qrow +
                (size_t)(tile >> 1) * cS * cHD + (size_t)rr * cHD + c * 8;
            cp_async16(uQ + tile * KTB + rr * 272 + c * 16, src);
        }
    }
    CP_COMMIT();

    const size_t krow0 = ((size_t)(b * cNKV + kvh) * cS) * cHD;
    const size_t vbase = ((size_t)(b * cNKV + kvh) * cHD) * cS;
    const int lrow = (tid >> 4);
    const int lc   = tid & 15;

#define LOAD_KV_STAGE(kt_, st_)                                               \
    do {                                                                      \
        const uint32_t ust = uKV + (st_) * KVSTAGE;                           \
        const size_t krow = krow0 + (size_t)((kt_) * 64) * cHD;               \
        _Pragma("unroll")                                                     \
        for (int i = 0; i < 8; i++) {                                         \
            const int tile = i >> 2;                                          \
            const int rr = (i & 3) * 16 + lrow;                               \
            const int srr = (rr & 0x38) | c_kperm[rr & 7];                    \
            const __nv_bfloat16* base = tile ? klo_g : khi_g;                 \
            cp_async16(ust + tile * KTB + srr * 272 + lc * 16,                \
                       base + krow + (size_t)rr * cHD + lc * 8);              \
        }                                                                     \
        _Pragma("unroll")                                                     \
        for (int i = 0; i < 8; i++) {                                         \
            const int dd = i * 16 + lrow;                                     \
            cp_async16(ust + 2 * KTB + dd * 272 + lc * 16,                    \
                       vt_g + vbase + (size_t)dd * cS + (kt_) * 64 + lc * 4); \
        }                                                                     \
    } while (0)

    LOAD_KV_STAGE(0, 0);
    CP_COMMIT();

    const uint32_t qoff = (uint32_t)((wr + (lane & 15)) * 272 + (lane >> 4) * 16);
    const uint32_t koff = (uint32_t)(((lane & 7) + ((lane >> 4) & 1) * 8) * 272 +
                                     ((lane >> 3) & 1) * 16);
    const uint32_t voff = (uint32_t)(((lane & 7) + ((lane >> 4) & 1) * 8) * 272 +
                                     ((lane >> 3) & 1) * 16);
    const uint32_t uQh = uQ + hs * 2 * KTB;
    const uint32_t uQl = uQh + KTB;

    float oacc[16][4];
#pragma unroll
    for (int i = 0; i < 16; i++)
#pragma unroll
        for (int r = 0; r < 4; r++) oacc[i][r] = 0.f;
    float l0 = 0.f, l1 = 0.f;

    for (int kt = 0; kt <= qt; kt++) {
        if (kt < qt) {
            LOAD_KV_STAGE(kt + 1, (kt + 1) & 1);
            CP_COMMIT();
            CP_WAIT(1);
        } else {
            CP_WAIT(0);
        }
        __syncthreads();

        const uint32_t ust  = uKV + (kt & 1) * KVSTAGE;
        const uint32_t ukhi = ust;
        const uint32_t uklo = ust + KTB;
        const uint32_t uvt  = ust + 2 * KTB;

        // ---------- QK: 3-term bf16 hi/lo ----------
        float sacc[8][4];
#pragma unroll
        for (int i = 0; i < 8; i++)
#pragma unroll
            for (int r = 0; r < 4; r++) sacc[i][r] = 0.f;

#pragma unroll
        for (int kk = 0; kk < 8; kk++) {
            uint32_t qh[4], ql[4];
            ldm_x4(qh, uQh + qoff + kk * 32);
            ldm_x4(ql, uQl + qoff + kk * 32);
#pragma unroll
            for (int njp = 0; njp < 4; njp++) {
                uint32_t kb[4];
                ldm_x4(kb, ukhi + njp * (16 * 272) + koff + kk * 32);
                mma16816(sacc[2 * njp],     qh, kb);
                mma16816(sacc[2 * njp + 1], qh, kb + 2);
                mma16816(sacc[2 * njp],     ql, kb);
                mma16816(sacc[2 * njp + 1], ql, kb + 2);
            }
#pragma unroll
            for (int njp = 0; njp < 4; njp++) {
                uint32_t kb[4];
                ldm_x4(kb, uklo + njp * (16 * 272) + koff + kk * 32);
                mma16816(sacc[2 * njp],     qh, kb);
                mma16816(sacc[2 * njp + 1], qh, kb + 2);
            }
        }

        // ---------- exp, mask, sums, weight write, tf32 A-fragments ----------
        const bool diag = (kt == qt);
        uint32_t pt[8][4];
#pragma unroll
        for (int nj = 0; nj < 8; nj++) {
            float p0 = __expf(sacc[nj][0] * cSCALE);   // (r0, cb+t)
            float p1 = __expf(sacc[nj][1] * cSCALE);   // (r0, cb+t+4)
            float p2 = __expf(sacc[nj][2] * cSCALE);   // (r1, cb+t)
            float p3 = __expf(sacc[nj][3] * cSCALE);   // (r1, cb+t+4)
            if (diag) {
                const int col0 = nj * 8 + t;
                const int col1 = col0 + 4;
                const int rlo = wr + g, rhi = wr + 8 + g;
                if (col0 > rlo) p0 = 0.f;
                if (col1 > rlo) p1 = 0.f;
                if (col0 > rhi) p2 = 0.f;
                if (col1 > rhi) p3 = 0.f;
            }
            l0 += p0 + p1;
            l1 += p2 + p3;
            if (write_w) {
                float* w0 = wout + ((size_t)(b * cNH + h) * cS + q0 + wr + g) * cS
                            + kt * 64 + nj * 8 + t;
                w0[0] = p0;
                w0[4] = p1;
                float* w1 = w0 + 8 * (size_t)cS;
                w1[0] = p2;
                w1[4] = p3;
            }
            pt[nj][0] = tf32b(p0);
            pt[nj][1] = tf32b(p2);
            pt[nj][2] = tf32b(p1);
            pt[nj][3] = tf32b(p3);
        }

        // ---------- PV: tf32, V^T [d][s] fp32 ----------
#pragma unroll
        for (int nj = 0; nj < 8; nj++) {
#pragma unroll
            for (int nd2 = 0; nd2 < 8; nd2++) {
                uint32_t vb[4];
                ldm_x4(vb, uvt + nd2 * (16 * 272) + nj * 32 + voff);
                mma1688_tf32(oacc[2 * nd2],     pt[nj], vb);
                mma1688_tf32(oacc[2 * nd2 + 1], pt[nj], vb + 2);
            }
        }
        __syncthreads();
    }

    l0 += __shfl_xor_sync(0xffffffffu, l0, 1);
    l0 += __shfl_xor_sync(0xffffffffu, l0, 2);
    l1 += __shfl_xor_sync(0xffffffffu, l1, 1);
    l1 += __shfl_xor_sync(0xffffffffu, l1, 2);
    const float inv0 = 1.f / l0;
    const float inv1 = 1.f / l1;

    // ---- PV output (normalized, tf32-rounded for the Wo GEMM) ----
#pragma unroll
    for (int nd = 0; nd < 16; nd++) {
        const int col = nd * 8 + 2 * t;
        float* o0 = outp + ((size_t)(b * cS + q0 + wr + g) * cNH + h) * cHD + col;
        float* o1 = outp + ((size_t)(b * cS + q0 + wr + 8 + g) * cNH + h) * cHD + col;
        *(float2*)o0 = make_float2(tf32r(oacc[nd][0] * inv0),
                                   tf32r(oacc[nd][1] * inv0));
        *(float2*)o1 = make_float2(tf32r(oacc[nd][2] * inv1),
                                   tf32r(oacc[nd][3] * inv1));
    }

    // ---- fused weight finalize: cooperative, fully-coalesced sweep ----
    if (write_w) {
        // stage per-row inv into smem (Q tiles are dead now)
        if (t == 0) {
            sinv[hs * 64 + wr + g]     = inv0;
            sinv[hs * 64 + wr + 8 + g] = inv1;
        }
        __syncthreads();   // also orders this CTA's global p-writes

        const int valid = q0 + 64;              // cols [0, valid) are written
        const int v4 = valid >> 2;              // float4 count of valid region
        const float4 z = make_float4(0.f, 0.f, 0.f, 0.f);
        // 128 rows x 512 float4 = 65536 elements, 256 threads
        for (int idx = tid; idx < 128 * 512; idx += 256) {
            const int r  = idx >> 9;            // 0..127 (head*64 + row)
            const int c4 = idx & 511;
            float* p = wout +
                ((size_t)(b * cNH + kvh * 2 + (r >> 6)) * cS + q0 + (r & 63)) * cS +
                (size_t)c4 * 4;
            if (c4 < v4) {
                const float inv = sinv[r];
                float4 v = *(float4*)p;
                v.x *= inv; v.y *= inv; v.z *= inv; v.w *= inv;
                *(float4*)p = v;
            } else {
                *(float4*)p = z;
            }
        }
    }
}

// ---------------------------------------------------------------------------
// Launch (single stream)
// ---------------------------------------------------------------------------
extern "C" void kernel_launch(void* const* d_in, const int* in_sizes, int n_in,
                              void* d_out, int out_size)
{
    const float* hidden = (const float*)d_in[0];
    const float* cosp   = (const float*)d_in[1];
    const float* sinp   = (const float*)d_in[2];
    const float* wq  = (const float*)d_in[4];
    const float* wk  = (const float*)d_in[5];
    const float* wv  = (const float*)d_in[6];
    const float* wo  = (const float*)d_in[7];
    const float* qnw = (const float*)d_in[8];
    const float* knw = (const float*)d_in[9];

    float* out = (float*)d_out;
    const size_t n_attn = (size_t)cM * cHID;
    const size_t n_w    = (size_t)cB * cNH * cS * cS;
    const int write_w   = ((size_t)out_size >= n_attn + n_w) ? 1 : 0;
    float* weights = out + n_attn;

    float *pahf, *pqkv, *pa, *pwt, *pwot, *pvt;
    cudaGetSymbolAddress((void**)&pahf, g_ahf);
    cudaGetSymbolAddress((void**)&pqkv, g_qkv);
    cudaGetSymbolAddress((void**)&pa,   g_att);
    cudaGetSymbolAddress((void**)&pwt,  g_wt);
    cudaGetSymbolAddress((void**)&pwot, g_wot);
    cudaGetSymbolAddress((void**)&pvt,  g_vt);
    __nv_bfloat16 *pqh, *pql, *pkh, *pklo;
    cudaGetSymbolAddress((void**)&pqh,  g_q2hi);
    cudaGetSymbolAddress((void**)&pql,  g_q2lo);
    cudaGetSymbolAddress((void**)&pkh,  g_k2hi);
    cudaGetSymbolAddress((void**)&pklo, g_k2lo);

    static bool attr_done = false;
    if (!attr_done) {
        cudaFuncSetAttribute(gemm_tf32_kernel,
                             cudaFuncAttributeMaxDynamicSharedMemorySize, GEMM_SMEM);
        cudaFuncSetAttribute(attn_mma_kernel,
                             cudaFuncAttributeMaxDynamicSharedMemorySize, ATTN_SMEM);
        attr_done = true;
    }

    // --- prep: tf32-rounded A, transposed+rounded weights ---
    round_tf32_kernel<<<(cM * cHID / 4) / 256, 256>>>(hidden, pahf);
    cvt_wT_kernel<<<dim3(2048 / 32, 2048 / 32), dim3(32, 8)>>>(
        wq, pwt, cHID, 2048);
    cvt_wT_kernel<<<dim3(1024 / 32, 2048 / 32), dim3(32, 8)>>>(
        wk, pwt + (size_t)2048 * cHID, cHID, 1024);
    cvt_wT_kernel<<<dim3(1024 / 32, 2048 / 32), dim3(32, 8)>>>(
        wv, pwt + (size_t)3072 * cHID, cHID, 1024);
    cvt_wT_kernel<<<dim3(2048 / 32, 2048 / 32), dim3(32, 8)>>>(
        wo, pwot, cHID, 2048);

    // --- fused QKV projection (tf32) ---
    gemm_tf32_kernel<<<dim3(cNQKV / GBN, cM / GBM), 256, GEMM_SMEM>>>(
        pahf, pwt, pqkv, cM, cNQKV, cHID);

    // --- RMSNorm + RoPE + bf16 hi/lo split (Q,K); V^T transpose (tf32) ---
    norm_rope_split_kernel<<<dim3(24, cM), 128>>>(cosp, sinp, qnw, knw);
    vT_kernel<<<dim3(cS / 32, cHD / 32, cB * cNKV), dim3(32, 8)>>>(pqkv, pvt);

    // --- single-pass MMA attention + cooperative weight finalize ---
    attn_mma_kernel<<<dim3(cB * cNKV, cS / 64), 256, ATTN_SMEM>>>(
        pqh, pql, pkh, pklo, pvt, weights, pa, write_w);

    // --- output projection (tf32) ---
    gemm_tf32_kernel<<<dim3(cHID / GBN, cM / GBM), 256, GEMM_SMEM>>>(
        pa, pwot, out, cM, cHID, cHID);
}

// round 11
// speedup vs baseline: 1.1609x; 1.1609x over previous
#include <cuda_runtime.h>
#include <cuda_bf16.h>
#include <math.h>
#include <stdint.h>

// ---------------------------------------------------------------------------
// Problem constants
// ---------------------------------------------------------------------------
namespace {
constexpr int cB   = 2;
constexpr int cS   = 2048;
constexpr int cHID = 2048;
constexpr int cNH  = 16;
constexpr int cNKV = 8;
constexpr int cHD  = 128;
constexpr float cEPS   = 1e-6f;
constexpr float cSCALE = 0.08838834764831845f;  // 128^-0.5
constexpr int cM   = cB * cS;        // 4096
constexpr int cNQKV = 4096;          // fused QKV output width
}

// ---------------------------------------------------------------------------
// Scratch (device globals -- no runtime allocation allowed)
// ---------------------------------------------------------------------------
__device__ float g_qkv [(size_t)cM * cNQKV];       // fused QKV projection out
__device__ float g_att [(size_t)cM * cNH * cHD];   // attn out pre-Wo (tf32-rounded)
__device__ float g_wt  [(size_t)cNQKV * cHID];     // [wq|wk|wv]^T tf32-rounded
__device__ float g_wot [(size_t)cHID * cHID];      // wo^T tf32-rounded
__device__ float g_vt  [(size_t)cB * cNKV * cHD * cS]; // V^T fp32 [b][kvh][d][s]

// bf16 hi/lo planes for attention QK, head-major layout [b][h][s][d]
__device__ __nv_bfloat16 g_q2hi[(size_t)cB * cNH  * cS * cHD];
__device__ __nv_bfloat16 g_q2lo[(size_t)cB * cNH  * cS * cHD];
__device__ __nv_bfloat16 g_k2hi[(size_t)cB * cNKV * cS * cHD];
__device__ __nv_bfloat16 g_k2lo[(size_t)cB * cNKV * cS * cHD];

// ---------------------------------------------------------------------------
// PTX helpers (portable: sm_80+)
// ---------------------------------------------------------------------------
__device__ __forceinline__ uint32_t smem_u32(const void* p) {
    uint32_t a;
    asm("{ .reg .u64 t; cvta.to.shared.u64 t, %1; cvt.u32.u64 %0, t; }"
        : "=r"(a) : "l"(p));
    return a;
}
__device__ __forceinline__ void cp_async16(uint32_t saddr, const void* gaddr) {
    asm volatile("cp.async.cg.shared.global [%0], [%1], 16;"
                 :: "r"(saddr), "l"(gaddr) : "memory");
}
#define CP_COMMIT()  asm volatile("cp.async.commit_group;" ::: "memory")
#define CP_WAIT(N)   asm volatile("cp.async.wait_group %0;" :: "n"(N) : "memory")

__device__ __forceinline__ void ldm_x4(uint32_t* r, uint32_t addr) {
    asm volatile("ldmatrix.sync.aligned.m8n8.x4.shared.b16 {%0,%1,%2,%3}, [%4];"
                 : "=r"(r[0]), "=r"(r[1]), "=r"(r[2]), "=r"(r[3]) : "r"(addr));
}
__device__ __forceinline__ void mma16816(float* d, const uint32_t* a,
                                         const uint32_t* b) {
    asm volatile(
        "mma.sync.aligned.m16n8k16.row.col.f32.bf16.bf16.f32 "
        "{%0,%1,%2,%3}, {%4,%5,%6,%7}, {%8,%9}, {%0,%1,%2,%3};"
        : "+f"(d[0]), "+f"(d[1]), "+f"(d[2]), "+f"(d[3])
        : "r"(a[0]), "r"(a[1]), "r"(a[2]), "r"(a[3]), "r"(b[0]), "r"(b[1]));
}
__device__ __forceinline__ void mma1688_tf32(float* d, const uint32_t* a,
                                             const uint32_t* b) {
    asm volatile(
        "mma.sync.aligned.m16n8k8.row.col.f32.tf32.tf32.f32 "
        "{%0,%1,%2,%3}, {%4,%5,%6,%7}, {%8,%9}, {%0,%1,%2,%3};"
        : "+f"(d[0]), "+f"(d[1]), "+f"(d[2]), "+f"(d[3])
        : "r"(a[0]), "r"(a[1]), "r"(a[2]), "r"(a[3]), "r"(b[0]), "r"(b[1]));
}
__device__ __forceinline__ uint32_t sw128(uint32_t off) {
    return off ^ ((off >> 3) & 0x70);
}
__device__ __forceinline__ float tf32r(float x) {
    uint32_t u;
    asm("cvt.rna.tf32.f32 %0, %1;" : "=r"(u) : "f"(x));
    return __uint_as_float(u);
}
__device__ __forceinline__ uint32_t tf32b(float x) {
    uint32_t u;
    asm("cvt.rna.tf32.f32 %0, %1;" : "=r"(u) : "f"(x));
    return u;
}
__device__ __forceinline__ uint32_t tf32u(uint32_t x) {
    uint32_t u;
    asm("cvt.rna.tf32.f32 %0, %1;" : "=r"(u) : "f"(__uint_as_float(x)));
    return u;
}

// ---------------------------------------------------------------------------
// Prep kernels
// ---------------------------------------------------------------------------
__global__ __launch_bounds__(256) void cvt_wT_kernel(
    const float* __restrict__ W, float* __restrict__ Y, int K, int N)
{
    __shared__ float t[32][33];
    int n0 = blockIdx.x * 32;
    int k0 = blockIdx.y * 32;
    int tx = threadIdx.x;
    int ty = threadIdx.y;
#pragma unroll
    for (int i = 0; i < 32; i += 8)
        t[ty + i][tx] = W[(size_t)(k0 + ty + i) * N + n0 + tx];
    __syncthreads();
#pragma unroll
    for (int i = 0; i < 32; i += 8) {
        int n = n0 + ty + i;
        int k = k0 + tx;
        Y[(size_t)n * K + k] = tf32r(t[tx][ty + i]);
    }
}

// V^T: g_qkv v-section [b][s][kvh*128+d] -> g_vt [b][kvh][d][s], tf32-rounded
__global__ __launch_bounds__(256) void vT_kernel(
    const float* __restrict__ qkv, float* __restrict__ vt)
{
    __shared__ float t[32][33];
    const int s0 = blockIdx.x * 32;
    const int d0 = blockIdx.y * 32;
    const int bk = blockIdx.z;           // b*8 + kvh
    const int b  = bk >> 3;
    const int kvh = bk & 7;
    const int tx = threadIdx.x;
    const int ty = threadIdx.y;
#pragma unroll
    for (int i = 0; i < 32; i += 8)
        t[ty + i][tx] = qkv[(size_t)(b * cS + s0 + ty + i) * cNQKV +
                            3072 + kvh * cHD + d0 + tx];
    __syncthreads();
#pragma unroll
    for (int i = 0; i < 32; i += 8)
        vt[((size_t)bk * cHD + d0 + ty + i) * cS + s0 + tx] =
            tf32r(t[tx][ty + i]);
}

// ---------------------------------------------------------------------------
// TF32 HMMA GEMM: C[M,N] = A[M,K] @ B[N,K]^T (row-major fp32).
// ROUND_A: apply cvt.rna.tf32 to A fragments in-register (A not prerounded).
// CTA tile 128x256, BK=32, 4-stage cp.async, SW128, warp tile 64x64.
// ---------------------------------------------------------------------------
namespace {
constexpr int GBM = 128, GBN = 256, GBK = 32;
constexpr int NSTAGE = 4;
constexpr int A_BYTES = GBM * GBK * 4;              // 16KB
constexpr int B_BYTES = GBN * GBK * 4;              // 32KB
constexpr int STAGE_BYTES = A_BYTES + B_BYTES;      // 48KB
constexpr int GEMM_SMEM   = NSTAGE * STAGE_BYTES;   // 192KB
}

__device__ __forceinline__ void gemm_load_stage(
    const float* __restrict__ Ag, const float* __restrict__ Bg,
    int K, int it, uint32_t stage_base, int tid)
{
#pragma unroll
    for (int i = 0; i < 4; i++) {
        int idx = tid + (i << 8);
        int row = idx >> 3;
        int c4  = idx & 7;
        uint32_t sw = sw128((uint32_t)(row * 128 + c4 * 16));
        cp_async16(stage_base + sw,
                   Ag + (size_t)row * K + (size_t)it * GBK + c4 * 4);
    }
#pragma unroll
    for (int i = 0; i < 8; i++) {
        int idx = tid + (i << 8);
        int row = idx >> 3;
        int c4  = idx & 7;
        uint32_t sw = sw128((uint32_t)(row * 128 + c4 * 16));
        cp_async16(stage_base + A_BYTES + sw,
                   Bg + (size_t)row * K + (size_t)it * GBK + c4 * 4);
    }
}

template <bool ROUND_A>
__global__ __launch_bounds__(256, 1)
void gemm_tf32_kernel(const float* __restrict__ A,
                      const float* __restrict__ B,
                      float* __restrict__ C, int M, int N, int K)
{
    extern __shared__ char smraw[];
    const uint32_t sbase = smem_u32(smraw);

    const int tid  = threadIdx.x;
    const int wid  = tid >> 5;
    const int lane = tid & 31;
    const int m0 = blockIdx.y * GBM;
    const int n0 = blockIdx.x * GBN;
    const int mw = (wid >> 2) * 64;
    const int nw = (wid & 3) * 64;

    const float* Ag = A + (size_t)m0 * K;
    const float* Bg = B + (size_t)n0 * K;
    const int KITERS = K / GBK;

    float acc[4][8][4];
#pragma unroll
    for (int i = 0; i < 4; i++)
#pragma unroll
        for (int j = 0; j < 8; j++)
#pragma unroll
            for (int r = 0; r < 4; r++) acc[i][j][r] = 0.f;

    const int a_row = lane & 15;
    const int a_cb  = (lane >> 4) * 16;
    const int b_row = (lane & 7) + ((lane >> 4) & 1) * 8;
    const int b_cb  = ((lane >> 3) & 1) * 16;

#pragma unroll
    for (int s = 0; s < NSTAGE - 1; s++) {
        gemm_load_stage(Ag, Bg, K, s, sbase + s * STAGE_BYTES, tid);
        CP_COMMIT();
    }

    for (int it = 0; it < KITERS; ++it) {
        CP_WAIT(NSTAGE - 2);
        __syncthreads();

        int nx = it + NSTAGE - 1;
        if (nx < KITERS)
            gemm_load_stage(Ag, Bg, K, nx,
                            sbase + (nx % NSTAGE) * STAGE_BYTES, tid);
        CP_COMMIT();

        const uint32_t sa = sbase + (it % NSTAGE) * STAGE_BYTES;
        const uint32_t sb = sa + A_BYTES;

#pragma unroll
        for (int ks = 0; ks < 4; ks++) {
            uint32_t af[4][4], bf[4][4];
#pragma unroll
            for (int mi = 0; mi < 4; mi++) {
                uint32_t off = (uint32_t)((mw + 16 * mi + a_row) * 128 +
                                          ks * 32 + a_cb);
                ldm_x4(af[mi], sa + sw128(off));
                if (ROUND_A) {
#pragma unroll
                    for (int j = 0; j < 4; j++) af[mi][j] = tf32u(af[mi][j]);
                }
            }
#pragma unroll
            for (int njp = 0; njp < 4; njp++) {
                uint32_t off = (uint32_t)((nw + 16 * njp + b_row) * 128 +
                                          ks * 32 + b_cb);
                ldm_x4(bf[njp], sb + sw128(off));
            }
#pragma unroll
            for (int mi = 0; mi < 4; mi++)
#pragma unroll
                for (int njp = 0; njp < 4; njp++) {
                    mma1688_tf32(acc[mi][2 * njp],     af[mi], bf[njp]);
                    mma1688_tf32(acc[mi][2 * njp + 1], af[mi], bf[njp] + 2);
                }
        }
    }

    const int g = lane >> 2;
    const int t = lane & 3;
#pragma unroll
    for (int mi = 0; mi < 4; mi++) {
#pragma unroll
        for (int nj = 0; nj < 8; nj++) {
            int r0 = m0 + mw + 16 * mi + g;
            int cc = n0 + nw + 8 * nj + t * 2;
            *(float2*)(C + (size_t)r0 * N + cc) =
                make_float2(acc[mi][nj][0], acc[mi][nj][1]);
            *(float2*)(C + (size_t)(r0 + 8) * N + cc) =
                make_float2(acc[mi][nj][2], acc[mi][nj][3]);
        }
    }
}

// ---------------------------------------------------------------------------
// RMSNorm + RoPE + hi/lo bf16 split for Q and K only (V handled by vT_kernel).
// ---------------------------------------------------------------------------
__global__ __launch_bounds__(128) void norm_rope_split_kernel(
    const float* __restrict__ cosp, const float* __restrict__ sinp,
    const float* __restrict__ qw,   const float* __restrict__ kw)
{
    const int slot = blockIdx.x;
    const int bs   = blockIdx.y;
    const int d    = threadIdx.x;
    const int b    = bs >> 11;
    const int s    = bs & 2047;

    const float* src;
    const float* w;
    __nv_bfloat16 *dhi, *dlo;
    if (slot < 16) {
        src = g_qkv + (size_t)bs * cNQKV + slot * cHD;
        w = qw;
        size_t dst = ((size_t)(b * cNH + slot) * cS + s) * cHD;
        dhi = g_q2hi + dst; dlo = g_q2lo + dst;
    } else {
        src = g_qkv + (size_t)bs * cNQKV + 2048 + (slot - 16) * cHD;
        w = kw;
        size_t dst = ((size_t)(b * cNKV + (slot - 16)) * cS + s) * cHD;
        dhi = g_k2hi + dst; dlo = g_k2lo + dst;
    }
    float x = src[d];
    float v = x * x;
#pragma unroll
    for (int o = 16; o; o >>= 1) v += __shfl_xor_sync(0xffffffffu, v, o);
    __shared__ float wsum[4];
    if ((d & 31) == 0) wsum[d >> 5] = v;
    __syncthreads();
    float var = (wsum[0] + wsum[1] + wsum[2] + wsum[3]) * (1.f / cHD);
    float rs  = rsqrtf(var + cEPS);
    float xn  = x * rs * w[d];

    __shared__ float buf[cHD];
    buf[d] = xn;
    __syncthreads();
    float other = (d < cHD / 2) ? -buf[d + cHD / 2] : buf[d - cHD / 2];
    float cv = cosp[(size_t)bs * cHD + d];
    float sv = sinp[(size_t)bs * cHD + d];
    float val = xn * cv + other * sv;

    __nv_bfloat16 hi = __float2bfloat16(val);
    __nv_bfloat16 lo = __float2bfloat16(val - __bfloat162float(hi));
    dhi[d] = hi;
    dlo[d] = lo;
}

// ---------------------------------------------------------------------------
// Single-pass MMA attention: QK bf16 3-term, PV tf32 via K-row-permute trick.
// Fused weight normalize (R9 scattered per-thread form) + zero-fill.
// ---------------------------------------------------------------------------
namespace {
constexpr int KTB = 64 * 272;          // K tile bytes (64 rows x 272B)
constexpr int VTB = 128 * 272;         // V^T tile bytes
constexpr int KVSTAGE = 2 * KTB + VTB;
constexpr int ATTN_SMEM = 4 * KTB + 2 * KVSTAGE;   // 208896
__device__ __constant__ int c_kperm[8] = {0, 2, 4, 6, 1, 3, 5, 7};
}

__global__ __launch_bounds__(256, 1)
void attn_mma_kernel(const __nv_bfloat16* __restrict__ qhi_g,
                     const __nv_bfloat16* __restrict__ qlo_g,
                     const __nv_bfloat16* __restrict__ khi_g,
                     const __nv_bfloat16* __restrict__ klo_g,
                     const float* __restrict__ vt_g,
                     float* __restrict__ wout,
                     float* __restrict__ outp,
                     int write_w)
{
    extern __shared__ char smraw[];
    const uint32_t uQ  = smem_u32(smraw);
    const uint32_t uKV = uQ + 4 * KTB;

    const int tid  = threadIdx.x;
    const int wid  = tid >> 5;
    const int lane = tid & 31;
    const int qt  = gridDim.y - 1 - blockIdx.y;    // heavy-first
    const int bkv = blockIdx.x;
    const int b   = bkv >> 3;
    const int kvh = bkv & 7;
    const int hs  = wid >> 2;
    const int h   = kvh * 2 + hs;
    const int wr  = (wid & 3) * 16;
    const int q0  = qt * 64;
    const int g   = lane >> 2;
    const int t   = lane & 3;

    // ---- Q tiles (4: h0hi, h0lo, h1hi, h1lo)
    {
        const size_t qrow = ((size_t)(b * cNH + kvh * 2) * cS + q0) * cHD;
        const int row = (tid >> 4);
        const int c   = tid & 15;
#pragma unroll
        for (int i = 0; i < 16; i++) {
            const int tile = i >> 2;
            const int rr = (i & 3) * 16 + row;
            const __nv_bfloat16* base = (tile & 1) ? qlo_g : qhi_g;
            const __nv_bfloat16* src = base + qrow +
                (size_t)(tile >> 1) * cS * cHD + (size_t)rr * cHD + c * 8;
            cp_async16(uQ + tile * KTB + rr * 272 + c * 16, src);
        }
    }
    CP_COMMIT();

    const size_t krow0 = ((size_t)(b * cNKV + kvh) * cS) * cHD;
    const size_t vbase = ((size_t)(b * cNKV + kvh) * cHD) * cS;
    const int lrow = (tid >> 4);
    const int lc   = tid & 15;

#define LOAD_KV_STAGE(kt_, st_)                                               \
    do {                                                                      \
        const uint32_t ust = uKV + (st_) * KVSTAGE;                           \
        const size_t krow = krow0 + (size_t)((kt_) * 64) * cHD;               \
        _Pragma("unroll")                                                     \
        for (int i = 0; i < 8; i++) {                                         \
            const int tile = i >> 2;                                          \
            const int rr = (i & 3) * 16 + lrow;                               \
            const int srr = (rr & 0x38) | c_kperm[rr & 7];                    \
            const __nv_bfloat16* base = tile ? klo_g : khi_g;                 \
            cp_async16(ust + tile * KTB + srr * 272 + lc * 16,                \
                       base + krow + (size_t)rr * cHD + lc * 8);              \
        }                                                                     \
        _Pragma("unroll")                                                     \
        for (int i = 0; i < 8; i++) {                                         \
            const int dd = i * 16 + lrow;                                     \
            cp_async16(ust + 2 * KTB + dd * 272 + lc * 16,                    \
                       vt_g + vbase + (size_t)dd * cS + (kt_) * 64 + lc * 4); \
        }                                                                     \
    } while (0)

    LOAD_KV_STAGE(0, 0);
    CP_COMMIT();

    const uint32_t qoff = (uint32_t)((wr + (lane & 15)) * 272 + (lane >> 4) * 16);
    const uint32_t koff = (uint32_t)(((lane & 7) + ((lane >> 4) & 1) * 8) * 272 +
                                     ((lane >> 3) & 1) * 16);
    const uint32_t voff = (uint32_t)(((lane & 7) + ((lane >> 4) & 1) * 8) * 272 +
                                     ((lane >> 3) & 1) * 16);
    const uint32_t uQh = uQ + hs * 2 * KTB;
    const uint32_t uQl = uQh + KTB;

    float oacc[16][4];
#pragma unroll
    for (int i = 0; i < 16; i++)
#pragma unroll
        for (int r = 0; r < 4; r++) oacc[i][r] = 0.f;
    float l0 = 0.f, l1 = 0.f;

    for (int kt = 0; kt <= qt; kt++) {
        if (kt < qt) {
            LOAD_KV_STAGE(kt + 1, (kt + 1) & 1);
            CP_COMMIT();
            CP_WAIT(1);
        } else {
            CP_WAIT(0);
        }
        __syncthreads();

        const uint32_t ust  = uKV + (kt & 1) * KVSTAGE;
        const uint32_t ukhi = ust;
        const uint32_t uklo = ust + KTB;
        const uint32_t uvt  = ust + 2 * KTB;

        // ---------- QK: 3-term bf16 hi/lo ----------
        float sacc[8][4];
#pragma unroll
        for (int i = 0; i < 8; i++)
#pragma unroll
            for (int r = 0; r < 4; r++) sacc[i][r] = 0.f;

#pragma unroll
        for (int kk = 0; kk < 8; kk++) {
            uint32_t qh[4], ql[4];
            ldm_x4(qh, uQh + qoff + kk * 32);
            ldm_x4(ql, uQl + qoff + kk * 32);
#pragma unroll
            for (int njp = 0; njp < 4; njp++) {
                uint32_t kb[4];
                ldm_x4(kb, ukhi + njp * (16 * 272) + koff + kk * 32);
                mma16816(sacc[2 * njp],     qh, kb);
                mma16816(sacc[2 * njp + 1], qh, kb + 2);
                mma16816(sacc[2 * njp],     ql, kb);
                mma16816(sacc[2 * njp + 1], ql, kb + 2);
            }
#pragma unroll
            for (int njp = 0; njp < 4; njp++) {
                uint32_t kb[4];
                ldm_x4(kb, uklo + njp * (16 * 272) + koff + kk * 32);
                mma16816(sacc[2 * njp],     qh, kb);
                mma16816(sacc[2 * njp + 1], qh, kb + 2);
            }
        }

        // ---------- exp, mask, sums, weight write, tf32 A-fragments ----------
        const bool diag = (kt == qt);
        uint32_t pt[8][4];
#pragma unroll
        for (int nj = 0; nj < 8; nj++) {
            float p0 = __expf(sacc[nj][0] * cSCALE);   // (r0, cb+t)
            float p1 = __expf(sacc[nj][1] * cSCALE);   // (r0, cb+t+4)
            float p2 = __expf(sacc[nj][2] * cSCALE);   // (r1, cb+t)
            float p3 = __expf(sacc[nj][3] * cSCALE);   // (r1, cb+t+4)
            if (diag) {
                const int col0 = nj * 8 + t;
                const int col1 = col0 + 4;
                const int rlo = wr + g, rhi = wr + 8 + g;
                if (col0 > rlo) p0 = 0.f;
                if (col1 > rlo) p1 = 0.f;
                if (col0 > rhi) p2 = 0.f;
                if (col1 > rhi) p3 = 0.f;
            }
            l0 += p0 + p1;
            l1 += p2 + p3;
            if (write_w) {
                float* w0 = wout + ((size_t)(b * cNH + h) * cS + q0 + wr + g) * cS
                            + kt * 64 + nj * 8 + t;
                w0[0] = p0;
                w0[4] = p1;
                float* w1 = w0 + 8 * (size_t)cS;
                w1[0] = p2;
                w1[4] = p3;
            }
            pt[nj][0] = tf32b(p0);
            pt[nj][1] = tf32b(p2);
            pt[nj][2] = tf32b(p1);
            pt[nj][3] = tf32b(p3);
        }

        // ---------- PV: tf32, V^T [d][s] fp32 ----------
#pragma unroll
        for (int nj = 0; nj < 8; nj++) {
#pragma unroll
            for (int nd2 = 0; nd2 < 8; nd2++) {
                uint32_t vb[4];
                ldm_x4(vb, uvt + nd2 * (16 * 272) + nj * 32 + voff);
                mma1688_tf32(oacc[2 * nd2],     pt[nj], vb);
                mma1688_tf32(oacc[2 * nd2 + 1], pt[nj], vb + 2);
            }
        }
        __syncthreads();
    }

    l0 += __shfl_xor_sync(0xffffffffu, l0, 1);
    l0 += __shfl_xor_sync(0xffffffffu, l0, 2);
    l1 += __shfl_xor_sync(0xffffffffu, l1, 1);
    l1 += __shfl_xor_sync(0xffffffffu, l1, 2);
    const float inv0 = 1.f / l0;
    const float inv1 = 1.f / l1;

    // ---- PV output (normalized, tf32-rounded for the Wo GEMM) ----
#pragma unroll
    for (int nd = 0; nd < 16; nd++) {
        const int col = nd * 8 + 2 * t;
        float* o0 = outp + ((size_t)(b * cS + q0 + wr + g) * cNH + h) * cHD + col;
        float* o1 = outp + ((size_t)(b * cS + q0 + wr + 8 + g) * cNH + h) * cHD + col;
        *(float2*)o0 = make_float2(tf32r(oacc[nd][0] * inv0),
                                   tf32r(oacc[nd][1] * inv0));
        *(float2*)o1 = make_float2(tf32r(oacc[nd][2] * inv1),
                                   tf32r(oacc[nd][3] * inv1));
    }

    // ---- fused weight normalization (R9 form: rescale own writes) ----
    if (write_w) {
        const size_t rb0 = ((size_t)(b * cNH + h) * cS + q0 + wr + g) * cS;
        const size_t rb1 = rb0 + 8 * (size_t)cS;
        for (int kt = 0; kt <= qt; kt++) {
#pragma unroll
            for (int nj = 0; nj < 8; nj++) {
                const int cc = kt * 64 + nj * 8 + t;
                float* w0 = wout + rb0 + cc;
                w0[0] *= inv0;
                w0[4] *= inv0;
                float* w1 = wout + rb1 + cc;
                w1[0] *= inv1;
                w1[4] *= inv1;
            }
        }
        // ---- zero the upper-triangle tail of this CTA's 128 rows
        const int zc = cS - (q0 + 64);
        if (zc > 0) {
            const int z4 = zc >> 2;
            const int tot = 128 * z4;
            const float4 z = make_float4(0.f, 0.f, 0.f, 0.f);
            for (int i = tid; i < tot; i += 256) {
                const int r  = i / z4;
                const int c4 = i - r * z4;
                const int head = r >> 6;
                const int row  = r & 63;
                float* p = wout +
                    ((size_t)(b * cNH + kvh * 2 + head) * cS + q0 + row) * cS +
                    q0 + 64 + c4 * 4;
                *(float4*)p = z;
            }
        }
    }
}

// ---------------------------------------------------------------------------
// Launch (single stream)
// ---------------------------------------------------------------------------
extern "C" void kernel_launch(void* const* d_in, const int* in_sizes, int n_in,
                              void* d_out, int out_size)
{
    const float* hidden = (const float*)d_in[0];
    const float* cosp   = (const float*)d_in[1];
    const float* sinp   = (const float*)d_in[2];
    const float* wq  = (const float*)d_in[4];
    const float* wk  = (const float*)d_in[5];
    const float* wv  = (const float*)d_in[6];
    const float* wo  = (const float*)d_in[7];
    const float* qnw = (const float*)d_in[8];
    const float* knw = (const float*)d_in[9];

    float* out = (float*)d_out;
    const size_t n_attn = (size_t)cM * cHID;
    const size_t n_w    = (size_t)cB * cNH * cS * cS;
    const int write_w   = ((size_t)out_size >= n_attn + n_w) ? 1 : 0;
    float* weights = out + n_attn;

    float *pqkv, *pa, *pwt, *pwot, *pvt;
    cudaGetSymbolAddress((void**)&pqkv, g_qkv);
    cudaGetSymbolAddress((void**)&pa,   g_att);
    cudaGetSymbolAddress((void**)&pwt,  g_wt);
    cudaGetSymbolAddress((void**)&pwot, g_wot);
    cudaGetSymbolAddress((void**)&pvt,  g_vt);
    __nv_bfloat16 *pqh, *pql, *pkh, *pklo;
    cudaGetSymbolAddress((void**)&pqh,  g_q2hi);
    cudaGetSymbolAddress((void**)&pql,  g_q2lo);
    cudaGetSymbolAddress((void**)&pkh,  g_k2hi);
    cudaGetSymbolAddress((void**)&pklo, g_k2lo);

    static bool attr_done = false;
    if (!attr_done) {
        cudaFuncSetAttribute(gemm_tf32_kernel<true>,
                             cudaFuncAttributeMaxDynamicSharedMemorySize, GEMM_SMEM);
        cudaFuncSetAttribute(gemm_tf32_kernel<false>,
                             cudaFuncAttributeMaxDynamicSharedMemorySize, GEMM_SMEM);
        cudaFuncSetAttribute(attn_mma_kernel,
                             cudaFuncAttributeMaxDynamicSharedMemorySize, ATTN_SMEM);
        attr_done = true;
    }

    // --- prep: transposed+rounded weights (A rounding is fused in-GEMM) ---
    cvt_wT_kernel<<<dim3(2048 / 32, 2048 / 32), dim3(32, 8)>>>(
        wq, pwt, cHID, 2048);
    cvt_wT_kernel<<<dim3(1024 / 32, 2048 / 32), dim3(32, 8)>>>(
        wk, pwt + (size_t)2048 * cHID, cHID, 1024);
    cvt_wT_kernel<<<dim3(1024 / 32, 2048 / 32), dim3(32, 8)>>>(
        wv, pwt + (size_t)3072 * cHID, cHID, 1024);
    cvt_wT_kernel<<<dim3(2048 / 32, 2048 / 32), dim3(32, 8)>>>(
        wo, pwot, cHID, 2048);

    // --- fused QKV projection (tf32, A rounded in-register) ---
    gemm_tf32_kernel<true><<<dim3(cNQKV / GBN, cM / GBM), 256, GEMM_SMEM>>>(
        hidden, pwt, pqkv, cM, cNQKV, cHID);

    // --- RMSNorm + RoPE + bf16 hi/lo split (Q,K); V^T transpose (tf32) ---
    norm_rope_split_kernel<<<dim3(24, cM), 128>>>(cosp, sinp, qnw, knw);
    vT_kernel<<<dim3(cS / 32, cHD / 32, cB * cNKV), dim3(32, 8)>>>(pqkv, pvt);

    // --- single-pass MMA attention + fused weight normalize/zero-fill ---
    attn_mma_kernel<<<dim3(cB * cNKV, cS / 64), 256, ATTN_SMEM>>>(
        pqh, pql, pkh, pklo, pvt, weights, pa, write_w);

    // --- output projection (tf32, A already rounded) ---
    gemm_tf32_kernel<false><<<dim3(cHID / GBN, cM / GBM), 256, GEMM_SMEM>>>(
        pa, pwot, out, cM, cHID, cHID);
}

// round 12
// speedup vs baseline: 1.1673x; 1.0056x over previous
#include <cuda_runtime.h>
#include <cuda_bf16.h>
#include <math.h>
#include <stdint.h>

// ---------------------------------------------------------------------------
// Problem constants
// ---------------------------------------------------------------------------
namespace {
constexpr int cB   = 2;
constexpr int cS   = 2048;
constexpr int cHID = 2048;
constexpr int cNH  = 16;
constexpr int cNKV = 8;
constexpr int cHD  = 128;
constexpr float cEPS   = 1e-6f;
constexpr float cSCALE = 0.08838834764831845f;  // 128^-0.5
constexpr int cM   = cB * cS;        // 4096
constexpr int cNQKV = 4096;          // fused QKV output width
}

// ---------------------------------------------------------------------------
// Scratch (device globals -- no runtime allocation allowed)
// ---------------------------------------------------------------------------
__device__ float g_ahf [(size_t)cM * cHID];        // tf32-rounded hidden
__device__ float g_qkv [(size_t)cM * cNQKV];       // fused QKV projection out
__device__ float g_att [(size_t)cM * cNH * cHD];   // attn out pre-Wo (tf32-rounded)
__device__ float g_wt  [(size_t)cNQKV * cHID];     // [wq|wk|wv]^T tf32-rounded
__device__ float g_wot [(size_t)cHID * cHID];      // wo^T tf32-rounded
__device__ float g_vt  [(size_t)cB * cNKV * cHD * cS]; // V^T fp32 [b][kvh][d][s]

// bf16 hi/lo planes for attention QK, head-major layout [b][h][s][d]
__device__ __nv_bfloat16 g_q2hi[(size_t)cB * cNH  * cS * cHD];
__device__ __nv_bfloat16 g_q2lo[(size_t)cB * cNH  * cS * cHD];
__device__ __nv_bfloat16 g_k2hi[(size_t)cB * cNKV * cS * cHD];
__device__ __nv_bfloat16 g_k2lo[(size_t)cB * cNKV * cS * cHD];

// ---------------------------------------------------------------------------
// PTX helpers (portable: sm_80+)
// ---------------------------------------------------------------------------
__device__ __forceinline__ uint32_t smem_u32(const void* p) {
    uint32_t a;
    asm("{ .reg .u64 t; cvta.to.shared.u64 t, %1; cvt.u32.u64 %0, t; }"
        : "=r"(a) : "l"(p));
    return a;
}
__device__ __forceinline__ void cp_async16(uint32_t saddr, const void* gaddr) {
    asm volatile("cp.async.cg.shared.global [%0], [%1], 16;"
                 :: "r"(saddr), "l"(gaddr) : "memory");
}
#define CP_COMMIT()  asm volatile("cp.async.commit_group;" ::: "memory")
#define CP_WAIT(N)   asm volatile("cp.async.wait_group %0;" :: "n"(N) : "memory")

__device__ __forceinline__ void ldm_x4(uint32_t* r, uint32_t addr) {
    asm volatile("ldmatrix.sync.aligned.m8n8.x4.shared.b16 {%0,%1,%2,%3}, [%4];"
                 : "=r"(r[0]), "=r"(r[1]), "=r"(r[2]), "=r"(r[3]) : "r"(addr));
}
__device__ __forceinline__ void mma16816(float* d, const uint32_t* a,
                                         const uint32_t* b) {
    asm volatile(
        "mma.sync.aligned.m16n8k16.row.col.f32.bf16.bf16.f32 "
        "{%0,%1,%2,%3}, {%4,%5,%6,%7}, {%8,%9}, {%0,%1,%2,%3};"
        : "+f"(d[0]), "+f"(d[1]), "+f"(d[2]), "+f"(d[3])
        : "r"(a[0]), "r"(a[1]), "r"(a[2]), "r"(a[3]), "r"(b[0]), "r"(b[1]));
}
__device__ __forceinline__ void mma1688_tf32(float* d, const uint32_t* a,
                                             const uint32_t* b) {
    asm volatile(
        "mma.sync.aligned.m16n8k8.row.col.f32.tf32.tf32.f32 "
        "{%0,%1,%2,%3}, {%4,%5,%6,%7}, {%8,%9}, {%0,%1,%2,%3};"
        : "+f"(d[0]), "+f"(d[1]), "+f"(d[2]), "+f"(d[3])
        : "r"(a[0]), "r"(a[1]), "r"(a[2]), "r"(a[3]), "r"(b[0]), "r"(b[1]));
}
__device__ __forceinline__ uint32_t sw128(uint32_t off) {
    return off ^ ((off >> 3) & 0x70);
}
__device__ __forceinline__ float tf32r(float x) {
    uint32_t u;
    asm("cvt.rna.tf32.f32 %0, %1;" : "=r"(u) : "f"(x));
    return __uint_as_float(u);
}
__device__ __forceinline__ uint32_t tf32b(float x) {
    uint32_t u;
    asm("cvt.rna.tf32.f32 %0, %1;" : "=r"(u) : "f"(x));
    return u;
}

// ---------------------------------------------------------------------------
// Prep kernels
// ---------------------------------------------------------------------------
__global__ __launch_bounds__(256) void round_tf32_kernel(
    const float* __restrict__ X, float* __restrict__ Y)
{
    size_t e = ((size_t)blockIdx.x * 256 + threadIdx.x) * 4;
    float4 x = *(const float4*)(X + e);
    x.x = tf32r(x.x); x.y = tf32r(x.y); x.z = tf32r(x.z); x.w = tf32r(x.w);
    *(float4*)(Y + e) = x;
}

__global__ __launch_bounds__(256) void cvt_wT_kernel(
    const float* __restrict__ W, float* __restrict__ Y, int K, int N)
{
    __shared__ float t[32][33];
    int n0 = blockIdx.x * 32;
    int k0 = blockIdx.y * 32;
    int tx = threadIdx.x;
    int ty = threadIdx.y;
#pragma unroll
    for (int i = 0; i < 32; i += 8)
        t[ty + i][tx] = W[(size_t)(k0 + ty + i) * N + n0 + tx];
    __syncthreads();
#pragma unroll
    for (int i = 0; i < 32; i += 8) {
        int n = n0 + ty + i;
        int k = k0 + tx;
        Y[(size_t)n * K + k] = tf32r(t[tx][ty + i]);
    }
}

// V^T: g_qkv v-section [b][s][kvh*128+d] -> g_vt [b][kvh][d][s], tf32-rounded
__global__ __launch_bounds__(256) void vT_kernel(
    const float* __restrict__ qkv, float* __restrict__ vt)
{
    __shared__ float t[32][33];
    const int s0 = blockIdx.x * 32;
    const int d0 = blockIdx.y * 32;
    const int bk = blockIdx.z;           // b*8 + kvh
    const int b  = bk >> 3;
    const int kvh = bk & 7;
    const int tx = threadIdx.x;
    const int ty = threadIdx.y;
#pragma unroll
    for (int i = 0; i < 32; i += 8)
        t[ty + i][tx] = qkv[(size_t)(b * cS + s0 + ty + i) * cNQKV +
                            3072 + kvh * cHD + d0 + tx];
    __syncthreads();
#pragma unroll
    for (int i = 0; i < 32; i += 8)
        vt[((size_t)bk * cHD + d0 + ty + i) * cS + s0 + tx] =
            tf32r(t[tx][ty + i]);
}

// ---------------------------------------------------------------------------
// TF32 HMMA GEMM: C[M,N] = A[M,K] @ B[N,K]^T (row-major fp32, tf32-prerounded)
// CTA tile 128x256, BK=32, 4-stage cp.async, SW128, warp tile 64x64.
// ---------------------------------------------------------------------------
namespace {
constexpr int GBM = 128, GBN = 256, GBK = 32;
constexpr int NSTAGE = 4;
constexpr int A_BYTES = GBM * GBK * 4;              // 16KB
constexpr int B_BYTES = GBN * GBK * 4;              // 32KB
constexpr int STAGE_BYTES = A_BYTES + B_BYTES;      // 48KB
constexpr int GEMM_SMEM   = NSTAGE * STAGE_BYTES;   // 192KB
}

__device__ __forceinline__ void gemm_load_stage(
    const float* __restrict__ Ag, const float* __restrict__ Bg,
    int K, int it, uint32_t stage_base, int tid)
{
#pragma unroll
    for (int i = 0; i < 4; i++) {
        int idx = tid + (i << 8);
        int row = idx >> 3;
        int c4  = idx & 7;
        uint32_t sw = sw128((uint32_t)(row * 128 + c4 * 16));
        cp_async16(stage_base + sw,
                   Ag + (size_t)row * K + (size_t)it * GBK + c4 * 4);
    }
#pragma unroll
    for (int i = 0; i < 8; i++) {
        int idx = tid + (i << 8);
        int row = idx >> 3;
        int c4  = idx & 7;
        uint32_t sw = sw128((uint32_t)(row * 128 + c4 * 16));
        cp_async16(stage_base + A_BYTES + sw,
                   Bg + (size_t)row * K + (size_t)it * GBK + c4 * 4);
    }
}

__global__ __launch_bounds__(256, 1)
void gemm_tf32_kernel(const float* __restrict__ A,
                      const float* __restrict__ B,
                      float* __restrict__ C, int M, int N, int K)
{
    extern __shared__ char smraw[];
    const uint32_t sbase = smem_u32(smraw);

    const int tid  = threadIdx.x;
    const int wid  = tid >> 5;
    const int lane = tid & 31;
    const int m0 = blockIdx.y * GBM;
    const int n0 = blockIdx.x * GBN;
    const int mw = (wid >> 2) * 64;
    const int nw = (wid & 3) * 64;

    const float* Ag = A + (size_t)m0 * K;
    const float* Bg = B + (size_t)n0 * K;
    const int KITERS = K / GBK;

    float acc[4][8][4];
#pragma unroll
    for (int i = 0; i < 4; i++)
#pragma unroll
        for (int j = 0; j < 8; j++)
#pragma unroll
            for (int r = 0; r < 4; r++) acc[i][j][r] = 0.f;

    const int a_row = lane & 15;
    const int a_cb  = (lane >> 4) * 16;
    const int b_row = (lane & 7) + ((lane >> 4) & 1) * 8;
    const int b_cb  = ((lane >> 3) & 1) * 16;

#pragma unroll
    for (int s = 0; s < NSTAGE - 1; s++) {
        gemm_load_stage(Ag, Bg, K, s, sbase + s * STAGE_BYTES, tid);
        CP_COMMIT();
    }

    for (int it = 0; it < KITERS; ++it) {
        CP_WAIT(NSTAGE - 2);
        __syncthreads();

        int nx = it + NSTAGE - 1;
        if (nx < KITERS)
            gemm_load_stage(Ag, Bg, K, nx,
                            sbase + (nx % NSTAGE) * STAGE_BYTES, tid);
        CP_COMMIT();

        const uint32_t sa = sbase + (it % NSTAGE) * STAGE_BYTES;
        const uint32_t sb = sa + A_BYTES;

#pragma unroll
        for (int ks = 0; ks < 4; ks++) {
            uint32_t af[4][4], bf[4][4];
#pragma unroll
            for (int mi = 0; mi < 4; mi++) {
                uint32_t off = (uint32_t)((mw + 16 * mi + a_row) * 128 +
                                          ks * 32 + a_cb);
                ldm_x4(af[mi], sa + sw128(off));
            }
#pragma unroll
            for (int njp = 0; njp < 4; njp++) {
                uint32_t off = (uint32_t)((nw + 16 * njp + b_row) * 128 +
                                          ks * 32 + b_cb);
                ldm_x4(bf[njp], sb + sw128(off));
            }
#pragma unroll
            for (int mi = 0; mi < 4; mi++)
#pragma unroll
                for (int njp = 0; njp < 4; njp++) {
                    mma1688_tf32(acc[mi][2 * njp],     af[mi], bf[njp]);
                    mma1688_tf32(acc[mi][2 * njp + 1], af[mi], bf[njp] + 2);
                }
        }
    }

    const int g = lane >> 2;
    const int t = lane & 3;
#pragma unroll
    for (int mi = 0; mi < 4; mi++) {
#pragma unroll
        for (int nj = 0; nj < 8; nj++) {
            int r0 = m0 + mw + 16 * mi + g;
            int cc = n0 + nw + 8 * nj + t * 2;
            *(float2*)(C + (size_t)r0 * N + cc) =
                make_float2(acc[mi][nj][0], acc[mi][nj][1]);
            *(float2*)(C + (size_t)(r0 + 8) * N + cc) =
                make_float2(acc[mi][nj][2], acc[mi][nj][3]);
        }
    }
}

// ---------------------------------------------------------------------------
// RMSNorm + RoPE + hi/lo bf16 split for Q and K only (V handled by vT_kernel).
// ---------------------------------------------------------------------------
__global__ __launch_bounds__(128) void norm_rope_split_kernel(
    const float* __restrict__ cosp, const float* __restrict__ sinp,
    const float* __restrict__ qw,   const float* __restrict__ kw)
{
    const int slot = blockIdx.x;
    const int bs   = blockIdx.y;
    const int d    = threadIdx.x;
    const int b    = bs >> 11;
    const int s    = bs & 2047;

    const float* src;
    const float* w;
    __nv_bfloat16 *dhi, *dlo;
    if (slot < 16) {
        src = g_qkv + (size_t)bs * cNQKV + slot * cHD;
        w = qw;
        size_t dst = ((size_t)(b * cNH + slot) * cS + s) * cHD;
        dhi = g_q2hi + dst; dlo = g_q2lo + dst;
    } else {
        src = g_qkv + (size_t)bs * cNQKV + 2048 + (slot - 16) * cHD;
        w = kw;
        size_t dst = ((size_t)(b * cNKV + (slot - 16)) * cS + s) * cHD;
        dhi = g_k2hi + dst; dlo = g_k2lo + dst;
    }
    float x = src[d];
    float v = x * x;
#pragma unroll
    for (int o = 16; o; o >>= 1) v += __shfl_xor_sync(0xffffffffu, v, o);
    __shared__ float wsum[4];
    if ((d & 31) == 0) wsum[d >> 5] = v;
    __syncthreads();
    float var = (wsum[0] + wsum[1] + wsum[2] + wsum[3]) * (1.f / cHD);
    float rs  = rsqrtf(var + cEPS);
    float xn  = x * rs * w[d];

    __shared__ float buf[cHD];
    buf[d] = xn;
    __syncthreads();
    float other = (d < cHD / 2) ? -buf[d + cHD / 2] : buf[d - cHD / 2];
    float cv = cosp[(size_t)bs * cHD + d];
    float sv = sinp[(size_t)bs * cHD + d];
    float val = xn * cv + other * sv;

    __nv_bfloat16 hi = __float2bfloat16(val);
    __nv_bfloat16 lo = __float2bfloat16(val - __bfloat162float(hi));
    dhi[d] = hi;
    dlo[d] = lo;
}

// ---------------------------------------------------------------------------
// Single-pass MMA attention, ONE head per 128-thread CTA, 2 CTAs/SM.
// QK bf16 3-term, PV tf32 via K-row-permute trick. Single-buffered KV
// (cross-CTA overlap replaces intra-CTA double buffering).
// Fused weight normalize (scattered own-writes form) + zero-fill.
// ---------------------------------------------------------------------------
namespace {
constexpr int AKTB = 64 * 272;            // 17408 (64 rows x 272B)
constexpr int AVTB = 128 * 272;           // 34816 (V^T tile)
constexpr int AQ_BYTES  = 2 * AKTB;       // Q hi/lo
constexpr int AKV_BYTES = 2 * AKTB + AVTB;
constexpr int ATTN_SMEM = AQ_BYTES + AKV_BYTES;   // 104448 -> 2 CTAs/SM
__device__ __constant__ int c_kperm[8] = {0, 2, 4, 6, 1, 3, 5, 7};
}

__global__ __launch_bounds__(128, 2)
void attn_mma_kernel(const __nv_bfloat16* __restrict__ qhi_g,
                     const __nv_bfloat16* __restrict__ qlo_g,
                     const __nv_bfloat16* __restrict__ khi_g,
                     const __nv_bfloat16* __restrict__ klo_g,
                     const float* __restrict__ vt_g,
                     float* __restrict__ wout,
                     float* __restrict__ outp,
                     int write_w)
{
    extern __shared__ char smraw[];
    const uint32_t uQ  = smem_u32(smraw);
    const uint32_t uKV = uQ + AQ_BYTES;

    const int tid  = threadIdx.x;
    const int wid  = tid >> 5;
    const int lane = tid & 31;
    const int qt = gridDim.y - 1 - blockIdx.y;     // heavy-first
    const int bh = blockIdx.x;
    const int b  = bh >> 4;
    const int h  = bh & 15;
    const int kvh = h >> 1;
    const int wr = wid * 16;
    const int q0 = qt * 64;
    const int g  = lane >> 2;
    const int t  = lane & 3;

    // ---- Q tiles (hi, lo) for this head: 64 rows x 256B each
    {
        const size_t qrow = ((size_t)(b * cNH + h) * cS + q0) * cHD;
        const int row = tid >> 4;          // 0..7
        const int c   = tid & 15;
#pragma unroll
        for (int i = 0; i < 16; i++) {
            const int tile = i >> 3;
            const int rr = (i & 7) * 8 + row;
            const __nv_bfloat16* base = tile ? qlo_g : qhi_g;
            cp_async16(uQ + tile * AKTB + rr * 272 + c * 16,
                       base + qrow + (size_t)rr * cHD + c * 8);
        }
    }
    CP_COMMIT();

    const size_t krow0 = ((size_t)(b * cNKV + kvh) * cS) * cHD;
    const size_t vbase = ((size_t)(b * cNKV + kvh) * cHD) * cS;
    const int lrow = tid >> 4;             // 0..7
    const int lc   = tid & 15;

#define LOAD_KV(kt_)                                                          \
    do {                                                                      \
        const size_t krow = krow0 + (size_t)((kt_) * 64) * cHD;               \
        _Pragma("unroll")                                                     \
        for (int i = 0; i < 16; i++) {                                        \
            const int tile = i >> 3;                                          \
            const int rr = (i & 7) * 8 + lrow;                                \
            const int srr = (rr & 0x38) | c_kperm[rr & 7];                    \
            const __nv_bfloat16* base = tile ? klo_g : khi_g;                 \
            cp_async16(uKV + tile * AKTB + srr * 272 + lc * 16,               \
                       base + krow + (size_t)rr * cHD + lc * 8);              \
        }                                                                     \
        _Pragma("unroll")                                                     \
        for (int i = 0; i < 16; i++) {                                        \
            const int dd = i * 8 + lrow;                                      \
            cp_async16(uKV + 2 * AKTB + dd * 272 + lc * 16,                   \
                       vt_g + vbase + (size_t)dd * cS + (kt_) * 64 + lc * 4); \
        }                                                                     \
    } while (0)

    LOAD_KV(0);
    CP_COMMIT();
    CP_WAIT(0);
    __syncthreads();

    // ldmatrix per-lane offsets
    const uint32_t qoff = (uint32_t)((wr + (lane & 15)) * 272 + (lane >> 4) * 16);
    const uint32_t koff = (uint32_t)(((lane & 7) + ((lane >> 4) & 1) * 8) * 272 +
                                     ((lane >> 3) & 1) * 16);
    const uint32_t voff = (uint32_t)(((lane & 7) + ((lane >> 4) & 1) * 8) * 272 +
                                     ((lane >> 3) & 1) * 16);
    const uint32_t uQh = uQ;
    const uint32_t uQl = uQ + AKTB;
    const uint32_t ukhi = uKV;
    const uint32_t uklo = uKV + AKTB;
    const uint32_t uvt  = uKV + 2 * AKTB;

    float oacc[16][4];
#pragma unroll
    for (int i = 0; i < 16; i++)
#pragma unroll
        for (int r = 0; r < 4; r++) oacc[i][r] = 0.f;
    float l0 = 0.f, l1 = 0.f;

    for (int kt = 0; kt <= qt; kt++) {
        // ---------- QK: 3-term bf16 hi/lo ----------
        float sacc[8][4];
#pragma unroll
        for (int i = 0; i < 8; i++)
#pragma unroll
            for (int r = 0; r < 4; r++) sacc[i][r] = 0.f;

#pragma unroll
        for (int kk = 0; kk < 8; kk++) {
            uint32_t qh[4], ql[4];
            ldm_x4(qh, uQh + qoff + kk * 32);
            ldm_x4(ql, uQl + qoff + kk * 32);
#pragma unroll
            for (int njp = 0; njp < 4; njp++) {
                uint32_t kb[4];
                ldm_x4(kb, ukhi + njp * (16 * 272) + koff + kk * 32);
                mma16816(sacc[2 * njp],     qh, kb);
                mma16816(sacc[2 * njp + 1], qh, kb + 2);
                mma16816(sacc[2 * njp],     ql, kb);
                mma16816(sacc[2 * njp + 1], ql, kb + 2);
            }
#pragma unroll
            for (int njp = 0; njp < 4; njp++) {
                uint32_t kb[4];
                ldm_x4(kb, uklo + njp * (16 * 272) + koff + kk * 32);
                mma16816(sacc[2 * njp],     qh, kb);
                mma16816(sacc[2 * njp + 1], qh, kb + 2);
            }
        }

        // ---------- exp, mask, sums, weight write, tf32 A-fragments ----------
        const bool diag = (kt == qt);
        uint32_t pt[8][4];
#pragma unroll
        for (int nj = 0; nj < 8; nj++) {
            float p0 = __expf(sacc[nj][0] * cSCALE);   // (r0, cb+t)
            float p1 = __expf(sacc[nj][1] * cSCALE);   // (r0, cb+t+4)
            float p2 = __expf(sacc[nj][2] * cSCALE);   // (r1, cb+t)
            float p3 = __expf(sacc[nj][3] * cSCALE);   // (r1, cb+t+4)
            if (diag) {
                const int col0 = nj * 8 + t;
                const int col1 = col0 + 4;
                const int rlo = wr + g, rhi = wr + 8 + g;
                if (col0 > rlo) p0 = 0.f;
                if (col1 > rlo) p1 = 0.f;
                if (col0 > rhi) p2 = 0.f;
                if (col1 > rhi) p3 = 0.f;
            }
            l0 += p0 + p1;
            l1 += p2 + p3;
            if (write_w) {
                float* w0 = wout + ((size_t)(b * cNH + h) * cS + q0 + wr + g) * cS
                            + kt * 64 + nj * 8 + t;
                w0[0] = p0;
                w0[4] = p1;
                float* w1 = w0 + 8 * (size_t)cS;
                w1[0] = p2;
                w1[4] = p3;
            }
            pt[nj][0] = tf32b(p0);
            pt[nj][1] = tf32b(p2);
            pt[nj][2] = tf32b(p1);
            pt[nj][3] = tf32b(p3);
        }

        // ---------- PV: tf32, V^T [d][s] fp32 ----------
#pragma unroll
        for (int nj = 0; nj < 8; nj++) {
#pragma unroll
            for (int nd2 = 0; nd2 < 8; nd2++) {
                uint32_t vb[4];
                ldm_x4(vb, uvt + nd2 * (16 * 272) + nj * 32 + voff);
                mma1688_tf32(oacc[2 * nd2],     pt[nj], vb);
                mma1688_tf32(oacc[2 * nd2 + 1], pt[nj], vb + 2);
            }
        }

        // ---------- refill single KV buffer ----------
        __syncthreads();                    // all smem reads done
        if (kt < qt) {
            LOAD_KV(kt + 1);
            CP_COMMIT();
            CP_WAIT(0);
            __syncthreads();                // buffer ready
        }
    }

    l0 += __shfl_xor_sync(0xffffffffu, l0, 1);
    l0 += __shfl_xor_sync(0xffffffffu, l0, 2);
    l1 += __shfl_xor_sync(0xffffffffu, l1, 1);
    l1 += __shfl_xor_sync(0xffffffffu, l1, 2);
    const float inv0 = 1.f / l0;
    const float inv1 = 1.f / l1;

    // ---- PV output (normalized, tf32-rounded for the Wo GEMM) ----
#pragma unroll
    for (int nd = 0; nd < 16; nd++) {
        const int col = nd * 8 + 2 * t;
        float* o0 = outp + ((size_t)(b * cS + q0 + wr + g) * cNH + h) * cHD + col;
        float* o1 = outp + ((size_t)(b * cS + q0 + wr + 8 + g) * cNH + h) * cHD + col;
        *(float2*)o0 = make_float2(tf32r(oacc[nd][0] * inv0),
                                   tf32r(oacc[nd][1] * inv0));
        *(float2*)o1 = make_float2(tf32r(oacc[nd][2] * inv1),
                                   tf32r(oacc[nd][3] * inv1));
    }

    // ---- fused weight normalization (rescale own writes) ----
    if (write_w) {
        const size_t rb0 = ((size_t)(b * cNH + h) * cS + q0 + wr + g) * cS;
        const size_t rb1 = rb0 + 8 * (size_t)cS;
        for (int kt = 0; kt <= qt; kt++) {
#pragma unroll
            for (int nj = 0; nj < 8; nj++) {
                const int cc = kt * 64 + nj * 8 + t;
                float* w0 = wout + rb0 + cc;
                w0[0] *= inv0;
                w0[4] *= inv0;
                float* w1 = wout + rb1 + cc;
                w1[0] *= inv1;
                w1[4] *= inv1;
            }
        }
        // ---- zero the upper-triangle tail of this CTA's 64 rows
        const int zc = cS - (q0 + 64);
        if (zc > 0) {
            const int z4 = zc >> 2;
            const int tot = 64 * z4;
            const float4 z = make_float4(0.f, 0.f, 0.f, 0.f);
            for (int i = tid; i < tot; i += 128) {
                const int r  = i / z4;
                const int c4 = i - r * z4;
                float* p = wout +
                    ((size_t)(b * cNH + h) * cS + q0 + r) * cS +
                    q0 + 64 + c4 * 4;
                *(float4*)p = z;
            }
        }
    }
}

// ---------------------------------------------------------------------------
// Launch (single stream)
// ---------------------------------------------------------------------------
extern "C" void kernel_launch(void* const* d_in, const int* in_sizes, int n_in,
                              void* d_out, int out_size)
{
    const float* hidden = (const float*)d_in[0];
    const float* cosp   = (const float*)d_in[1];
    const float* sinp   = (const float*)d_in[2];
    const float* wq  = (const float*)d_in[4];
    const float* wk  = (const float*)d_in[5];
    const float* wv  = (const float*)d_in[6];
    const float* wo  = (const float*)d_in[7];
    const float* qnw = (const float*)d_in[8];
    const float* knw = (const float*)d_in[9];

    float* out = (float*)d_out;
    const size_t n_attn = (size_t)cM * cHID;
    const size_t n_w    = (size_t)cB * cNH * cS * cS;
    const int write_w   = ((size_t)out_size >= n_attn + n_w) ? 1 : 0;
    float* weights = out + n_attn;

    float *pahf, *pqkv, *pa, *pwt, *pwot, *pvt;
    cudaGetSymbolAddress((void**)&pahf, g_ahf);
    cudaGetSymbolAddress((void**)&pqkv, g_qkv);
    cudaGetSymbolAddress((void**)&pa,   g_att);
    cudaGetSymbolAddress((void**)&pwt,  g_wt);
    cudaGetSymbolAddress((void**)&pwot, g_wot);
    cudaGetSymbolAddress((void**)&pvt,  g_vt);
    __nv_bfloat16 *pqh, *pql, *pkh, *pklo;
    cudaGetSymbolAddress((void**)&pqh,  g_q2hi);
    cudaGetSymbolAddress((void**)&pql,  g_q2lo);
    cudaGetSymbolAddress((void**)&pkh,  g_k2hi);
    cudaGetSymbolAddress((void**)&pklo, g_k2lo);

    static bool attr_done = false;
    if (!attr_done) {
        cudaFuncSetAttribute(gemm_tf32_kernel,
                             cudaFuncAttributeMaxDynamicSharedMemorySize, GEMM_SMEM);
        cudaFuncSetAttribute(attn_mma_kernel,
                             cudaFuncAttributeMaxDynamicSharedMemorySize, ATTN_SMEM);
        attr_done = true;
    }

    // --- prep: tf32-rounded A, transposed+rounded weights ---
    round_tf32_kernel<<<(cM * cHID / 4) / 256, 256>>>(hidden, pahf);
    cvt_wT_kernel<<<dim3(2048 / 32, 2048 / 32), dim3(32, 8)>>>(
        wq, pwt, cHID, 2048);
    cvt_wT_kernel<<<dim3(1024 / 32, 2048 / 32), dim3(32, 8)>>>(
        wk, pwt + (size_t)2048 * cHID, cHID, 1024);
    cvt_wT_kernel<<<dim3(1024 / 32, 2048 / 32), dim3(32, 8)>>>(
        wv, pwt + (size_t)3072 * cHID, cHID, 1024);
    cvt_wT_kernel<<<dim3(2048 / 32, 2048 / 32), dim3(32, 8)>>>(
        wo, pwot, cHID, 2048);

    // --- fused QKV projection (tf32) ---
    gemm_tf32_kernel<<<dim3(cNQKV / GBN, cM / GBM), 256, GEMM_SMEM>>>(
        pahf, pwt, pqkv, cM, cNQKV, cHID);

    // --- RMSNorm + RoPE + bf16 hi/lo split (Q,K); V^T transpose (tf32) ---
    norm_rope_split_kernel<<<dim3(24, cM), 128>>>(cosp, sinp, qnw, knw);
    vT_kernel<<<dim3(cS / 32, cHD / 32, cB * cNKV), dim3(32, 8)>>>(pqkv, pvt);

    // --- single-pass MMA attention (1 head/CTA, 2 CTAs/SM) ---
    attn_mma_kernel<<<dim3(cB * cNH, cS / 64), 128, ATTN_SMEM>>>(
        pqh, pql, pkh, pklo, pvt, weights, pa, write_w);

    // --- output projection (tf32) ---
    gemm_tf32_kernel<<<dim3(cHID / GBN, cM / GBM), 256, GEMM_SMEM>>>(
        pa, pwot, out, cM, cHID, cHID);
}

// round 13
// speedup vs baseline: 1.2031x; 1.0306x over previous
#include <cuda_runtime.h>
#include <cuda_bf16.h>
#include <math.h>
#include <stdint.h>

// ---------------------------------------------------------------------------
// Problem constants
// ---------------------------------------------------------------------------
namespace {
constexpr int cB   = 2;
constexpr int cS   = 2048;
constexpr int cHID = 2048;
constexpr int cNH  = 16;
constexpr int cNKV = 8;
constexpr int cHD  = 128;
constexpr float cEPS   = 1e-6f;
constexpr float cSCALE = 0.08838834764831845f;  // 128^-0.5
constexpr int cM   = cB * cS;        // 4096
constexpr int cNQKV = 4096;          // fused QKV output width
}

// ---------------------------------------------------------------------------
// Scratch (device globals -- no runtime allocation allowed)
// ---------------------------------------------------------------------------
__device__ float g_ahf [(size_t)cM * cHID];        // tf32-rounded hidden
__device__ float g_qkv [(size_t)cM * cNQKV];       // fused QKV projection out
__device__ float g_att [(size_t)cM * cNH * cHD];   // attn out pre-Wo (tf32-rounded)
__device__ float g_wt  [(size_t)cNQKV * cHID];     // [wq|wk|wv]^T tf32-rounded
__device__ float g_wot [(size_t)cHID * cHID];      // wo^T tf32-rounded
__device__ float g_vt  [(size_t)cB * cNKV * cHD * cS]; // V^T fp32 [b][kvh][d][s]

// bf16 hi/lo planes for attention QK, head-major layout [b][h][s][d]
__device__ __nv_bfloat16 g_q2hi[(size_t)cB * cNH  * cS * cHD];
__device__ __nv_bfloat16 g_q2lo[(size_t)cB * cNH  * cS * cHD];
__device__ __nv_bfloat16 g_k2hi[(size_t)cB * cNKV * cS * cHD];
__device__ __nv_bfloat16 g_k2lo[(size_t)cB * cNKV * cS * cHD];

// ---------------------------------------------------------------------------
// PTX helpers (portable: sm_80+)
// ---------------------------------------------------------------------------
__device__ __forceinline__ uint32_t smem_u32(const void* p) {
    uint32_t a;
    asm("{ .reg .u64 t; cvta.to.shared.u64 t, %1; cvt.u32.u64 %0, t; }"
        : "=r"(a) : "l"(p));
    return a;
}
__device__ __forceinline__ void cp_async16(uint32_t saddr, const void* gaddr) {
    asm volatile("cp.async.cg.shared.global [%0], [%1], 16;"
                 :: "r"(saddr), "l"(gaddr) : "memory");
}
#define CP_COMMIT()  asm volatile("cp.async.commit_group;" ::: "memory")
#define CP_WAIT(N)   asm volatile("cp.async.wait_group %0;" :: "n"(N) : "memory")

__device__ __forceinline__ void ldm_x4(uint32_t* r, uint32_t addr) {
    asm volatile("ldmatrix.sync.aligned.m8n8.x4.shared.b16 {%0,%1,%2,%3}, [%4];"
                 : "=r"(r[0]), "=r"(r[1]), "=r"(r[2]), "=r"(r[3]) : "r"(addr));
}
__device__ __forceinline__ void mma16816(float* d, const uint32_t* a,
                                         const uint32_t* b) {
    asm volatile(
        "mma.sync.aligned.m16n8k16.row.col.f32.bf16.bf16.f32 "
        "{%0,%1,%2,%3}, {%4,%5,%6,%7}, {%8,%9}, {%0,%1,%2,%3};"
        : "+f"(d[0]), "+f"(d[1]), "+f"(d[2]), "+f"(d[3])
        : "r"(a[0]), "r"(a[1]), "r"(a[2]), "r"(a[3]), "r"(b[0]), "r"(b[1]));
}
__device__ __forceinline__ void mma1688_tf32(float* d, const uint32_t* a,
                                             const uint32_t* b) {
    asm volatile(
        "mma.sync.aligned.m16n8k8.row.col.f32.tf32.tf32.f32 "
        "{%0,%1,%2,%3}, {%4,%5,%6,%7}, {%8,%9}, {%0,%1,%2,%3};"
        : "+f"(d[0]), "+f"(d[1]), "+f"(d[2]), "+f"(d[3])
        : "r"(a[0]), "r"(a[1]), "r"(a[2]), "r"(a[3]), "r"(b[0]), "r"(b[1]));
}
__device__ __forceinline__ uint32_t sw128(uint32_t off) {
    return off ^ ((off >> 3) & 0x70);
}
__device__ __forceinline__ float tf32r(float x) {
    uint32_t u;
    asm("cvt.rna.tf32.f32 %0, %1;" : "=r"(u) : "f"(x));
    return __uint_as_float(u);
}
__device__ __forceinline__ uint32_t tf32b(float x) {
    uint32_t u;
    asm("cvt.rna.tf32.f32 %0, %1;" : "=r"(u) : "f"(x));
    return u;
}

// ---------------------------------------------------------------------------
// Prep kernels
// ---------------------------------------------------------------------------
__global__ __launch_bounds__(256) void round_tf32_kernel(
    const float* __restrict__ X, float* __restrict__ Y)
{
    size_t e = ((size_t)blockIdx.x * 256 + threadIdx.x) * 4;
    float4 x = *(const float4*)(X + e);
    x.x = tf32r(x.x); x.y = tf32r(x.y); x.z = tf32r(x.z); x.w = tf32r(x.w);
    *(float4*)(Y + e) = x;
}

__global__ __launch_bounds__(256) void cvt_wT_kernel(
    const float* __restrict__ W, float* __restrict__ Y, int K, int N)
{
    __shared__ float t[32][33];
    int n0 = blockIdx.x * 32;
    int k0 = blockIdx.y * 32;
    int tx = threadIdx.x;
    int ty = threadIdx.y;
#pragma unroll
    for (int i = 0; i < 32; i += 8)
        t[ty + i][tx] = W[(size_t)(k0 + ty + i) * N + n0 + tx];
    __syncthreads();
#pragma unroll
    for (int i = 0; i < 32; i += 8) {
        int n = n0 + ty + i;
        int k = k0 + tx;
        Y[(size_t)n * K + k] = tf32r(t[tx][ty + i]);
    }
}

// V^T: g_qkv v-section [b][s][kvh*128+d] -> g_vt [b][kvh][d][s], tf32-rounded
__global__ __launch_bounds__(256) void vT_kernel(
    const float* __restrict__ qkv, float* __restrict__ vt)
{
    __shared__ float t[32][33];
    const int s0 = blockIdx.x * 32;
    const int d0 = blockIdx.y * 32;
    const int bk = blockIdx.z;           // b*8 + kvh
    const int b  = bk >> 3;
    const int kvh = bk & 7;
    const int tx = threadIdx.x;
    const int ty = threadIdx.y;
#pragma unroll
    for (int i = 0; i < 32; i += 8)
        t[ty + i][tx] = qkv[(size_t)(b * cS + s0 + ty + i) * cNQKV +
                            3072 + kvh * cHD + d0 + tx];
    __syncthreads();
#pragma unroll
    for (int i = 0; i < 32; i += 8)
        vt[((size_t)bk * cHD + d0 + ty + i) * cS + s0 + tx] =
            tf32r(t[tx][ty + i]);
}

// ---------------------------------------------------------------------------
// TF32 HMMA GEMM: C[M,N] = A[M,K] @ B[N,K]^T (row-major fp32, tf32-prerounded)
// CTA tile 128x256, BK=32, 4-stage cp.async, SW128, warp tile 64x64.
// ---------------------------------------------------------------------------
namespace {
constexpr int GBM = 128, GBN = 256, GBK = 32;
constexpr int NSTAGE = 4;
constexpr int A_BYTES = GBM * GBK * 4;              // 16KB
constexpr int B_BYTES = GBN * GBK * 4;              // 32KB
constexpr int STAGE_BYTES = A_BYTES + B_BYTES;      // 48KB
constexpr int GEMM_SMEM   = NSTAGE * STAGE_BYTES;   // 192KB
}

__device__ __forceinline__ void gemm_load_stage(
    const float* __restrict__ Ag, const float* __restrict__ Bg,
    int K, int it, uint32_t stage_base, int tid)
{
#pragma unroll
    for (int i = 0; i < 4; i++) {
        int idx = tid + (i << 8);
        int row = idx >> 3;
        int c4  = idx & 7;
        uint32_t sw = sw128((uint32_t)(row * 128 + c4 * 16));
        cp_async16(stage_base + sw,
                   Ag + (size_t)row * K + (size_t)it * GBK + c4 * 4);
    }
#pragma unroll
    for (int i = 0; i < 8; i++) {
        int idx = tid + (i << 8);
        int row = idx >> 3;
        int c4  = idx & 7;
        uint32_t sw = sw128((uint32_t)(row * 128 + c4 * 16));
        cp_async16(stage_base + A_BYTES + sw,
                   Bg + (size_t)row * K + (size_t)it * GBK + c4 * 4);
    }
}

__global__ __launch_bounds__(256, 1)
void gemm_tf32_kernel(const float* __restrict__ A,
                      const float* __restrict__ B,
                      float* __restrict__ C, int M, int N, int K)
{
    extern __shared__ char smraw[];
    const uint32_t sbase = smem_u32(smraw);

    const int tid  = threadIdx.x;
    const int wid  = tid >> 5;
    const int lane = tid & 31;
    const int m0 = blockIdx.y * GBM;
    const int n0 = blockIdx.x * GBN;
    const int mw = (wid >> 2) * 64;
    const int nw = (wid & 3) * 64;

    const float* Ag = A + (size_t)m0 * K;
    const float* Bg = B + (size_t)n0 * K;
    const int KITERS = K / GBK;

    float acc[4][8][4];
#pragma unroll
    for (int i = 0; i < 4; i++)
#pragma unroll
        for (int j = 0; j < 8; j++)
#pragma unroll
            for (int r = 0; r < 4; r++) acc[i][j][r] = 0.f;

    const int a_row = lane & 15;
    const int a_cb  = (lane >> 4) * 16;
    const int b_row = (lane & 7) + ((lane >> 4) & 1) * 8;
    const int b_cb  = ((lane >> 3) & 1) * 16;

#pragma unroll
    for (int s = 0; s < NSTAGE - 1; s++) {
        gemm_load_stage(Ag, Bg, K, s, sbase + s * STAGE_BYTES, tid);
        CP_COMMIT();
    }

    for (int it = 0; it < KITERS; ++it) {
        CP_WAIT(NSTAGE - 2);
        __syncthreads();

        int nx = it + NSTAGE - 1;
        if (nx < KITERS)
            gemm_load_stage(Ag, Bg, K, nx,
                            sbase + (nx % NSTAGE) * STAGE_BYTES, tid);
        CP_COMMIT();

        const uint32_t sa = sbase + (it % NSTAGE) * STAGE_BYTES;
        const uint32_t sb = sa + A_BYTES;

#pragma unroll
        for (int ks = 0; ks < 4; ks++) {
            uint32_t af[4][4], bf[4][4];
#pragma unroll
            for (int mi = 0; mi < 4; mi++) {
                uint32_t off = (uint32_t)((mw + 16 * mi + a_row) * 128 +
                                          ks * 32 + a_cb);
                ldm_x4(af[mi], sa + sw128(off));
            }
#pragma unroll
            for (int njp = 0; njp < 4; njp++) {
                uint32_t off = (uint32_t)((nw + 16 * njp + b_row) * 128 +
                                          ks * 32 + b_cb);
                ldm_x4(bf[njp], sb + sw128(off));
            }
#pragma unroll
            for (int mi = 0; mi < 4; mi++)
#pragma unroll
                for (int njp = 0; njp < 4; njp++) {
                    mma1688_tf32(acc[mi][2 * njp],     af[mi], bf[njp]);
                    mma1688_tf32(acc[mi][2 * njp + 1], af[mi], bf[njp] + 2);
                }
        }
    }

    const int g = lane >> 2;
    const int t = lane & 3;
#pragma unroll
    for (int mi = 0; mi < 4; mi++) {
#pragma unroll
        for (int nj = 0; nj < 8; nj++) {
            int r0 = m0 + mw + 16 * mi + g;
            int cc = n0 + nw + 8 * nj + t * 2;
            *(float2*)(C + (size_t)r0 * N + cc) =
                make_float2(acc[mi][nj][0], acc[mi][nj][1]);
            *(float2*)(C + (size_t)(r0 + 8) * N + cc) =
                make_float2(acc[mi][nj][2], acc[mi][nj][3]);
        }
    }
}

// ---------------------------------------------------------------------------
// RMSNorm + RoPE + hi/lo bf16 split for Q and K only (V handled by vT_kernel).
// ---------------------------------------------------------------------------
__global__ __launch_bounds__(128) void norm_rope_split_kernel(
    const float* __restrict__ cosp, const float* __restrict__ sinp,
    const float* __restrict__ qw,   const float* __restrict__ kw)
{
    const int slot = blockIdx.x;
    const int bs   = blockIdx.y;
    const int d    = threadIdx.x;
    const int b    = bs >> 11;
    const int s    = bs & 2047;

    const float* src;
    const float* w;
    __nv_bfloat16 *dhi, *dlo;
    if (slot < 16) {
        src = g_qkv + (size_t)bs * cNQKV + slot * cHD;
        w = qw;
        size_t dst = ((size_t)(b * cNH + slot) * cS + s) * cHD;
        dhi = g_q2hi + dst; dlo = g_q2lo + dst;
    } else {
        src = g_qkv + (size_t)bs * cNQKV + 2048 + (slot - 16) * cHD;
        w = kw;
        size_t dst = ((size_t)(b * cNKV + (slot - 16)) * cS + s) * cHD;
        dhi = g_k2hi + dst; dlo = g_k2lo + dst;
    }
    float x = src[d];
    float v = x * x;
#pragma unroll
    for (int o = 16; o; o >>= 1) v += __shfl_xor_sync(0xffffffffu, v, o);
    __shared__ float wsum[4];
    if ((d & 31) == 0) wsum[d >> 5] = v;
    __syncthreads();
    float var = (wsum[0] + wsum[1] + wsum[2] + wsum[3]) * (1.f / cHD);
    float rs  = rsqrtf(var + cEPS);
    float xn  = x * rs * w[d];

    __shared__ float buf[cHD];
    buf[d] = xn;
    __syncthreads();
    float other = (d < cHD / 2) ? -buf[d + cHD / 2] : buf[d - cHD / 2];
    float cv = cosp[(size_t)bs * cHD + d];
    float sv = sinp[(size_t)bs * cHD + d];
    float val = xn * cv + other * sv;

    __nv_bfloat16 hi = __float2bfloat16(val);
    __nv_bfloat16 lo = __float2bfloat16(val - __bfloat162float(hi));
    dhi[d] = hi;
    dlo[d] = lo;
}

// ---------------------------------------------------------------------------
// TWO-PASS single-kernel MMA attention (R9 spine: 2 heads/CTA, 256 thr).
// Pass 1: K-only pipeline, QK + exp, accumulate l (no stores, no V).
// Pass 2: K+V pipeline, recompute QK/exp, store NORMALIZED weights once,
//         PV on raw p (tf32 via K-row-permute trick), scale output by inv.
// Weights buffer is written exactly once -- no RMW rescale pass.
// ---------------------------------------------------------------------------
namespace {
constexpr int KTB = 64 * 272;          // K tile bytes (64 rows x 272B)
constexpr int VTB = 128 * 272;         // V^T tile bytes
constexpr int KVSTAGE = 2 * KTB + VTB;
constexpr int ATTN_SMEM = 4 * KTB + 2 * KVSTAGE;   // 208896
__device__ __constant__ int c_kperm[8] = {0, 2, 4, 6, 1, 3, 5, 7};
}

__global__ __launch_bounds__(256, 1)
void attn_mma_kernel(const __nv_bfloat16* __restrict__ qhi_g,
                     const __nv_bfloat16* __restrict__ qlo_g,
                     const __nv_bfloat16* __restrict__ khi_g,
                     const __nv_bfloat16* __restrict__ klo_g,
                     const float* __restrict__ vt_g,
                     float* __restrict__ wout,
                     float* __restrict__ outp,
                     int write_w)
{
    extern __shared__ char smraw[];
    const uint32_t uQ  = smem_u32(smraw);
    const uint32_t uKV = uQ + 4 * KTB;

    const int tid  = threadIdx.x;
    const int wid  = tid >> 5;
    const int lane = tid & 31;
    const int qt  = gridDim.y - 1 - blockIdx.y;    // heavy-first
    const int bkv = blockIdx.x;
    const int b   = bkv >> 3;
    const int kvh = bkv & 7;
    const int hs  = wid >> 2;
    const int h   = kvh * 2 + hs;
    const int wr  = (wid & 3) * 16;
    const int q0  = qt * 64;
    const int g   = lane >> 2;
    const int t   = lane & 3;

    // ---- Q tiles (4: h0hi, h0lo, h1hi, h1lo)
    {
        const size_t qrow = ((size_t)(b * cNH + kvh * 2) * cS + q0) * cHD;
        const int row = (tid >> 4);
        const int c   = tid & 15;
#pragma unroll
        for (int i = 0; i < 16; i++) {
            const int tile = i >> 2;
            const int rr = (i & 3) * 16 + row;
            const __nv_bfloat16* base = (tile & 1) ? qlo_g : qhi_g;
            const __nv_bfloat16* src = base + qrow +
                (size_t)(tile >> 1) * cS * cHD + (size_t)rr * cHD + c * 8;
            cp_async16(uQ + tile * KTB + rr * 272 + c * 16, src);
        }
    }
    CP_COMMIT();

    const size_t krow0 = ((size_t)(b * cNKV + kvh) * cS) * cHD;
    const size_t vbase = ((size_t)(b * cNKV + kvh) * cHD) * cS;
    const int lrow = (tid >> 4);
    const int lc   = tid & 15;

#define LOAD_K_STAGE(kt_, st_)                                                \
    do {                                                                      \
        const uint32_t ust = uKV + (st_) * KVSTAGE;                           \
        const size_t krow = krow0 + (size_t)((kt_) * 64) * cHD;               \
        _Pragma("unroll")                                                     \
        for (int i = 0; i < 8; i++) {                                         \
            const int tile = i >> 2;                                          \
            const int rr = (i & 3) * 16 + lrow;                               \
            const int srr = (rr & 0x38) | c_kperm[rr & 7];                    \
            const __nv_bfloat16* base = tile ? klo_g : khi_g;                 \
            cp_async16(ust + tile * KTB + srr * 272 + lc * 16,                \
                       base + krow + (size_t)rr * cHD + lc * 8);              \
        }                                                                     \
    } while (0)

#define LOAD_V_STAGE(kt_, st_)                                                \
    do {                                                                      \
        const uint32_t ust = uKV + (st_) * KVSTAGE;                           \
        _Pragma("unroll")                                                     \
        for (int i = 0; i < 8; i++) {                                         \
            const int dd = i * 16 + lrow;                                     \
            cp_async16(ust + 2 * KTB + dd * 272 + lc * 16,                    \
                       vt_g + vbase + (size_t)dd * cS + (kt_) * 64 + lc * 4); \
        }                                                                     \
    } while (0)

    // ldmatrix per-lane offsets
    const uint32_t qoff = (uint32_t)((wr + (lane & 15)) * 272 + (lane >> 4) * 16);
    const uint32_t koff = (uint32_t)(((lane & 7) + ((lane >> 4) & 1) * 8) * 272 +
                                     ((lane >> 3) & 1) * 16);
    const uint32_t voff = (uint32_t)(((lane & 7) + ((lane >> 4) & 1) * 8) * 272 +
                                     ((lane >> 3) & 1) * 16);
    const uint32_t uQh = uQ + hs * 2 * KTB;
    const uint32_t uQl = uQh + KTB;

    float l0 = 0.f, l1 = 0.f;

    // =================== PASS 1: l accumulation (K only) ===================
    LOAD_K_STAGE(0, 0);
    CP_COMMIT();

    for (int kt = 0; kt <= qt; kt++) {
        if (kt < qt) {
            LOAD_K_STAGE(kt + 1, (kt + 1) & 1);
            CP_COMMIT();
            CP_WAIT(1);
        } else {
            CP_WAIT(0);
        }
        __syncthreads();

        const uint32_t ust  = uKV + (kt & 1) * KVSTAGE;
        const uint32_t ukhi = ust;
        const uint32_t uklo = ust + KTB;

        float sacc[8][4];
#pragma unroll
        for (int i = 0; i < 8; i++)
#pragma unroll
            for (int r = 0; r < 4; r++) sacc[i][r] = 0.f;

#pragma unroll
        for (int kk = 0; kk < 8; kk++) {
            uint32_t qh[4], ql[4];
            ldm_x4(qh, uQh + qoff + kk * 32);
            ldm_x4(ql, uQl + qoff + kk * 32);
#pragma unroll
            for (int njp = 0; njp < 4; njp++) {
                uint32_t kb[4];
                ldm_x4(kb, ukhi + njp * (16 * 272) + koff + kk * 32);
                mma16816(sacc[2 * njp],     qh, kb);
                mma16816(sacc[2 * njp + 1], qh, kb + 2);
                mma16816(sacc[2 * njp],     ql, kb);
                mma16816(sacc[2 * njp + 1], ql, kb + 2);
            }
#pragma unroll
            for (int njp = 0; njp < 4; njp++) {
                uint32_t kb[4];
                ldm_x4(kb, uklo + njp * (16 * 272) + koff + kk * 32);
                mma16816(sacc[2 * njp],     qh, kb);
                mma16816(sacc[2 * njp + 1], qh, kb + 2);
            }
        }

        const bool diag = (kt == qt);
#pragma unroll
        for (int nj = 0; nj < 8; nj++) {
            float p0 = __expf(sacc[nj][0] * cSCALE);
            float p1 = __expf(sacc[nj][1] * cSCALE);
            float p2 = __expf(sacc[nj][2] * cSCALE);
            float p3 = __expf(sacc[nj][3] * cSCALE);
            if (diag) {
                const int col0 = nj * 8 + t;
                const int col1 = col0 + 4;
                const int rlo = wr + g, rhi = wr + 8 + g;
                if (col0 > rlo) p0 = 0.f;
                if (col1 > rlo) p1 = 0.f;
                if (col0 > rhi) p2 = 0.f;
                if (col1 > rhi) p3 = 0.f;
            }
            l0 += p0 + p1;
            l1 += p2 + p3;
        }
        __syncthreads();
    }

    l0 += __shfl_xor_sync(0xffffffffu, l0, 1);
    l0 += __shfl_xor_sync(0xffffffffu, l0, 2);
    l1 += __shfl_xor_sync(0xffffffffu, l1, 1);
    l1 += __shfl_xor_sync(0xffffffffu, l1, 2);
    const float inv0 = 1.f / l0;
    const float inv1 = 1.f / l1;

    // =================== PASS 2: weights (normalized) + PV =================
    float oacc[16][4];
#pragma unroll
    for (int i = 0; i < 16; i++)
#pragma unroll
        for (int r = 0; r < 4; r++) oacc[i][r] = 0.f;

    LOAD_K_STAGE(0, 0);
    LOAD_V_STAGE(0, 0);
    CP_COMMIT();

    for (int kt = 0; kt <= qt; kt++) {
        if (kt < qt) {
            LOAD_K_STAGE(kt + 1, (kt + 1) & 1);
            LOAD_V_STAGE(kt + 1, (kt + 1) & 1);
            CP_COMMIT();
            CP_WAIT(1);
        } else {
            CP_WAIT(0);
        }
        __syncthreads();

        const uint32_t ust  = uKV + (kt & 1) * KVSTAGE;
        const uint32_t ukhi = ust;
        const uint32_t uklo = ust + KTB;
        const uint32_t uvt  = ust + 2 * KTB;

        float sacc[8][4];
#pragma unroll
        for (int i = 0; i < 8; i++)
#pragma unroll
            for (int r = 0; r < 4; r++) sacc[i][r] = 0.f;

#pragma unroll
        for (int kk = 0; kk < 8; kk++) {
            uint32_t qh[4], ql[4];
            ldm_x4(qh, uQh + qoff + kk * 32);
            ldm_x4(ql, uQl + qoff + kk * 32);
#pragma unroll
            for (int njp = 0; njp < 4; njp++) {
                uint32_t kb[4];
                ldm_x4(kb, ukhi + njp * (16 * 272) + koff + kk * 32);
                mma16816(sacc[2 * njp],     qh, kb);
                mma16816(sacc[2 * njp + 1], qh, kb + 2);
                mma16816(sacc[2 * njp],     ql, kb);
                mma16816(sacc[2 * njp + 1], ql, kb + 2);
            }
#pragma unroll
            for (int njp = 0; njp < 4; njp++) {
                uint32_t kb[4];
                ldm_x4(kb, uklo + njp * (16 * 272) + koff + kk * 32);
                mma16816(sacc[2 * njp],     qh, kb);
                mma16816(sacc[2 * njp + 1], qh, kb + 2);
            }
        }

        const bool diag = (kt == qt);
        uint32_t pt[8][4];
#pragma unroll
        for (int nj = 0; nj < 8; nj++) {
            float p0 = __expf(sacc[nj][0] * cSCALE);   // (r0, cb+t)
            float p1 = __expf(sacc[nj][1] * cSCALE);   // (r0, cb+t+4)
            float p2 = __expf(sacc[nj][2] * cSCALE);   // (r1, cb+t)
            float p3 = __expf(sacc[nj][3] * cSCALE);   // (r1, cb+t+4)
            if (diag) {
                const int col0 = nj * 8 + t;
                const int col1 = col0 + 4;
                const int rlo = wr + g, rhi = wr + 8 + g;
                if (col0 > rlo) p0 = 0.f;
                if (col1 > rlo) p1 = 0.f;
                if (col0 > rhi) p2 = 0.f;
                if (col1 > rhi) p3 = 0.f;
            }
            if (write_w) {
                float* w0 = wout + ((size_t)(b * cNH + h) * cS + q0 + wr + g) * cS
                            + kt * 64 + nj * 8 + t;
                w0[0] = p0 * inv0;
                w0[4] = p1 * inv0;
                float* w1 = w0 + 8 * (size_t)cS;
                w1[0] = p2 * inv1;
                w1[4] = p3 * inv1;
            }
            // tf32 A-fragment from RAW p (output scaled by inv at the end)
            pt[nj][0] = tf32b(p0);
            pt[nj][1] = tf32b(p2);
            pt[nj][2] = tf32b(p1);
            pt[nj][3] = tf32b(p3);
        }

        // ---------- PV: tf32, V^T [d][s] fp32 ----------
#pragma unroll
        for (int nj = 0; nj < 8; nj++) {
#pragma unroll
            for (int nd2 = 0; nd2 < 8; nd2++) {
                uint32_t vb[4];
                ldm_x4(vb, uvt + nd2 * (16 * 272) + nj * 32 + voff);
                mma1688_tf32(oacc[2 * nd2],     pt[nj], vb);
                mma1688_tf32(oacc[2 * nd2 + 1], pt[nj], vb + 2);
            }
        }
        __syncthreads();
    }

    // ---- PV output (normalized, tf32-rounded for the Wo GEMM) ----
#pragma unroll
    for (int nd = 0; nd < 16; nd++) {
        const int col = nd * 8 + 2 * t;
        float* o0 = outp + ((size_t)(b * cS + q0 + wr + g) * cNH + h) * cHD + col;
        float* o1 = outp + ((size_t)(b * cS + q0 + wr + 8 + g) * cNH + h) * cHD + col;
        *(float2*)o0 = make_float2(tf32r(oacc[nd][0] * inv0),
                                   tf32r(oacc[nd][1] * inv0));
        *(float2*)o1 = make_float2(tf32r(oacc[nd][2] * inv1),
                                   tf32r(oacc[nd][3] * inv1));
    }

    // ---- zero the upper-triangle tail of this CTA's 128 rows ----
    if (write_w) {
        const int zc = cS - (q0 + 64);
        if (zc > 0) {
            const int z4 = zc >> 2;
            const int tot = 128 * z4;
            const float4 z = make_float4(0.f, 0.f, 0.f, 0.f);
            for (int i = tid; i < tot; i += 256) {
                const int r  = i / z4;
                const int c4 = i - r * z4;
                const int head = r >> 6;
                const int row  = r & 63;
                float* p = wout +
                    ((size_t)(b * cNH + kvh * 2 + head) * cS + q0 + row) * cS +
                    q0 + 64 + c4 * 4;
                *(float4*)p = z;
            }
        }
    }
}

// ---------------------------------------------------------------------------
// Launch (single stream)
// ---------------------------------------------------------------------------
extern "C" void kernel_launch(void* const* d_in, const int* in_sizes, int n_in,
                              void* d_out, int out_size)
{
    const float* hidden = (const float*)d_in[0];
    const float* cosp   = (const float*)d_in[1];
    const float* sinp   = (const float*)d_in[2];
    const float* wq  = (const float*)d_in[4];
    const float* wk  = (const float*)d_in[5];
    const float* wv  = (const float*)d_in[6];
    const float* wo  = (const float*)d_in[7];
    const float* qnw = (const float*)d_in[8];
    const float* knw = (const float*)d_in[9];

    float* out = (float*)d_out;
    const size_t n_attn = (size_t)cM * cHID;
    const size_t n_w    = (size_t)cB * cNH * cS * cS;
    const int write_w   = ((size_t)out_size >= n_attn + n_w) ? 1 : 0;
    float* weights = out + n_attn;

    float *pahf, *pqkv, *pa, *pwt, *pwot, *pvt;
    cudaGetSymbolAddress((void**)&pahf, g_ahf);
    cudaGetSymbolAddress((void**)&pqkv, g_qkv);
    cudaGetSymbolAddress((void**)&pa,   g_att);
    cudaGetSymbolAddress((void**)&pwt,  g_wt);
    cudaGetSymbolAddress((void**)&pwot, g_wot);
    cudaGetSymbolAddress((void**)&pvt,  g_vt);
    __nv_bfloat16 *pqh, *pql, *pkh, *pklo;
    cudaGetSymbolAddress((void**)&pqh,  g_q2hi);
    cudaGetSymbolAddress((void**)&pql,  g_q2lo);
    cudaGetSymbolAddress((void**)&pkh,  g_k2hi);
    cudaGetSymbolAddress((void**)&pklo, g_k2lo);

    static bool attr_done = false;
    if (!attr_done) {
        cudaFuncSetAttribute(gemm_tf32_kernel,
                             cudaFuncAttributeMaxDynamicSharedMemorySize, GEMM_SMEM);
        cudaFuncSetAttribute(attn_mma_kernel,
                             cudaFuncAttributeMaxDynamicSharedMemorySize, ATTN_SMEM);
        attr_done = true;
    }

    // --- prep: tf32-rounded A, transposed+rounded weights ---
    round_tf32_kernel<<<(cM * cHID / 4) / 256, 256>>>(hidden, pahf);
    cvt_wT_kernel<<<dim3(2048 / 32, 2048 / 32), dim3(32, 8)>>>(
        wq, pwt, cHID, 2048);
    cvt_wT_kernel<<<dim3(1024 / 32, 2048 / 32), dim3(32, 8)>>>(
        wk, pwt + (size_t)2048 * cHID, cHID, 1024);
    cvt_wT_kernel<<<dim3(1024 / 32, 2048 / 32), dim3(32, 8)>>>(
        wv, pwt + (size_t)3072 * cHID, cHID, 1024);
    cvt_wT_kernel<<<dim3(2048 / 32, 2048 / 32), dim3(32, 8)>>>(
        wo, pwot, cHID, 2048);

    // --- fused QKV projection (tf32) ---
    gemm_tf32_kernel<<<dim3(cNQKV / GBN, cM / GBM), 256, GEMM_SMEM>>>(
        pahf, pwt, pqkv, cM, cNQKV, cHID);

    // --- RMSNorm + RoPE + bf16 hi/lo split (Q,K); V^T transpose (tf32) ---
    norm_rope_split_kernel<<<dim3(24, cM), 128>>>(cosp, sinp, qnw, knw);
    vT_kernel<<<dim3(cS / 32, cHD / 32, cB * cNKV), dim3(32, 8)>>>(pqkv, pvt);

    // --- two-pass single-kernel MMA attention (weights written once) ---
    attn_mma_kernel<<<dim3(cB * cNKV, cS / 64), 256, ATTN_SMEM>>>(
        pqh, pql, pkh, pklo, pvt, weights, pa, write_w);

    // --- output projection (tf32) ---
    gemm_tf32_kernel<<<dim3(cHID / GBN, cM / GBM), 256, GEMM_SMEM>>>(
        pa, pwot, out, cM, cHID, cHID);
}

// round 14
// speedup vs baseline: 1.2424x; 1.0327x over previous
#include <cuda_runtime.h>
#include <cuda_bf16.h>
#include <math.h>
#include <stdint.h>

// ---------------------------------------------------------------------------
// Problem constants
// ---------------------------------------------------------------------------
namespace {
constexpr int cB   = 2;
constexpr int cS   = 2048;
constexpr int cHID = 2048;
constexpr int cNH  = 16;
constexpr int cNKV = 8;
constexpr int cHD  = 128;
constexpr float cEPS   = 1e-6f;
constexpr float cSCALE = 0.08838834764831845f;  // 128^-0.5
constexpr int cM   = cB * cS;        // 4096
constexpr int cNQKV = 4096;          // fused QKV output width
}

// ---------------------------------------------------------------------------
// Scratch (device globals -- no runtime allocation allowed)
// ---------------------------------------------------------------------------
__device__ float g_ahf [(size_t)cM * cHID];        // tf32-rounded hidden
__device__ float g_qkv [(size_t)cM * cNQKV];       // fused QKV projection out
__device__ float g_att [(size_t)cM * cNH * cHD];   // attn out pre-Wo (tf32-rounded)
__device__ float g_wt  [(size_t)cNQKV * cHID];     // [wq|wk|wv]^T tf32-rounded
__device__ float g_wot [(size_t)cHID * cHID];      // wo^T tf32-rounded
__device__ float g_vt  [(size_t)cB * cNKV * cHD * cS]; // V^T fp32 [b][kvh][d][s]

// bf16 hi/lo planes for attention QK, head-major layout [b][h][s][d]
__device__ __nv_bfloat16 g_q2hi[(size_t)cB * cNH  * cS * cHD];
__device__ __nv_bfloat16 g_q2lo[(size_t)cB * cNH  * cS * cHD];
__device__ __nv_bfloat16 g_k2hi[(size_t)cB * cNKV * cS * cHD];
__device__ __nv_bfloat16 g_k2lo[(size_t)cB * cNKV * cS * cHD];

// ---------------------------------------------------------------------------
// PTX helpers (portable: sm_80+)
// ---------------------------------------------------------------------------
__device__ __forceinline__ uint32_t smem_u32(const void* p) {
    uint32_t a;
    asm("{ .reg .u64 t; cvta.to.shared.u64 t, %1; cvt.u32.u64 %0, t; }"
        : "=r"(a) : "l"(p));
    return a;
}
__device__ __forceinline__ void cp_async16(uint32_t saddr, const void* gaddr) {
    asm volatile("cp.async.cg.shared.global [%0], [%1], 16;"
                 :: "r"(saddr), "l"(gaddr) : "memory");
}
#define CP_COMMIT()  asm volatile("cp.async.commit_group;" ::: "memory")
#define CP_WAIT(N)   asm volatile("cp.async.wait_group %0;" :: "n"(N) : "memory")

__device__ __forceinline__ void ldm_x4(uint32_t* r, uint32_t addr) {
    asm volatile("ldmatrix.sync.aligned.m8n8.x4.shared.b16 {%0,%1,%2,%3}, [%4];"
                 : "=r"(r[0]), "=r"(r[1]), "=r"(r[2]), "=r"(r[3]) : "r"(addr));
}
__device__ __forceinline__ void mma16816(float* d, const uint32_t* a,
                                         const uint32_t* b) {
    asm volatile(
        "mma.sync.aligned.m16n8k16.row.col.f32.bf16.bf16.f32 "
        "{%0,%1,%2,%3}, {%4,%5,%6,%7}, {%8,%9}, {%0,%1,%2,%3};"
        : "+f"(d[0]), "+f"(d[1]), "+f"(d[2]), "+f"(d[3])
        : "r"(a[0]), "r"(a[1]), "r"(a[2]), "r"(a[3]), "r"(b[0]), "r"(b[1]));
}
__device__ __forceinline__ void mma1688_tf32(float* d, const uint32_t* a,
                                             const uint32_t* b) {
    asm volatile(
        "mma.sync.aligned.m16n8k8.row.col.f32.tf32.tf32.f32 "
        "{%0,%1,%2,%3}, {%4,%5,%6,%7}, {%8,%9}, {%0,%1,%2,%3};"
        : "+f"(d[0]), "+f"(d[1]), "+f"(d[2]), "+f"(d[3])
        : "r"(a[0]), "r"(a[1]), "r"(a[2]), "r"(a[3]), "r"(b[0]), "r"(b[1]));
}
__device__ __forceinline__ uint32_t sw128(uint32_t off) {
    return off ^ ((off >> 3) & 0x70);
}
__device__ __forceinline__ float tf32r(float x) {
    uint32_t u;
    asm("cvt.rna.tf32.f32 %0, %1;" : "=r"(u) : "f"(x));
    return __uint_as_float(u);
}
__device__ __forceinline__ uint32_t tf32b(float x) {
    uint32_t u;
    asm("cvt.rna.tf32.f32 %0, %1;" : "=r"(u) : "f"(x));
    return u;
}

// ---------------------------------------------------------------------------
// Prep kernels
// ---------------------------------------------------------------------------
__global__ __launch_bounds__(256) void round_tf32_kernel(
    const float* __restrict__ X, float* __restrict__ Y)
{
    size_t e = ((size_t)blockIdx.x * 256 + threadIdx.x) * 4;
    float4 x = *(const float4*)(X + e);
    x.x = tf32r(x.x); x.y = tf32r(x.y); x.z = tf32r(x.z); x.w = tf32r(x.w);
    *(float4*)(Y + e) = x;
}

// All four weight transposes in one launch (blockIdx.z selects matrix).
struct WTJob { const float* W; float* Y; int N; };

__global__ __launch_bounds__(256) void cvt_wT4_kernel(
    WTJob j0, WTJob j1, WTJob j2, WTJob j3, int K)
{
    const WTJob j = (blockIdx.z == 0) ? j0 : (blockIdx.z == 1) ? j1 :
                    (blockIdx.z == 2) ? j2 : j3;
    const int n0 = blockIdx.x * 32;
    if (n0 >= j.N) return;
    const int k0 = blockIdx.y * 32;
    const int tx = threadIdx.x;
    const int ty = threadIdx.y;
    __shared__ float t[32][33];
#pragma unroll
    for (int i = 0; i < 32; i += 8)
        t[ty + i][tx] = j.W[(size_t)(k0 + ty + i) * j.N + n0 + tx];
    __syncthreads();
#pragma unroll
    for (int i = 0; i < 32; i += 8) {
        int n = n0 + ty + i;
        int k = k0 + tx;
        j.Y[(size_t)n * K + k] = tf32r(t[tx][ty + i]);
    }
}

// V^T: g_qkv v-section [b][s][kvh*128+d] -> g_vt [b][kvh][d][s], tf32-rounded
__global__ __launch_bounds__(256) void vT_kernel(
    const float* __restrict__ qkv, float* __restrict__ vt)
{
    __shared__ float t[32][33];
    const int s0 = blockIdx.x * 32;
    const int d0 = blockIdx.y * 32;
    const int bk = blockIdx.z;           // b*8 + kvh
    const int b  = bk >> 3;
    const int kvh = bk & 7;
    const int tx = threadIdx.x;
    const int ty = threadIdx.y;
#pragma unroll
    for (int i = 0; i < 32; i += 8)
        t[ty + i][tx] = qkv[(size_t)(b * cS + s0 + ty + i) * cNQKV +
                            3072 + kvh * cHD + d0 + tx];
    __syncthreads();
#pragma unroll
    for (int i = 0; i < 32; i += 8)
        vt[((size_t)bk * cHD + d0 + ty + i) * cS + s0 + tx] =
            tf32r(t[tx][ty + i]);
}

// ---------------------------------------------------------------------------
// TF32 HMMA GEMM: C[M,N] = A[M,K] @ B[N,K]^T (row-major fp32, tf32-prerounded)
// CTA tile 128x256, BK=32, 4-stage cp.async, SW128, warp tile 64x64.
// ---------------------------------------------------------------------------
namespace {
constexpr int GBM = 128, GBN = 256, GBK = 32;
constexpr int NSTAGE = 4;
constexpr int A_BYTES = GBM * GBK * 4;              // 16KB
constexpr int B_BYTES = GBN * GBK * 4;              // 32KB
constexpr int STAGE_BYTES = A_BYTES + B_BYTES;      // 48KB
constexpr int GEMM_SMEM   = NSTAGE * STAGE_BYTES;   // 192KB
}

__device__ __forceinline__ void gemm_load_stage(
    const float* __restrict__ Ag, const float* __restrict__ Bg,
    int K, int it, uint32_t stage_base, int tid)
{
#pragma unroll
    for (int i = 0; i < 4; i++) {
        int idx = tid + (i << 8);
        int row = idx >> 3;
        int c4  = idx & 7;
        uint32_t sw = sw128((uint32_t)(row * 128 + c4 * 16));
        cp_async16(stage_base + sw,
                   Ag + (size_t)row * K + (size_t)it * GBK + c4 * 4);
    }
#pragma unroll
    for (int i = 0; i < 8; i++) {
        int idx = tid + (i << 8);
        int row = idx >> 3;
        int c4  = idx & 7;
        uint32_t sw = sw128((uint32_t)(row * 128 + c4 * 16));
        cp_async16(stage_base + A_BYTES + sw,
                   Bg + (size_t)row * K + (size_t)it * GBK + c4 * 4);
    }
}

__global__ __launch_bounds__(256, 1)
void gemm_tf32_kernel(const float* __restrict__ A,
                      const float* __restrict__ B,
                      float* __restrict__ C, int M, int N, int K)
{
    extern __shared__ char smraw[];
    const uint32_t sbase = smem_u32(smraw);

    const int tid  = threadIdx.x;
    const int wid  = tid >> 5;
    const int lane = tid & 31;
    const int m0 = blockIdx.y * GBM;
    const int n0 = blockIdx.x * GBN;
    const int mw = (wid >> 2) * 64;
    const int nw = (wid & 3) * 64;

    const float* Ag = A + (size_t)m0 * K;
    const float* Bg = B + (size_t)n0 * K;
    const int KITERS = K / GBK;

    float acc[4][8][4];
#pragma unroll
    for (int i = 0; i < 4; i++)
#pragma unroll
        for (int j = 0; j < 8; j++)
#pragma unroll
            for (int r = 0; r < 4; r++) acc[i][j][r] = 0.f;

    const int a_row = lane & 15;
    const int a_cb  = (lane >> 4) * 16;
    const int b_row = (lane & 7) + ((lane >> 4) & 1) * 8;
    const int b_cb  = ((lane >> 3) & 1) * 16;

#pragma unroll
    for (int s = 0; s < NSTAGE - 1; s++) {
        gemm_load_stage(Ag, Bg, K, s, sbase + s * STAGE_BYTES, tid);
        CP_COMMIT();
    }

    for (int it = 0; it < KITERS; ++it) {
        CP_WAIT(NSTAGE - 2);
        __syncthreads();

        int nx = it + NSTAGE - 1;
        if (nx < KITERS)
            gemm_load_stage(Ag, Bg, K, nx,
                            sbase + (nx % NSTAGE) * STAGE_BYTES, tid);
        CP_COMMIT();

        const uint32_t sa = sbase + (it % NSTAGE) * STAGE_BYTES;
        const uint32_t sb = sa + A_BYTES;

#pragma unroll
        for (int ks = 0; ks < 4; ks++) {
            uint32_t af[4][4], bf[4][4];
#pragma unroll
            for (int mi = 0; mi < 4; mi++) {
                uint32_t off = (uint32_t)((mw + 16 * mi + a_row) * 128 +
                                          ks * 32 + a_cb);
                ldm_x4(af[mi], sa + sw128(off));
            }
#pragma unroll
            for (int njp = 0; njp < 4; njp++) {
                uint32_t off = (uint32_t)((nw + 16 * njp + b_row) * 128 +
                                          ks * 32 + b_cb);
                ldm_x4(bf[njp], sb + sw128(off));
            }
#pragma unroll
            for (int mi = 0; mi < 4; mi++)
#pragma unroll
                for (int njp = 0; njp < 4; njp++) {
                    mma1688_tf32(acc[mi][2 * njp],     af[mi], bf[njp]);
                    mma1688_tf32(acc[mi][2 * njp + 1], af[mi], bf[njp] + 2);
                }
        }
    }

    const int g = lane >> 2;
    const int t = lane & 3;
#pragma unroll
    for (int mi = 0; mi < 4; mi++) {
#pragma unroll
        for (int nj = 0; nj < 8; nj++) {
            int r0 = m0 + mw + 16 * mi + g;
            int cc = n0 + nw + 8 * nj + t * 2;
            *(float2*)(C + (size_t)r0 * N + cc) =
                make_float2(acc[mi][nj][0], acc[mi][nj][1]);
            *(float2*)(C + (size_t)(r0 + 8) * N + cc) =
                make_float2(acc[mi][nj][2], acc[mi][nj][3]);
        }
    }
}

// ---------------------------------------------------------------------------
// RMSNorm + RoPE + hi/lo bf16 split, ONE WARP PER HEAD VECTOR.
// Lane holds 4 elements at stride 32 (d = lane + 32*i) so rotate_half pairs
// (d, d+64) are register-local (i <-> i+2). No barriers, no smem.
// slot 0-15: q heads, 16-23: k heads. 8 warps per 256-thread block.
// ---------------------------------------------------------------------------
__global__ __launch_bounds__(256) void norm_rope_warp_kernel(
    const float* __restrict__ cosp, const float* __restrict__ sinp,
    const float* __restrict__ qw,   const float* __restrict__ kw)
{
    const int wid  = threadIdx.x >> 5;
    const int lane = threadIdx.x & 31;
    const int gslot = blockIdx.x * 8 + wid;     // 0 .. cM*24-1
    const int bs   = gslot / 24;
    const int slot = gslot - bs * 24;
    const int b    = bs >> 11;
    const int s    = bs & 2047;

    const float* src;
    const float* w;
    __nv_bfloat16 *dhi, *dlo;
    if (slot < 16) {
        src = g_qkv + (size_t)bs * cNQKV + slot * cHD;
        w = qw;
        size_t dst = ((size_t)(b * cNH + slot) * cS + s) * cHD;
        dhi = g_q2hi + dst; dlo = g_q2lo + dst;
    } else {
        src = g_qkv + (size_t)bs * cNQKV + 2048 + (slot - 16) * cHD;
        w = kw;
        size_t dst = ((size_t)(b * cNKV + (slot - 16)) * cS + s) * cHD;
        dhi = g_k2hi + dst; dlo = g_k2lo + dst;
    }

    float x[4];
#pragma unroll
    for (int i = 0; i < 4; i++) x[i] = src[lane + 32 * i];

    float v = x[0] * x[0] + x[1] * x[1] + x[2] * x[2] + x[3] * x[3];
#pragma unroll
    for (int o = 16; o; o >>= 1) v += __shfl_xor_sync(0xffffffffu, v, o);
    const float rs = rsqrtf(v * (1.f / cHD) + cEPS);

    float xn[4];
#pragma unroll
    for (int i = 0; i < 4; i++) xn[i] = x[i] * rs * w[lane + 32 * i];

#pragma unroll
    for (int i = 0; i < 4; i++) {
        const int d = lane + 32 * i;
        const float other = (i < 2) ? -xn[i + 2] : xn[i - 2];
        const float cv = cosp[(size_t)bs * cHD + d];
        const float sv = sinp[(size_t)bs * cHD + d];
        const float val = xn[i] * cv + other * sv;
        const __nv_bfloat16 hi = __float2bfloat16(val);
        dhi[d] = hi;
        dlo[d] = __float2bfloat16(val - __bfloat162float(hi));
    }
}

// ---------------------------------------------------------------------------
// TWO-PASS single-kernel MMA attention (unchanged from R13 best).
// ---------------------------------------------------------------------------
namespace {
constexpr int KTB = 64 * 272;
constexpr int VTB = 128 * 272;
constexpr int KVSTAGE = 2 * KTB + VTB;
constexpr int ATTN_SMEM = 4 * KTB + 2 * KVSTAGE;   // 208896
__device__ __constant__ int c_kperm[8] = {0, 2, 4, 6, 1, 3, 5, 7};
}

__global__ __launch_bounds__(256, 1)
void attn_mma_kernel(const __nv_bfloat16* __restrict__ qhi_g,
                     const __nv_bfloat16* __restrict__ qlo_g,
                     const __nv_bfloat16* __restrict__ khi_g,
                     const __nv_bfloat16* __restrict__ klo_g,
                     const float* __restrict__ vt_g,
                     float* __restrict__ wout,
                     float* __restrict__ outp,
                     int write_w)
{
    extern __shared__ char smraw[];
    const uint32_t uQ  = smem_u32(smraw);
    const uint32_t uKV = uQ + 4 * KTB;

    const int tid  = threadIdx.x;
    const int wid  = tid >> 5;
    const int lane = tid & 31;
    const int qt  = gridDim.y - 1 - blockIdx.y;    // heavy-first
    const int bkv = blockIdx.x;
    const int b   = bkv >> 3;
    const int kvh = bkv & 7;
    const int hs  = wid >> 2;
    const int h   = kvh * 2 + hs;
    const int wr  = (wid & 3) * 16;
    const int q0  = qt * 64;
    const int g   = lane >> 2;
    const int t   = lane & 3;

    // ---- Q tiles (4: h0hi, h0lo, h1hi, h1lo)
    {
        const size_t qrow = ((size_t)(b * cNH + kvh * 2) * cS + q0) * cHD;
        const int row = (tid >> 4);
        const int c   = tid & 15;
#pragma unroll
        for (int i = 0; i < 16; i++) {
            const int tile = i >> 2;
            const int rr = (i & 3) * 16 + row;
            const __nv_bfloat16* base = (tile & 1) ? qlo_g : qhi_g;
            const __nv_bfloat16* src = base + qrow +
                (size_t)(tile >> 1) * cS * cHD + (size_t)rr * cHD + c * 8;
            cp_async16(uQ + tile * KTB + rr * 272 + c * 16, src);
        }
    }
    CP_COMMIT();

    const size_t krow0 = ((size_t)(b * cNKV + kvh) * cS) * cHD;
    const size_t vbase = ((size_t)(b * cNKV + kvh) * cHD) * cS;
    const int lrow = (tid >> 4);
    const int lc   = tid & 15;

#define LOAD_K_STAGE(kt_, st_)                                                \
    do {                                                                      \
        const uint32_t ust = uKV + (st_) * KVSTAGE;                           \
        const size_t krow = krow0 + (size_t)((kt_) * 64) * cHD;               \
        _Pragma("unroll")                                                     \
        for (int i = 0; i < 8; i++) {                                         \
            const int tile = i >> 2;                                          \
            const int rr = (i & 3) * 16 + lrow;                               \
            const int srr = (rr & 0x38) | c_kperm[rr & 7];                    \
            const __nv_bfloat16* base = tile ? klo_g : khi_g;                 \
            cp_async16(ust + tile * KTB + srr * 272 + lc * 16,                \
                       base + krow + (size_t)rr * cHD + lc * 8);              \
        }                                                                     \
    } while (0)

#define LOAD_V_STAGE(kt_, st_)                                                \
    do {                                                                      \
        const uint32_t ust = uKV + (st_) * KVSTAGE;                           \
        _Pragma("unroll")                                                     \
        for (int i = 0; i < 8; i++) {                                         \
            const int dd = i * 16 + lrow;                                     \
            cp_async16(ust + 2 * KTB + dd * 272 + lc * 16,                    \
                       vt_g + vbase + (size_t)dd * cS + (kt_) * 64 + lc * 4); \
        }                                                                     \
    } while (0)

    const uint32_t qoff = (uint32_t)((wr + (lane & 15)) * 272 + (lane >> 4) * 16);
    const uint32_t koff = (uint32_t)(((lane & 7) + ((lane >> 4) & 1) * 8) * 272 +
                                     ((lane >> 3) & 1) * 16);
    const uint32_t voff = (uint32_t)(((lane & 7) + ((lane >> 4) & 1) * 8) * 272 +
                                     ((lane >> 3) & 1) * 16);
    const uint32_t uQh = uQ + hs * 2 * KTB;
    const uint32_t uQl = uQh + KTB;

    float l0 = 0.f, l1 = 0.f;

    // =================== PASS 1: l accumulation (K only) ===================
    LOAD_K_STAGE(0, 0);
    CP_COMMIT();

    for (int kt = 0; kt <= qt; kt++) {
        if (kt < qt) {
            LOAD_K_STAGE(kt + 1, (kt + 1) & 1);
            CP_COMMIT();
            CP_WAIT(1);
        } else {
            CP_WAIT(0);
        }
        __syncthreads();

        const uint32_t ust  = uKV + (kt & 1) * KVSTAGE;
        const uint32_t ukhi = ust;
        const uint32_t uklo = ust + KTB;

        float sacc[8][4];
#pragma unroll
        for (int i = 0; i < 8; i++)
#pragma unroll
            for (int r = 0; r < 4; r++) sacc[i][r] = 0.f;

#pragma unroll
        for (int kk = 0; kk < 8; kk++) {
            uint32_t qh[4], ql[4];
            ldm_x4(qh, uQh + qoff + kk * 32);
            ldm_x4(ql, uQl + qoff + kk * 32);
#pragma unroll
            for (int njp = 0; njp < 4; njp++) {
                uint32_t kb[4];
                ldm_x4(kb, ukhi + njp * (16 * 272) + koff + kk * 32);
                mma16816(sacc[2 * njp],     qh, kb);
                mma16816(sacc[2 * njp + 1], qh, kb + 2);
                mma16816(sacc[2 * njp],     ql, kb);
                mma16816(sacc[2 * njp + 1], ql, kb + 2);
            }
#pragma unroll
            for (int njp = 0; njp < 4; njp++) {
                uint32_t kb[4];
                ldm_x4(kb, uklo + njp * (16 * 272) + koff + kk * 32);
                mma16816(sacc[2 * njp],     qh, kb);
                mma16816(sacc[2 * njp + 1], qh, kb + 2);
            }
        }

        const bool diag = (kt == qt);
#pragma unroll
        for (int nj = 0; nj < 8; nj++) {
            float p0 = __expf(sacc[nj][0] * cSCALE);
            float p1 = __expf(sacc[nj][1] * cSCALE);
            float p2 = __expf(sacc[nj][2] * cSCALE);
            float p3 = __expf(sacc[nj][3] * cSCALE);
            if (diag) {
                const int col0 = nj * 8 + t;
                const int col1 = col0 + 4;
                const int rlo = wr + g, rhi = wr + 8 + g;
                if (col0 > rlo) p0 = 0.f;
                if (col1 > rlo) p1 = 0.f;
                if (col0 > rhi) p2 = 0.f;
                if (col1 > rhi) p3 = 0.f;
            }
            l0 += p0 + p1;
            l1 += p2 + p3;
        }
        __syncthreads();
    }

    l0 += __shfl_xor_sync(0xffffffffu, l0, 1);
    l0 += __shfl_xor_sync(0xffffffffu, l0, 2);
    l1 += __shfl_xor_sync(0xffffffffu, l1, 1);
    l1 += __shfl_xor_sync(0xffffffffu, l1, 2);
    const float inv0 = 1.f / l0;
    const float inv1 = 1.f / l1;

    // =================== PASS 2: weights (normalized) + PV =================
    float oacc[16][4];
#pragma unroll
    for (int i = 0; i < 16; i++)
#pragma unroll
        for (int r = 0; r < 4; r++) oacc[i][r] = 0.f;

    LOAD_K_STAGE(0, 0);
    LOAD_V_STAGE(0, 0);
    CP_COMMIT();

    for (int kt = 0; kt <= qt; kt++) {
        if (kt < qt) {
            LOAD_K_STAGE(kt + 1, (kt + 1) & 1);
            LOAD_V_STAGE(kt + 1, (kt + 1) & 1);
            CP_COMMIT();
            CP_WAIT(1);
        } else {
            CP_WAIT(0);
        }
        __syncthreads();

        const uint32_t ust  = uKV + (kt & 1) * KVSTAGE;
        const uint32_t ukhi = ust;
        const uint32_t uklo = ust + KTB;
        const uint32_t uvt  = ust + 2 * KTB;

        float sacc[8][4];
#pragma unroll
        for (int i = 0; i < 8; i++)
#pragma unroll
            for (int r = 0; r < 4; r++) sacc[i][r] = 0.f;

#pragma unroll
        for (int kk = 0; kk < 8; kk++) {
            uint32_t qh[4], ql[4];
            ldm_x4(qh, uQh + qoff + kk * 32);
            ldm_x4(ql, uQl + qoff + kk * 32);
#pragma unroll
            for (int njp = 0; njp < 4; njp++) {
                uint32_t kb[4];
                ldm_x4(kb, ukhi + njp * (16 * 272) + koff + kk * 32);
                mma16816(sacc[2 * njp],     qh, kb);
                mma16816(sacc[2 * njp + 1], qh, kb + 2);
                mma16816(sacc[2 * njp],     ql, kb);
                mma16816(sacc[2 * njp + 1], ql, kb + 2);
            }
#pragma unroll
            for (int njp = 0; njp < 4; njp++) {
                uint32_t kb[4];
                ldm_x4(kb, uklo + njp * (16 * 272) + koff + kk * 32);
                mma16816(sacc[2 * njp],     qh, kb);
                mma16816(sacc[2 * njp + 1], qh, kb + 2);
            }
        }

        const bool diag = (kt == qt);
        uint32_t pt[8][4];
#pragma unroll
        for (int nj = 0; nj < 8; nj++) {
            float p0 = __expf(sacc[nj][0] * cSCALE);
            float p1 = __expf(sacc[nj][1] * cSCALE);
            float p2 = __expf(sacc[nj][2] * cSCALE);
            float p3 = __expf(sacc[nj][3] * cSCALE);
            if (diag) {
                const int col0 = nj * 8 + t;
                const int col1 = col0 + 4;
                const int rlo = wr + g, rhi = wr + 8 + g;
                if (col0 > rlo) p0 = 0.f;
                if (col1 > rlo) p1 = 0.f;
                if (col0 > rhi) p2 = 0.f;
                if (col1 > rhi) p3 = 0.f;
            }
            if (write_w) {
                float* w0 = wout + ((size_t)(b * cNH + h) * cS + q0 + wr + g) * cS
                            + kt * 64 + nj * 8 + t;
                w0[0] = p0 * inv0;
                w0[4] = p1 * inv0;
                float* w1 = w0 + 8 * (size_t)cS;
                w1[0] = p2 * inv1;
                w1[4] = p3 * inv1;
            }
            pt[nj][0] = tf32b(p0);
            pt[nj][1] = tf32b(p2);
            pt[nj][2] = tf32b(p1);
            pt[nj][3] = tf32b(p3);
        }

#pragma unroll
        for (int nj = 0; nj < 8; nj++) {
#pragma unroll
            for (int nd2 = 0; nd2 < 8; nd2++) {
                uint32_t vb[4];
                ldm_x4(vb, uvt + nd2 * (16 * 272) + nj * 32 + voff);
                mma1688_tf32(oacc[2 * nd2],     pt[nj], vb);
                mma1688_tf32(oacc[2 * nd2 + 1], pt[nj], vb + 2);
            }
        }
        __syncthreads();
    }

    // ---- PV output (normalized, tf32-rounded for the Wo GEMM) ----
#pragma unroll
    for (int nd = 0; nd < 16; nd++) {
        const int col = nd * 8 + 2 * t;
        float* o0 = outp + ((size_t)(b * cS + q0 + wr + g) * cNH + h) * cHD + col;
        float* o1 = outp + ((size_t)(b * cS + q0 + wr + 8 + g) * cNH + h) * cHD + col;
        *(float2*)o0 = make_float2(tf32r(oacc[nd][0] * inv0),
                                   tf32r(oacc[nd][1] * inv0));
        *(float2*)o1 = make_float2(tf32r(oacc[nd][2] * inv1),
                                   tf32r(oacc[nd][3] * inv1));
    }

    // ---- zero the upper-triangle tail of this CTA's 128 rows ----
    if (write_w) {
        const int zc = cS - (q0 + 64);
        if (zc > 0) {
            const int z4 = zc >> 2;
            const int tot = 128 * z4;
            const float4 z = make_float4(0.f, 0.f, 0.f, 0.f);
            for (int i = tid; i < tot; i += 256) {
                const int r  = i / z4;
                const int c4 = i - r * z4;
                const int head = r >> 6;
                const int row  = r & 63;
                float* p = wout +
                    ((size_t)(b * cNH + kvh * 2 + head) * cS + q0 + row) * cS +
                    q0 + 64 + c4 * 4;
                *(float4*)p = z;
            }
        }
    }
}

// ---------------------------------------------------------------------------
// Launch (single stream)
// ---------------------------------------------------------------------------
extern "C" void kernel_launch(void* const* d_in, const int* in_sizes, int n_in,
                              void* d_out, int out_size)
{
    const float* hidden = (const float*)d_in[0];
    const float* cosp   = (const float*)d_in[1];
    const float* sinp   = (const float*)d_in[2];
    const float* wq  = (const float*)d_in[4];
    const float* wk  = (const float*)d_in[5];
    const float* wv  = (const float*)d_in[6];
    const float* wo  = (const float*)d_in[7];
    const float* qnw = (const float*)d_in[8];
    const float* knw = (const float*)d_in[9];

    float* out = (float*)d_out;
    const size_t n_attn = (size_t)cM * cHID;
    const size_t n_w    = (size_t)cB * cNH * cS * cS;
    const int write_w   = ((size_t)out_size >= n_attn + n_w) ? 1 : 0;
    float* weights = out + n_attn;

    float *pahf, *pqkv, *pa, *pwt, *pwot, *pvt;
    cudaGetSymbolAddress((void**)&pahf, g_ahf);
    cudaGetSymbolAddress((void**)&pqkv, g_qkv);
    cudaGetSymbolAddress((void**)&pa,   g_att);
    cudaGetSymbolAddress((void**)&pwt,  g_wt);
    cudaGetSymbolAddress((void**)&pwot, g_wot);
    cudaGetSymbolAddress((void**)&pvt,  g_vt);
    __nv_bfloat16 *pqh, *pql, *pkh, *pklo;
    cudaGetSymbolAddress((void**)&pqh,  g_q2hi);
    cudaGetSymbolAddress((void**)&pql,  g_q2lo);
    cudaGetSymbolAddress((void**)&pkh,  g_k2hi);
    cudaGetSymbolAddress((void**)&pklo, g_k2lo);

    static bool attr_done = false;
    if (!attr_done) {
        cudaFuncSetAttribute(gemm_tf32_kernel,
                             cudaFuncAttributeMaxDynamicSharedMemorySize, GEMM_SMEM);
        cudaFuncSetAttribute(attn_mma_kernel,
                             cudaFuncAttributeMaxDynamicSharedMemorySize, ATTN_SMEM);
        attr_done = true;
    }

    // --- prep: tf32-rounded A; all 4 weight transposes in one launch ---
    round_tf32_kernel<<<(cM * cHID / 4) / 256, 256>>>(hidden, pahf);
    {
        WTJob j0 = { wq, pwt,                          2048 };
        WTJob j1 = { wk, pwt + (size_t)2048 * cHID,    1024 };
        WTJob j2 = { wv, pwt + (size_t)3072 * cHID,    1024 };
        WTJob j3 = { wo, pwot,                         2048 };
        cvt_wT4_kernel<<<dim3(64, 64, 4), dim3(32, 8)>>>(j0, j1, j2, j3, cHID);
    }

    // --- fused QKV projection (tf32) ---
    gemm_tf32_kernel<<<dim3(cNQKV / GBN, cM / GBM), 256, GEMM_SMEM>>>(
        pahf, pwt, pqkv, cM, cNQKV, cHID);

    // --- RMSNorm + RoPE + bf16 hi/lo split (warp-per-head); V^T transpose ---
    norm_rope_warp_kernel<<<cM * 24 / 8, 256>>>(cosp, sinp, qnw, knw);
    vT_kernel<<<dim3(cS / 32, cHD / 32, cB * cNKV), dim3(32, 8)>>>(pqkv, pvt);

    // --- two-pass single-kernel MMA attention (weights written once) ---
    attn_mma_kernel<<<dim3(cB * cNKV, cS / 64), 256, ATTN_SMEM>>>(
        pqh, pql, pkh, pklo, pvt, weights, pa, write_w);

    // --- output projection (tf32) ---
    gemm_tf32_kernel<<<dim3(cHID / GBN, cM / GBM), 256, GEMM_SMEM>>>(
        pa, pwot, out, cM, cHID, cHID);
}

// round 15
// speedup vs baseline: 1.2471x; 1.0038x over previous
#include <cuda_runtime.h>
#include <cuda_bf16.h>
#include <math.h>
#include <stdint.h>

// ---------------------------------------------------------------------------
// Problem constants
// ---------------------------------------------------------------------------
namespace {
constexpr int cB   = 2;
constexpr int cS   = 2048;
constexpr int cHID = 2048;
constexpr int cNH  = 16;
constexpr int cNKV = 8;
constexpr int cHD  = 128;
constexpr float cEPS   = 1e-6f;
constexpr float cSCALE = 0.08838834764831845f;  // 128^-0.5
constexpr int cM   = cB * cS;        // 4096
constexpr int cNQKV = 4096;          // fused QKV output width
}

// ---------------------------------------------------------------------------
// Scratch (device globals -- no runtime allocation allowed)
// ---------------------------------------------------------------------------
__device__ float g_ahf [(size_t)cM * cHID];        // tf32-rounded hidden
__device__ float g_qkv [(size_t)cM * cNQKV];       // fused QKV projection out
__device__ float g_att [(size_t)cM * cNH * cHD];   // attn out pre-Wo (tf32-rounded)
__device__ float g_wt  [(size_t)cNQKV * cHID];     // [wq|wk|wv]^T tf32-rounded
__device__ float g_wot [(size_t)cHID * cHID];      // wo^T tf32-rounded
__device__ float g_vt  [(size_t)cB * cNKV * cHD * cS]; // V^T fp32 [b][kvh][d][s]

// bf16 hi/lo planes for attention QK, head-major layout [b][h][s][d]
__device__ __nv_bfloat16 g_q2hi[(size_t)cB * cNH  * cS * cHD];
__device__ __nv_bfloat16 g_q2lo[(size_t)cB * cNH  * cS * cHD];
__device__ __nv_bfloat16 g_k2hi[(size_t)cB * cNKV * cS * cHD];
__device__ __nv_bfloat16 g_k2lo[(size_t)cB * cNKV * cS * cHD];

// ---------------------------------------------------------------------------
// PTX helpers (portable: sm_80+)
// ---------------------------------------------------------------------------
__device__ __forceinline__ uint32_t smem_u32(const void* p) {
    uint32_t a;
    asm("{ .reg .u64 t; cvta.to.shared.u64 t, %1; cvt.u32.u64 %0, t; }"
        : "=r"(a) : "l"(p));
    return a;
}
__device__ __forceinline__ void cp_async16(uint32_t saddr, const void* gaddr) {
    asm volatile("cp.async.cg.shared.global [%0], [%1], 16;"
                 :: "r"(saddr), "l"(gaddr) : "memory");
}
#define CP_COMMIT()  asm volatile("cp.async.commit_group;" ::: "memory")
#define CP_WAIT(N)   asm volatile("cp.async.wait_group %0;" :: "n"(N) : "memory")

__device__ __forceinline__ void ldm_x4(uint32_t* r, uint32_t addr) {
    asm volatile("ldmatrix.sync.aligned.m8n8.x4.shared.b16 {%0,%1,%2,%3}, [%4];"
                 : "=r"(r[0]), "=r"(r[1]), "=r"(r[2]), "=r"(r[3]) : "r"(addr));
}
__device__ __forceinline__ void mma16816(float* d, const uint32_t* a,
                                         const uint32_t* b) {
    asm volatile(
        "mma.sync.aligned.m16n8k16.row.col.f32.bf16.bf16.f32 "
        "{%0,%1,%2,%3}, {%4,%5,%6,%7}, {%8,%9}, {%0,%1,%2,%3};"
        : "+f"(d[0]), "+f"(d[1]), "+f"(d[2]), "+f"(d[3])
        : "r"(a[0]), "r"(a[1]), "r"(a[2]), "r"(a[3]), "r"(b[0]), "r"(b[1]));
}
__device__ __forceinline__ void mma1688_tf32(float* d, const uint32_t* a,
                                             const uint32_t* b) {
    asm volatile(
        "mma.sync.aligned.m16n8k8.row.col.f32.tf32.tf32.f32 "
        "{%0,%1,%2,%3}, {%4,%5,%6,%7}, {%8,%9}, {%0,%1,%2,%3};"
        : "+f"(d[0]), "+f"(d[1]), "+f"(d[2]), "+f"(d[3])
        : "r"(a[0]), "r"(a[1]), "r"(a[2]), "r"(a[3]), "r"(b[0]), "r"(b[1]));
}
__device__ __forceinline__ uint32_t sw128(uint32_t off) {
    return off ^ ((off >> 3) & 0x70);
}
__device__ __forceinline__ float tf32r(float x) {
    uint32_t u;
    asm("cvt.rna.tf32.f32 %0, %1;" : "=r"(u) : "f"(x));
    return __uint_as_float(u);
}
__device__ __forceinline__ uint32_t tf32b(float x) {
    uint32_t u;
    asm("cvt.rna.tf32.f32 %0, %1;" : "=r"(u) : "f"(x));
    return u;
}

// ---------------------------------------------------------------------------
// Prep kernels
// ---------------------------------------------------------------------------
__global__ __launch_bounds__(256) void round_tf32_kernel(
    const float* __restrict__ X, float* __restrict__ Y)
{
    size_t e = ((size_t)blockIdx.x * 256 + threadIdx.x) * 4;
    float4 x = *(const float4*)(X + e);
    x.x = tf32r(x.x); x.y = tf32r(x.y); x.z = tf32r(x.z); x.w = tf32r(x.w);
    *(float4*)(Y + e) = x;
}

// All four weight transposes in one launch (blockIdx.z selects matrix).
struct WTJob { const float* W; float* Y; int N; };

__global__ __launch_bounds__(256) void cvt_wT4_kernel(
    WTJob j0, WTJob j1, WTJob j2, WTJob j3, int K)
{
    const WTJob j = (blockIdx.z == 0) ? j0 : (blockIdx.z == 1) ? j1 :
                    (blockIdx.z == 2) ? j2 : j3;
    const int n0 = blockIdx.x * 32;
    if (n0 >= j.N) return;
    const int k0 = blockIdx.y * 32;
    const int tx = threadIdx.x;
    const int ty = threadIdx.y;
    __shared__ float t[32][33];
#pragma unroll
    for (int i = 0; i < 32; i += 8)
        t[ty + i][tx] = j.W[(size_t)(k0 + ty + i) * j.N + n0 + tx];
    __syncthreads();
#pragma unroll
    for (int i = 0; i < 32; i += 8) {
        int n = n0 + ty + i;
        int k = k0 + tx;
        j.Y[(size_t)n * K + k] = tf32r(t[tx][ty + i]);
    }
}

// V^T: g_qkv v-section [b][s][kvh*128+d] -> g_vt [b][kvh][d][s], tf32-rounded
__global__ __launch_bounds__(256) void vT_kernel(
    const float* __restrict__ qkv, float* __restrict__ vt)
{
    __shared__ float t[32][33];
    const int s0 = blockIdx.x * 32;
    const int d0 = blockIdx.y * 32;
    const int bk = blockIdx.z;           // b*8 + kvh
    const int b  = bk >> 3;
    const int kvh = bk & 7;
    const int tx = threadIdx.x;
    const int ty = threadIdx.y;
#pragma unroll
    for (int i = 0; i < 32; i += 8)
        t[ty + i][tx] = qkv[(size_t)(b * cS + s0 + ty + i) * cNQKV +
                            3072 + kvh * cHD + d0 + tx];
    __syncthreads();
#pragma unroll
    for (int i = 0; i < 32; i += 8)
        vt[((size_t)bk * cHD + d0 + ty + i) * cS + s0 + tx] =
            tf32r(t[tx][ty + i]);
}

// ---------------------------------------------------------------------------
// TF32 HMMA GEMM: C[M,N] = A[M,K] @ B[N,K]^T (row-major fp32, tf32-prerounded)
// CTA tile 128x256, BK=32, 4-stage cp.async, SW128, warp tile 64x64.
// ---------------------------------------------------------------------------
namespace {
constexpr int GBM = 128, GBN = 256, GBK = 32;
constexpr int NSTAGE = 4;
constexpr int A_BYTES = GBM * GBK * 4;              // 16KB
constexpr int B_BYTES = GBN * GBK * 4;              // 32KB
constexpr int STAGE_BYTES = A_BYTES + B_BYTES;      // 48KB
constexpr int GEMM_SMEM   = NSTAGE * STAGE_BYTES;   // 192KB
}

__device__ __forceinline__ void gemm_load_stage(
    const float* __restrict__ Ag, const float* __restrict__ Bg,
    int K, int it, uint32_t stage_base, int tid)
{
#pragma unroll
    for (int i = 0; i < 4; i++) {
        int idx = tid + (i << 8);
        int row = idx >> 3;
        int c4  = idx & 7;
        uint32_t sw = sw128((uint32_t)(row * 128 + c4 * 16));
        cp_async16(stage_base + sw,
                   Ag + (size_t)row * K + (size_t)it * GBK + c4 * 4);
    }
#pragma unroll
    for (int i = 0; i < 8; i++) {
        int idx = tid + (i << 8);
        int row = idx >> 3;
        int c4  = idx & 7;
        uint32_t sw = sw128((uint32_t)(row * 128 + c4 * 16));
        cp_async16(stage_base + A_BYTES + sw,
                   Bg + (size_t)row * K + (size_t)it * GBK + c4 * 4);
    }
}

__global__ __launch_bounds__(256, 1)
void gemm_tf32_kernel(const float* __restrict__ A,
                      const float* __restrict__ B,
                      float* __restrict__ C, int M, int N, int K)
{
    extern __shared__ char smraw[];
    const uint32_t sbase = smem_u32(smraw);

    const int tid  = threadIdx.x;
    const int wid  = tid >> 5;
    const int lane = tid & 31;
    const int m0 = blockIdx.y * GBM;
    const int n0 = blockIdx.x * GBN;
    const int mw = (wid >> 2) * 64;
    const int nw = (wid & 3) * 64;

    const float* Ag = A + (size_t)m0 * K;
    const float* Bg = B + (size_t)n0 * K;
    const int KITERS = K / GBK;

    float acc[4][8][4];
#pragma unroll
    for (int i = 0; i < 4; i++)
#pragma unroll
        for (int j = 0; j < 8; j++)
#pragma unroll
            for (int r = 0; r < 4; r++) acc[i][j][r] = 0.f;

    const int a_row = lane & 15;
    const int a_cb  = (lane >> 4) * 16;
    const int b_row = (lane & 7) + ((lane >> 4) & 1) * 8;
    const int b_cb  = ((lane >> 3) & 1) * 16;

#pragma unroll
    for (int s = 0; s < NSTAGE - 1; s++) {
        gemm_load_stage(Ag, Bg, K, s, sbase + s * STAGE_BYTES, tid);
        CP_COMMIT();
    }

    for (int it = 0; it < KITERS; ++it) {
        CP_WAIT(NSTAGE - 2);
        __syncthreads();

        int nx = it + NSTAGE - 1;
        if (nx < KITERS)
            gemm_load_stage(Ag, Bg, K, nx,
                            sbase + (nx % NSTAGE) * STAGE_BYTES, tid);
        CP_COMMIT();

        const uint32_t sa = sbase + (it % NSTAGE) * STAGE_BYTES;
        const uint32_t sb = sa + A_BYTES;

#pragma unroll
        for (int ks = 0; ks < 4; ks++) {
            uint32_t af[4][4], bf[4][4];
#pragma unroll
            for (int mi = 0; mi < 4; mi++) {
                uint32_t off = (uint32_t)((mw + 16 * mi + a_row) * 128 +
                                          ks * 32 + a_cb);
                ldm_x4(af[mi], sa + sw128(off));
            }
#pragma unroll
            for (int njp = 0; njp < 4; njp++) {
                uint32_t off = (uint32_t)((nw + 16 * njp + b_row) * 128 +
                                          ks * 32 + b_cb);
                ldm_x4(bf[njp], sb + sw128(off));
            }
#pragma unroll
            for (int mi = 0; mi < 4; mi++)
#pragma unroll
                for (int njp = 0; njp < 4; njp++) {
                    mma1688_tf32(acc[mi][2 * njp],     af[mi], bf[njp]);
                    mma1688_tf32(acc[mi][2 * njp + 1], af[mi], bf[njp] + 2);
                }
        }
    }

    const int g = lane >> 2;
    const int t = lane & 3;
#pragma unroll
    for (int mi = 0; mi < 4; mi++) {
#pragma unroll
        for (int nj = 0; nj < 8; nj++) {
            int r0 = m0 + mw + 16 * mi + g;
            int cc = n0 + nw + 8 * nj + t * 2;
            *(float2*)(C + (size_t)r0 * N + cc) =
                make_float2(acc[mi][nj][0], acc[mi][nj][1]);
            *(float2*)(C + (size_t)(r0 + 8) * N + cc) =
                make_float2(acc[mi][nj][2], acc[mi][nj][3]);
        }
    }
}

// ---------------------------------------------------------------------------
// RMSNorm + RoPE + hi/lo bf16 split, ONE WARP PER HEAD VECTOR.
// ---------------------------------------------------------------------------
__global__ __launch_bounds__(256) void norm_rope_warp_kernel(
    const float* __restrict__ cosp, const float* __restrict__ sinp,
    const float* __restrict__ qw,   const float* __restrict__ kw)
{
    const int wid  = threadIdx.x >> 5;
    const int lane = threadIdx.x & 31;
    const int gslot = blockIdx.x * 8 + wid;
    const int bs   = gslot / 24;
    const int slot = gslot - bs * 24;
    const int b    = bs >> 11;
    const int s    = bs & 2047;

    const float* src;
    const float* w;
    __nv_bfloat16 *dhi, *dlo;
    if (slot < 16) {
        src = g_qkv + (size_t)bs * cNQKV + slot * cHD;
        w = qw;
        size_t dst = ((size_t)(b * cNH + slot) * cS + s) * cHD;
        dhi = g_q2hi + dst; dlo = g_q2lo + dst;
    } else {
        src = g_qkv + (size_t)bs * cNQKV + 2048 + (slot - 16) * cHD;
        w = kw;
        size_t dst = ((size_t)(b * cNKV + (slot - 16)) * cS + s) * cHD;
        dhi = g_k2hi + dst; dlo = g_k2lo + dst;
    }

    float x[4];
#pragma unroll
    for (int i = 0; i < 4; i++) x[i] = src[lane + 32 * i];

    float v = x[0] * x[0] + x[1] * x[1] + x[2] * x[2] + x[3] * x[3];
#pragma unroll
    for (int o = 16; o; o >>= 1) v += __shfl_xor_sync(0xffffffffu, v, o);
    const float rs = rsqrtf(v * (1.f / cHD) + cEPS);

    float xn[4];
#pragma unroll
    for (int i = 0; i < 4; i++) xn[i] = x[i] * rs * w[lane + 32 * i];

#pragma unroll
    for (int i = 0; i < 4; i++) {
        const int d = lane + 32 * i;
        const float other = (i < 2) ? -xn[i + 2] : xn[i - 2];
        const float cv = cosp[(size_t)bs * cHD + d];
        const float sv = sinp[(size_t)bs * cHD + d];
        const float val = xn[i] * cv + other * sv;
        const __nv_bfloat16 hi = __float2bfloat16(val);
        dhi[d] = hi;
        dlo[d] = __float2bfloat16(val - __bfloat162float(hi));
    }
}

// ---------------------------------------------------------------------------
// TWO-PASS single-kernel MMA attention.
// Pass 1: K-only, FOUR-stage pipeline (V space reused), QK + exp, accumulate l.
// Pass 2: K+V two-stage, recompute QK/exp, store normalized weights once,
//         PV tf32 via K-row-permute trick, output scaled by inv.
// ---------------------------------------------------------------------------
namespace {
constexpr int KTB = 64 * 272;
constexpr int VTB = 128 * 272;
constexpr int KVSTAGE = 2 * KTB + VTB;
constexpr int K4STAGE = 2 * KTB;                   // pass-1 K-only stage
constexpr int ATTN_SMEM = 4 * KTB + 2 * KVSTAGE;   // 208896 (4 K4 stages fit)
__device__ __constant__ int c_kperm[8] = {0, 2, 4, 6, 1, 3, 5, 7};
}

__global__ __launch_bounds__(256, 1)
void attn_mma_kernel(const __nv_bfloat16* __restrict__ qhi_g,
                     const __nv_bfloat16* __restrict__ qlo_g,
                     const __nv_bfloat16* __restrict__ khi_g,
                     const __nv_bfloat16* __restrict__ klo_g,
                     const float* __restrict__ vt_g,
                     float* __restrict__ wout,
                     float* __restrict__ outp,
                     int write_w)
{
    extern __shared__ char smraw[];
    const uint32_t uQ  = smem_u32(smraw);
    const uint32_t uKV = uQ + 4 * KTB;

    const int tid  = threadIdx.x;
    const int wid  = tid >> 5;
    const int lane = tid & 31;
    const int qt  = gridDim.y - 1 - blockIdx.y;    // heavy-first
    const int bkv = blockIdx.x;
    const int b   = bkv >> 3;
    const int kvh = bkv & 7;
    const int hs  = wid >> 2;
    const int h   = kvh * 2 + hs;
    const int wr  = (wid & 3) * 16;
    const int q0  = qt * 64;
    const int g   = lane >> 2;
    const int t   = lane & 3;

    // ---- Q tiles (4: h0hi, h0lo, h1hi, h1lo)
    {
        const size_t qrow = ((size_t)(b * cNH + kvh * 2) * cS + q0) * cHD;
        const int row = (tid >> 4);
        const int c   = tid & 15;
#pragma unroll
        for (int i = 0; i < 16; i++) {
            const int tile = i >> 2;
            const int rr = (i & 3) * 16 + row;
            const __nv_bfloat16* base = (tile & 1) ? qlo_g : qhi_g;
            const __nv_bfloat16* src = base + qrow +
                (size_t)(tile >> 1) * cS * cHD + (size_t)rr * cHD + c * 8;
            cp_async16(uQ + tile * KTB + rr * 272 + c * 16, src);
        }
    }
    CP_COMMIT();

    const size_t krow0 = ((size_t)(b * cNKV + kvh) * cS) * cHD;
    const size_t vbase = ((size_t)(b * cNKV + kvh) * cHD) * cS;
    const int lrow = (tid >> 4);
    const int lc   = tid & 15;

// K tiles into an arbitrary byte base (used by both passes)
#define LOAD_K_AT(kt_, ubase_)                                                \
    do {                                                                      \
        const size_t krow = krow0 + (size_t)((kt_) * 64) * cHD;               \
        _Pragma("unroll")                                                     \
        for (int i = 0; i < 8; i++) {                                         \
            const int tile = i >> 2;                                          \
            const int rr = (i & 3) * 16 + lrow;                               \
            const int srr = (rr & 0x38) | c_kperm[rr & 7];                    \
            const __nv_bfloat16* base = tile ? klo_g : khi_g;                 \
            cp_async16((ubase_) + tile * KTB + srr * 272 + lc * 16,           \
                       base + krow + (size_t)rr * cHD + lc * 8);              \
        }                                                                     \
    } while (0)

#define LOAD_V_AT(kt_, ubase_)                                                \
    do {                                                                      \
        _Pragma("unroll")                                                     \
        for (int i = 0; i < 8; i++) {                                         \
            const int dd = i * 16 + lrow;                                     \
            cp_async16((ubase_) + 2 * KTB + dd * 272 + lc * 16,               \
                       vt_g + vbase + (size_t)dd * cS + (kt_) * 64 + lc * 4); \
        }                                                                     \
    } while (0)

    const uint32_t qoff = (uint32_t)((wr + (lane & 15)) * 272 + (lane >> 4) * 16);
    const uint32_t koff = (uint32_t)(((lane & 7) + ((lane >> 4) & 1) * 8) * 272 +
                                     ((lane >> 3) & 1) * 16);
    const uint32_t voff = (uint32_t)(((lane & 7) + ((lane >> 4) & 1) * 8) * 272 +
                                     ((lane >> 3) & 1) * 16);
    const uint32_t uQh = uQ + hs * 2 * KTB;
    const uint32_t uQl = uQh + KTB;

    float l0 = 0.f, l1 = 0.f;

    // ============ PASS 1: l accumulation (K only, 4-stage pipeline) ========
#pragma unroll
    for (int s = 0; s < 3; s++) {
        if (s <= qt) LOAD_K_AT(s, uKV + s * K4STAGE);
        CP_COMMIT();
    }

    for (int kt = 0; kt <= qt; kt++) {
        CP_WAIT(2);
        __syncthreads();

        const int nx = kt + 3;
        if (nx <= qt) LOAD_K_AT(nx, uKV + (nx & 3) * K4STAGE);
        CP_COMMIT();

        const uint32_t ust  = uKV + (kt & 3) * K4STAGE;
        const uint32_t ukhi = ust;
        const uint32_t uklo = ust + KTB;

        float sacc[8][4];
#pragma unroll
        for (int i = 0; i < 8; i++)
#pragma unroll
            for (int r = 0; r < 4; r++) sacc[i][r] = 0.f;

#pragma unroll
        for (int kk = 0; kk < 8; kk++) {
            uint32_t qh[4], ql[4];
            ldm_x4(qh, uQh + qoff + kk * 32);
            ldm_x4(ql, uQl + qoff + kk * 32);
#pragma unroll
            for (int njp = 0; njp < 4; njp++) {
                uint32_t kb[4];
                ldm_x4(kb, ukhi + njp * (16 * 272) + koff + kk * 32);
                mma16816(sacc[2 * njp],     qh, kb);
                mma16816(sacc[2 * njp + 1], qh, kb + 2);
                mma16816(sacc[2 * njp],     ql, kb);
                mma16816(sacc[2 * njp + 1], ql, kb + 2);
            }
#pragma unroll
            for (int njp = 0; njp < 4; njp++) {
                uint32_t kb[4];
                ldm_x4(kb, uklo + njp * (16 * 272) + koff + kk * 32);
                mma16816(sacc[2 * njp],     qh, kb);
                mma16816(sacc[2 * njp + 1], qh, kb + 2);
            }
        }

        const bool diag = (kt == qt);
#pragma unroll
        for (int nj = 0; nj < 8; nj++) {
            float p0 = __expf(sacc[nj][0] * cSCALE);
            float p1 = __expf(sacc[nj][1] * cSCALE);
            float p2 = __expf(sacc[nj][2] * cSCALE);
            float p3 = __expf(sacc[nj][3] * cSCALE);
            if (diag) {
                const int col0 = nj * 8 + t;
                const int col1 = col0 + 4;
                const int rlo = wr + g, rhi = wr + 8 + g;
                if (col0 > rlo) p0 = 0.f;
                if (col1 > rlo) p1 = 0.f;
                if (col0 > rhi) p2 = 0.f;
                if (col1 > rhi) p3 = 0.f;
            }
            l0 += p0 + p1;
            l1 += p2 + p3;
        }
    }
    CP_WAIT(0);          // drain ledger (incl. empty tail groups)
    __syncthreads();

    l0 += __shfl_xor_sync(0xffffffffu, l0, 1);
    l0 += __shfl_xor_sync(0xffffffffu, l0, 2);
    l1 += __shfl_xor_sync(0xffffffffu, l1, 1);
    l1 += __shfl_xor_sync(0xffffffffu, l1, 2);
    const float inv0 = 1.f / l0;
    const float inv1 = 1.f / l1;

    // =================== PASS 2: weights (normalized) + PV =================
    float oacc[16][4];
#pragma unroll
    for (int i = 0; i < 16; i++)
#pragma unroll
        for (int r = 0; r < 4; r++) oacc[i][r] = 0.f;

    LOAD_K_AT(0, uKV);
    LOAD_V_AT(0, uKV);
    CP_COMMIT();

    for (int kt = 0; kt <= qt; kt++) {
        if (kt < qt) {
            const uint32_t un = uKV + ((kt + 1) & 1) * KVSTAGE;
            LOAD_K_AT(kt + 1, un);
            LOAD_V_AT(kt + 1, un);
            CP_COMMIT();
            CP_WAIT(1);
        } else {
            CP_WAIT(0);
        }
        __syncthreads();

        const uint32_t ust  = uKV + (kt & 1) * KVSTAGE;
        const uint32_t ukhi = ust;
        const uint32_t uklo = ust + KTB;
        const uint32_t uvt  = ust + 2 * KTB;

        float sacc[8][4];
#pragma unroll
        for (int i = 0; i < 8; i++)
#pragma unroll
            for (int r = 0; r < 4; r++) sacc[i][r] = 0.f;

#pragma unroll
        for (int kk = 0; kk < 8; kk++) {
            uint32_t qh[4], ql[4];
            ldm_x4(qh, uQh + qoff + kk * 32);
            ldm_x4(ql, uQl + qoff + kk * 32);
#pragma unroll
            for (int njp = 0; njp < 4; njp++) {
                uint32_t kb[4];
                ldm_x4(kb, ukhi + njp * (16 * 272) + koff + kk * 32);
                mma16816(sacc[2 * njp],     qh, kb);
                mma16816(sacc[2 * njp + 1], qh, kb + 2);
                mma16816(sacc[2 * njp],     ql, kb);
                mma16816(sacc[2 * njp + 1], ql, kb + 2);
            }
#pragma unroll
            for (int njp = 0; njp < 4; njp++) {
                uint32_t kb[4];
                ldm_x4(kb, uklo + njp * (16 * 272) + koff + kk * 32);
                mma16816(sacc[2 * njp],     qh, kb);
                mma16816(sacc[2 * njp + 1], qh, kb + 2);
            }
        }

        const bool diag = (kt == qt);
        uint32_t pt[8][4];
#pragma unroll
        for (int nj = 0; nj < 8; nj++) {
            float p0 = __expf(sacc[nj][0] * cSCALE);
            float p1 = __expf(sacc[nj][1] * cSCALE);
            float p2 = __expf(sacc[nj][2] * cSCALE);
            float p3 = __expf(sacc[nj][3] * cSCALE);
            if (diag) {
                const int col0 = nj * 8 + t;
                const int col1 = col0 + 4;
                const int rlo = wr + g, rhi = wr + 8 + g;
                if (col0 > rlo) p0 = 0.f;
                if (col1 > rlo) p1 = 0.f;
                if (col0 > rhi) p2 = 0.f;
                if (col1 > rhi) p3 = 0.f;
            }
            if (write_w) {
                float* w0 = wout + ((size_t)(b * cNH + h) * cS + q0 + wr + g) * cS
                            + kt * 64 + nj * 8 + t;
                w0[0] = p0 * inv0;
                w0[4] = p1 * inv0;
                float* w1 = w0 + 8 * (size_t)cS;
                w1[0] = p2 * inv1;
                w1[4] = p3 * inv1;
            }
            pt[nj][0] = tf32b(p0);
            pt[nj][1] = tf32b(p2);
            pt[nj][2] = tf32b(p1);
            pt[nj][3] = tf32b(p3);
        }

#pragma unroll
        for (int nj = 0; nj < 8; nj++) {
#pragma unroll
            for (int nd2 = 0; nd2 < 8; nd2++) {
                uint32_t vb[4];
                ldm_x4(vb, uvt + nd2 * (16 * 272) + nj * 32 + voff);
                mma1688_tf32(oacc[2 * nd2],     pt[nj], vb);
                mma1688_tf32(oacc[2 * nd2 + 1], pt[nj], vb + 2);
            }
        }
        __syncthreads();
    }

    // ---- PV output (normalized, tf32-rounded for the Wo GEMM) ----
#pragma unroll
    for (int nd = 0; nd < 16; nd++) {
        const int col = nd * 8 + 2 * t;
        float* o0 = outp + ((size_t)(b * cS + q0 + wr + g) * cNH + h) * cHD + col;
        float* o1 = outp + ((size_t)(b * cS + q0 + wr + 8 + g) * cNH + h) * cHD + col;
        *(float2*)o0 = make_float2(tf32r(oacc[nd][0] * inv0),
                                   tf32r(oacc[nd][1] * inv0));
        *(float2*)o1 = make_float2(tf32r(oacc[nd][2] * inv1),
                                   tf32r(oacc[nd][3] * inv1));
    }

    // ---- zero the upper-triangle tail of this CTA's 128 rows ----
    if (write_w) {
        const int zc = cS - (q0 + 64);
        if (zc > 0) {
            const int z4 = zc >> 2;
            const int tot = 128 * z4;
            const float4 z = make_float4(0.f, 0.f, 0.f, 0.f);
            for (int i = tid; i < tot; i += 256) {
                const int r  = i / z4;
                const int c4 = i - r * z4;
                const int head = r >> 6;
                const int row  = r & 63;
                float* p = wout +
                    ((size_t)(b * cNH + kvh * 2 + head) * cS + q0 + row) * cS +
                    q0 + 64 + c4 * 4;
                *(float4*)p = z;
            }
        }
    }
}

// ---------------------------------------------------------------------------
// Launch (single stream)
// ---------------------------------------------------------------------------
extern "C" void kernel_launch(void* const* d_in, const int* in_sizes, int n_in,
                              void* d_out, int out_size)
{
    const float* hidden = (const float*)d_in[0];
    const float* cosp   = (const float*)d_in[1];
    const float* sinp   = (const float*)d_in[2];
    const float* wq  = (const float*)d_in[4];
    const float* wk  = (const float*)d_in[5];
    const float* wv  = (const float*)d_in[6];
    const float* wo  = (const float*)d_in[7];
    const float* qnw = (const float*)d_in[8];
    const float* knw = (const float*)d_in[9];

    float* out = (float*)d_out;
    const size_t n_attn = (size_t)cM * cHID;
    const size_t n_w    = (size_t)cB * cNH * cS * cS;
    const int write_w   = ((size_t)out_size >= n_attn + n_w) ? 1 : 0;
    float* weights = out + n_attn;

    float *pahf, *pqkv, *pa, *pwt, *pwot, *pvt;
    cudaGetSymbolAddress((void**)&pahf, g_ahf);
    cudaGetSymbolAddress((void**)&pqkv, g_qkv);
    cudaGetSymbolAddress((void**)&pa,   g_att);
    cudaGetSymbolAddress((void**)&pwt,  g_wt);
    cudaGetSymbolAddress((void**)&pwot, g_wot);
    cudaGetSymbolAddress((void**)&pvt,  g_vt);
    __nv_bfloat16 *pqh, *pql, *pkh, *pklo;
    cudaGetSymbolAddress((void**)&pqh,  g_q2hi);
    cudaGetSymbolAddress((void**)&pql,  g_q2lo);
    cudaGetSymbolAddress((void**)&pkh,  g_k2hi);
    cudaGetSymbolAddress((void**)&pklo, g_k2lo);

    static bool attr_done = false;
    if (!attr_done) {
        cudaFuncSetAttribute(gemm_tf32_kernel,
                             cudaFuncAttributeMaxDynamicSharedMemorySize, GEMM_SMEM);
        cudaFuncSetAttribute(attn_mma_kernel,
                             cudaFuncAttributeMaxDynamicSharedMemorySize, ATTN_SMEM);
        attr_done = true;
    }

    // --- prep: tf32-rounded A; all 4 weight transposes in one launch ---
    round_tf32_kernel<<<(cM * cHID / 4) / 256, 256>>>(hidden, pahf);
    {
        WTJob j0 = { wq, pwt,                          2048 };
        WTJob j1 = { wk, pwt + (size_t)2048 * cHID,    1024 };
        WTJob j2 = { wv, pwt + (size_t)3072 * cHID,    1024 };
        WTJob j3 = { wo, pwot,                         2048 };
        cvt_wT4_kernel<<<dim3(64, 64, 4), dim3(32, 8)>>>(j0, j1, j2, j3, cHID);
    }

    // --- fused QKV projection (tf32) ---
    gemm_tf32_kernel<<<dim3(cNQKV / GBN, cM / GBM), 256, GEMM_SMEM>>>(
        pahf, pwt, pqkv, cM, cNQKV, cHID);

    // --- RMSNorm + RoPE + bf16 hi/lo split (warp-per-head); V^T transpose ---
    norm_rope_warp_kernel<<<cM * 24 / 8, 256>>>(cosp, sinp, qnw, knw);
    vT_kernel<<<dim3(cS / 32, cHD / 32, cB * cNKV), dim3(32, 8)>>>(pqkv, pvt);

    // --- two-pass single-kernel MMA attention (4-stage pass-1 pipeline) ---
    attn_mma_kernel<<<dim3(cB * cNKV, cS / 64), 256, ATTN_SMEM>>>(
        pqh, pql, pkh, pklo, pvt, weights, pa, write_w);

    // --- output projection (tf32) ---
    gemm_tf32_kernel<<<dim3(cHID / GBN, cM / GBM), 256, GEMM_SMEM>>>(
        pa, pwot, out, cM, cHID, cHID);
}

// round 16
// speedup vs baseline: 1.2510x; 1.0031x over previous
#include <cuda_runtime.h>
#include <cuda_bf16.h>
#include <math.h>
#include <stdint.h>

// ---------------------------------------------------------------------------
// Problem constants
// ---------------------------------------------------------------------------
namespace {
constexpr int cB   = 2;
constexpr int cS   = 2048;
constexpr int cHID = 2048;
constexpr int cNH  = 16;
constexpr int cNKV = 8;
constexpr int cHD  = 128;
constexpr float cEPS   = 1e-6f;
constexpr float cSCALE = 0.08838834764831845f;  // 128^-0.5
constexpr int cM   = cB * cS;        // 4096
constexpr int cNQKV = 4096;          // fused QKV output width
}

// ---------------------------------------------------------------------------
// Scratch (device globals -- no runtime allocation allowed)
// ---------------------------------------------------------------------------
__device__ float g_ahf [(size_t)cM * cHID];        // tf32-rounded hidden
__device__ float g_qkv [(size_t)cM * cNQKV];       // fused QKV projection out
__device__ float g_att [(size_t)cM * cNH * cHD];   // attn out pre-Wo (tf32-rounded)
__device__ float g_wt  [(size_t)cNQKV * cHID];     // [wq|wk|wv]^T tf32-rounded
__device__ float g_wot [(size_t)cHID * cHID];      // wo^T tf32-rounded
__device__ float g_vt  [(size_t)cB * cNKV * cHD * cS]; // V^T fp32 [b][kvh][d][s]

// bf16 hi/lo planes for attention QK, head-major layout [b][h][s][d]
__device__ __nv_bfloat16 g_q2hi[(size_t)cB * cNH  * cS * cHD];
__device__ __nv_bfloat16 g_q2lo[(size_t)cB * cNH  * cS * cHD];
__device__ __nv_bfloat16 g_k2hi[(size_t)cB * cNKV * cS * cHD];
__device__ __nv_bfloat16 g_k2lo[(size_t)cB * cNKV * cS * cHD];

// ---------------------------------------------------------------------------
// PTX helpers (portable: sm_80+)
// ---------------------------------------------------------------------------
__device__ __forceinline__ uint32_t smem_u32(const void* p) {
    uint32_t a;
    asm("{ .reg .u64 t; cvta.to.shared.u64 t, %1; cvt.u32.u64 %0, t; }"
        : "=r"(a) : "l"(p));
    return a;
}
__device__ __forceinline__ void cp_async16(uint32_t saddr, const void* gaddr) {
    asm volatile("cp.async.cg.shared.global [%0], [%1], 16;"
                 :: "r"(saddr), "l"(gaddr) : "memory");
}
#define CP_COMMIT()  asm volatile("cp.async.commit_group;" ::: "memory")
#define CP_WAIT(N)   asm volatile("cp.async.wait_group %0;" :: "n"(N) : "memory")

__device__ __forceinline__ void ldm_x4(uint32_t* r, uint32_t addr) {
    asm volatile("ldmatrix.sync.aligned.m8n8.x4.shared.b16 {%0,%1,%2,%3}, [%4];"
                 : "=r"(r[0]), "=r"(r[1]), "=r"(r[2]), "=r"(r[3]) : "r"(addr));
}
__device__ __forceinline__ void mma16816(float* d, const uint32_t* a,
                                         const uint32_t* b) {
    asm volatile(
        "mma.sync.aligned.m16n8k16.row.col.f32.bf16.bf16.f32 "
        "{%0,%1,%2,%3}, {%4,%5,%6,%7}, {%8,%9}, {%0,%1,%2,%3};"
        : "+f"(d[0]), "+f"(d[1]), "+f"(d[2]), "+f"(d[3])
        : "r"(a[0]), "r"(a[1]), "r"(a[2]), "r"(a[3]), "r"(b[0]), "r"(b[1]));
}
__device__ __forceinline__ void mma1688_tf32(float* d, const uint32_t* a,
                                             const uint32_t* b) {
    asm volatile(
        "mma.sync.aligned.m16n8k8.row.col.f32.tf32.tf32.f32 "
        "{%0,%1,%2,%3}, {%4,%5,%6,%7}, {%8,%9}, {%0,%1,%2,%3};"
        : "+f"(d[0]), "+f"(d[1]), "+f"(d[2]), "+f"(d[3])
        : "r"(a[0]), "r"(a[1]), "r"(a[2]), "r"(a[3]), "r"(b[0]), "r"(b[1]));
}
__device__ __forceinline__ uint32_t sw128(uint32_t off) {
    return off ^ ((off >> 3) & 0x70);
}
__device__ __forceinline__ float tf32r(float x) {
    uint32_t u;
    asm("cvt.rna.tf32.f32 %0, %1;" : "=r"(u) : "f"(x));
    return __uint_as_float(u);
}
__device__ __forceinline__ uint32_t tf32b(float x) {
    uint32_t u;
    asm("cvt.rna.tf32.f32 %0, %1;" : "=r"(u) : "f"(x));
    return u;
}

// ---------------------------------------------------------------------------
// Prep kernels
// ---------------------------------------------------------------------------
__global__ __launch_bounds__(256) void round_tf32_kernel(
    const float* __restrict__ X, float* __restrict__ Y)
{
    size_t e = ((size_t)blockIdx.x * 256 + threadIdx.x) * 4;
    float4 x = *(const float4*)(X + e);
    x.x = tf32r(x.x); x.y = tf32r(x.y); x.z = tf32r(x.z); x.w = tf32r(x.w);
    *(float4*)(Y + e) = x;
}

// All four weight transposes in one launch (blockIdx.z selects matrix).
struct WTJob { const float* W; float* Y; int N; };

__global__ __launch_bounds__(256) void cvt_wT4_kernel(
    WTJob j0, WTJob j1, WTJob j2, WTJob j3, int K)
{
    const WTJob j = (blockIdx.z == 0) ? j0 : (blockIdx.z == 1) ? j1 :
                    (blockIdx.z == 2) ? j2 : j3;
    const int n0 = blockIdx.x * 32;
    if (n0 >= j.N) return;
    const int k0 = blockIdx.y * 32;
    const int tx = threadIdx.x;
    const int ty = threadIdx.y;
    __shared__ float t[32][33];
#pragma unroll
    for (int i = 0; i < 32; i += 8)
        t[ty + i][tx] = j.W[(size_t)(k0 + ty + i) * j.N + n0 + tx];
    __syncthreads();
#pragma unroll
    for (int i = 0; i < 32; i += 8) {
        int n = n0 + ty + i;
        int k = k0 + tx;
        j.Y[(size_t)n * K + k] = tf32r(t[tx][ty + i]);
    }
}

// ---------------------------------------------------------------------------
// FUSED post-QKV prep: one launch.
//   blocks [0, NRB)          : RMSNorm + RoPE + hi/lo bf16 split (warp/head)
//   blocks [NRB, NRB + NVB)  : V^T transpose tiles (tf32-rounded)
// Each output word produced by instruction sequences identical to the prior
// separate kernels -> bitwise-identical results.
// ---------------------------------------------------------------------------
namespace {
constexpr int NRB = cM * 24 / 8;          // 12288 norm/rope blocks
constexpr int NVB = (cS / 32) * (cHD / 32) * (cB * cNKV);  // 4096 vT blocks
}

__global__ __launch_bounds__(256) void postqkv_prep_kernel(
    const float* __restrict__ cosp, const float* __restrict__ sinp,
    const float* __restrict__ qw,   const float* __restrict__ kw,
    float* __restrict__ vt)
{
    if (blockIdx.x < NRB) {
        // ---- norm + rope + split (warp per head vector) ----
        const int wid  = threadIdx.x >> 5;
        const int lane = threadIdx.x & 31;
        const int gslot = blockIdx.x * 8 + wid;
        const int bs   = gslot / 24;
        const int slot = gslot - bs * 24;
        const int b    = bs >> 11;
        const int s    = bs & 2047;

        const float* src;
        const float* w;
        __nv_bfloat16 *dhi, *dlo;
        if (slot < 16) {
            src = g_qkv + (size_t)bs * cNQKV + slot * cHD;
            w = qw;
            size_t dst = ((size_t)(b * cNH + slot) * cS + s) * cHD;
            dhi = g_q2hi + dst; dlo = g_q2lo + dst;
        } else {
            src = g_qkv + (size_t)bs * cNQKV + 2048 + (slot - 16) * cHD;
            w = kw;
            size_t dst = ((size_t)(b * cNKV + (slot - 16)) * cS + s) * cHD;
            dhi = g_k2hi + dst; dlo = g_k2lo + dst;
        }

        float x[4];
#pragma unroll
        for (int i = 0; i < 4; i++) x[i] = src[lane + 32 * i];

        float v = x[0] * x[0] + x[1] * x[1] + x[2] * x[2] + x[3] * x[3];
#pragma unroll
        for (int o = 16; o; o >>= 1) v += __shfl_xor_sync(0xffffffffu, v, o);
        const float rs = rsqrtf(v * (1.f / cHD) + cEPS);

        float xn[4];
#pragma unroll
        for (int i = 0; i < 4; i++) xn[i] = x[i] * rs * w[lane + 32 * i];

#pragma unroll
        for (int i = 0; i < 4; i++) {
            const int d = lane + 32 * i;
            const float other = (i < 2) ? -xn[i + 2] : xn[i - 2];
            const float cv = cosp[(size_t)bs * cHD + d];
            const float sv = sinp[(size_t)bs * cHD + d];
            const float val = xn[i] * cv + other * sv;
            const __nv_bfloat16 hi = __float2bfloat16(val);
            dhi[d] = hi;
            dlo[d] = __float2bfloat16(val - __bfloat162float(hi));
        }
    } else {
        // ---- V^T transpose tile ----
        const int vb = blockIdx.x - NRB;
        const int s0 = (vb & 63) * 32;           // cS/32 = 64
        const int d0 = ((vb >> 6) & 3) * 32;     // cHD/32 = 4
        const int bk = vb >> 8;                  // b*8 + kvh
        const int b  = bk >> 3;
        const int kvh = bk & 7;
        const int tx = threadIdx.x & 31;
        const int ty = threadIdx.x >> 5;

        __shared__ float t[32][33];
#pragma unroll
        for (int i = 0; i < 32; i += 8)
            t[ty + i][tx] = g_qkv[(size_t)(b * cS + s0 + ty + i) * cNQKV +
                                  3072 + kvh * cHD + d0 + tx];
        __syncthreads();
#pragma unroll
        for (int i = 0; i < 32; i += 8)
            vt[((size_t)bk * cHD + d0 + ty + i) * cS + s0 + tx] =
                tf32r(t[tx][ty + i]);
    }
}

// ---------------------------------------------------------------------------
// TF32 HMMA GEMM: C[M,N] = A[M,K] @ B[N,K]^T (row-major fp32, tf32-prerounded)
// CTA tile 128x256, BK=32, 4-stage cp.async, SW128, warp tile 64x64.
// ---------------------------------------------------------------------------
namespace {
constexpr int GBM = 128, GBN = 256, GBK = 32;
constexpr int NSTAGE = 4;
constexpr int A_BYTES = GBM * GBK * 4;              // 16KB
constexpr int B_BYTES = GBN * GBK * 4;              // 32KB
constexpr int STAGE_BYTES = A_BYTES + B_BYTES;      // 48KB
constexpr int GEMM_SMEM   = NSTAGE * STAGE_BYTES;   // 192KB
}

__device__ __forceinline__ void gemm_load_stage(
    const float* __restrict__ Ag, const float* __restrict__ Bg,
    int K, int it, uint32_t stage_base, int tid)
{
#pragma unroll
    for (int i = 0; i < 4; i++) {
        int idx = tid + (i << 8);
        int row = idx >> 3;
        int c4  = idx & 7;
        uint32_t sw = sw128((uint32_t)(row * 128 + c4 * 16));
        cp_async16(stage_base + sw,
                   Ag + (size_t)row * K + (size_t)it * GBK + c4 * 4);
    }
#pragma unroll
    for (int i = 0; i < 8; i++) {
        int idx = tid + (i << 8);
        int row = idx >> 3;
        int c4  = idx & 7;
        uint32_t sw = sw128((uint32_t)(row * 128 + c4 * 16));
        cp_async16(stage_base + A_BYTES + sw,
                   Bg + (size_t)row * K + (size_t)it * GBK + c4 * 4);
    }
}

__global__ __launch_bounds__(256, 1)
void gemm_tf32_kernel(const float* __restrict__ A,
                      const float* __restrict__ B,
                      float* __restrict__ C, int M, int N, int K)
{
    extern __shared__ char smraw[];
    const uint32_t sbase = smem_u32(smraw);

    const int tid  = threadIdx.x;
    const int wid  = tid >> 5;
    const int lane = tid & 31;
    const int m0 = blockIdx.y * GBM;
    const int n0 = blockIdx.x * GBN;
    const int mw = (wid >> 2) * 64;
    const int nw = (wid & 3) * 64;

    const float* Ag = A + (size_t)m0 * K;
    const float* Bg = B + (size_t)n0 * K;
    const int KITERS = K / GBK;

    float acc[4][8][4];
#pragma unroll
    for (int i = 0; i < 4; i++)
#pragma unroll
        for (int j = 0; j < 8; j++)
#pragma unroll
            for (int r = 0; r < 4; r++) acc[i][j][r] = 0.f;

    const int a_row = lane & 15;
    const int a_cb  = (lane >> 4) * 16;
    const int b_row = (lane & 7) + ((lane >> 4) & 1) * 8;
    const int b_cb  = ((lane >> 3) & 1) * 16;

#pragma unroll
    for (int s = 0; s < NSTAGE - 1; s++) {
        gemm_load_stage(Ag, Bg, K, s, sbase + s * STAGE_BYTES, tid);
        CP_COMMIT();
    }

    for (int it = 0; it < KITERS; ++it) {
        CP_WAIT(NSTAGE - 2);
        __syncthreads();

        int nx = it + NSTAGE - 1;
        if (nx < KITERS)
            gemm_load_stage(Ag, Bg, K, nx,
                            sbase + (nx % NSTAGE) * STAGE_BYTES, tid);
        CP_COMMIT();

        const uint32_t sa = sbase + (it % NSTAGE) * STAGE_BYTES;
        const uint32_t sb = sa + A_BYTES;

#pragma unroll
        for (int ks = 0; ks < 4; ks++) {
            uint32_t af[4][4], bf[4][4];
#pragma unroll
            for (int mi = 0; mi < 4; mi++) {
                uint32_t off = (uint32_t)((mw + 16 * mi + a_row) * 128 +
                                          ks * 32 + a_cb);
                ldm_x4(af[mi], sa + sw128(off));
            }
#pragma unroll
            for (int njp = 0; njp < 4; njp++) {
                uint32_t off = (uint32_t)((nw + 16 * njp + b_row) * 128 +
                                          ks * 32 + b_cb);
                ldm_x4(bf[njp], sb + sw128(off));
            }
#pragma unroll
            for (int mi = 0; mi < 4; mi++)
#pragma unroll
                for (int njp = 0; njp < 4; njp++) {
                    mma1688_tf32(acc[mi][2 * njp],     af[mi], bf[njp]);
                    mma1688_tf32(acc[mi][2 * njp + 1], af[mi], bf[njp] + 2);
                }
        }
    }

    const int g = lane >> 2;
    const int t = lane & 3;
#pragma unroll
    for (int mi = 0; mi < 4; mi++) {
#pragma unroll
        for (int nj = 0; nj < 8; nj++) {
            int r0 = m0 + mw + 16 * mi + g;
            int cc = n0 + nw + 8 * nj + t * 2;
            *(float2*)(C + (size_t)r0 * N + cc) =
                make_float2(acc[mi][nj][0], acc[mi][nj][1]);
            *(float2*)(C + (size_t)(r0 + 8) * N + cc) =
                make_float2(acc[mi][nj][2], acc[mi][nj][3]);
        }
    }
}

// ---------------------------------------------------------------------------
// TWO-PASS single-kernel MMA attention.
// Pass 1: K-only, FOUR-stage pipeline (V space reused), QK + exp, accumulate l.
// Pass 2: K+V two-stage, recompute QK/exp, store normalized weights once,
//         PV tf32 via K-row-permute trick, output scaled by inv.
// ---------------------------------------------------------------------------
namespace {
constexpr int KTB = 64 * 272;
constexpr int VTB = 128 * 272;
constexpr int KVSTAGE = 2 * KTB + VTB;
constexpr int K4STAGE = 2 * KTB;                   // pass-1 K-only stage
constexpr int ATTN_SMEM = 4 * KTB + 2 * KVSTAGE;   // 208896 (4 K4 stages fit)
__device__ __constant__ int c_kperm[8] = {0, 2, 4, 6, 1, 3, 5, 7};
}

__global__ __launch_bounds__(256, 1)
void attn_mma_kernel(const __nv_bfloat16* __restrict__ qhi_g,
                     const __nv_bfloat16* __restrict__ qlo_g,
                     const __nv_bfloat16* __restrict__ khi_g,
                     const __nv_bfloat16* __restrict__ klo_g,
                     const float* __restrict__ vt_g,
                     float* __restrict__ wout,
                     float* __restrict__ outp,
                     int write_w)
{
    extern __shared__ char smraw[];
    const uint32_t uQ  = smem_u32(smraw);
    const uint32_t uKV = uQ + 4 * KTB;

    const int tid  = threadIdx.x;
    const int wid  = tid >> 5;
    const int lane = tid & 31;
    const int qt  = gridDim.y - 1 - blockIdx.y;    // heavy-first
    const int bkv = blockIdx.x;
    const int b   = bkv >> 3;
    const int kvh = bkv & 7;
    const int hs  = wid >> 2;
    const int h   = kvh * 2 + hs;
    const int wr  = (wid & 3) * 16;
    const int q0  = qt * 64;
    const int g   = lane >> 2;
    const int t   = lane & 3;

    // ---- Q tiles (4: h0hi, h0lo, h1hi, h1lo)
    {
        const size_t qrow = ((size_t)(b * cNH + kvh * 2) * cS + q0) * cHD;
        const int row = (tid >> 4);
        const int c   = tid & 15;
#pragma unroll
        for (int i = 0; i < 16; i++) {
            const int tile = i >> 2;
            const int rr = (i & 3) * 16 + row;
            const __nv_bfloat16* base = (tile & 1) ? qlo_g : qhi_g;
            const __nv_bfloat16* src = base + qrow +
                (size_t)(tile >> 1) * cS * cHD + (size_t)rr * cHD + c * 8;
            cp_async16(uQ + tile * KTB + rr * 272 + c * 16, src);
        }
    }
    CP_COMMIT();

    const size_t krow0 = ((size_t)(b * cNKV + kvh) * cS) * cHD;
    const size_t vbase = ((size_t)(b * cNKV + kvh) * cHD) * cS;
    const int lrow = (tid >> 4);
    const int lc   = tid & 15;

#define LOAD_K_AT(kt_, ubase_)                                                \
    do {                                                                      \
        const size_t krow = krow0 + (size_t)((kt_) * 64) * cHD;               \
        _Pragma("unroll")                                                     \
        for (int i = 0; i < 8; i++) {                                         \
            const int tile = i >> 2;                                          \
            const int rr = (i & 3) * 16 + lrow;                               \
            const int srr = (rr & 0x38) | c_kperm[rr & 7];                    \
            const __nv_bfloat16* base = tile ? klo_g : khi_g;                 \
            cp_async16((ubase_) + tile * KTB + srr * 272 + lc * 16,           \
                       base + krow + (size_t)rr * cHD + lc * 8);              \
        }                                                                     \
    } while (0)

#define LOAD_V_AT(kt_, ubase_)                                                \
    do {                                                                      \
        _Pragma("unroll")                                                     \
        for (int i = 0; i < 8; i++) {                                         \
            const int dd = i * 16 + lrow;                                     \
            cp_async16((ubase_) + 2 * KTB + dd * 272 + lc * 16,               \
                       vt_g + vbase + (size_t)dd * cS + (kt_) * 64 + lc * 4); \
        }                                                                     \
    } while (0)

    const uint32_t qoff = (uint32_t)((wr + (lane & 15)) * 272 + (lane >> 4) * 16);
    const uint32_t koff = (uint32_t)(((lane & 7) + ((lane >> 4) & 1) * 8) * 272 +
                                     ((lane >> 3) & 1) * 16);
    const uint32_t voff = (uint32_t)(((lane & 7) + ((lane >> 4) & 1) * 8) * 272 +
                                     ((lane >> 3) & 1) * 16);
    const uint32_t uQh = uQ + hs * 2 * KTB;
    const uint32_t uQl = uQh + KTB;

    float l0 = 0.f, l1 = 0.f;

    // ============ PASS 1: l accumulation (K only, 4-stage pipeline) ========
#pragma unroll
    for (int s = 0; s < 3; s++) {
        if (s <= qt) LOAD_K_AT(s, uKV + s * K4STAGE);
        CP_COMMIT();
    }

    for (int kt = 0; kt <= qt; kt++) {
        CP_WAIT(2);
        __syncthreads();

        const int nx = kt + 3;
        if (nx <= qt) LOAD_K_AT(nx, uKV + (nx & 3) * K4STAGE);
        CP_COMMIT();

        const uint32_t ust  = uKV + (kt & 3) * K4STAGE;
        const uint32_t ukhi = ust;
        const uint32_t uklo = ust + KTB;

        float sacc[8][4];
#pragma unroll
        for (int i = 0; i < 8; i++)
#pragma unroll
            for (int r = 0; r < 4; r++) sacc[i][r] = 0.f;

#pragma unroll
        for (int kk = 0; kk < 8; kk++) {
            uint32_t qh[4], ql[4];
            ldm_x4(qh, uQh + qoff + kk * 32);
            ldm_x4(ql, uQl + qoff + kk * 32);
#pragma unroll
            for (int njp = 0; njp < 4; njp++) {
                uint32_t kb[4];
                ldm_x4(kb, ukhi + njp * (16 * 272) + koff + kk * 32);
                mma16816(sacc[2 * njp],     qh, kb);
                mma16816(sacc[2 * njp + 1], qh, kb + 2);
                mma16816(sacc[2 * njp],     ql, kb);
                mma16816(sacc[2 * njp + 1], ql, kb + 2);
            }
#pragma unroll
            for (int njp = 0; njp < 4; njp++) {
                uint32_t kb[4];
                ldm_x4(kb, uklo + njp * (16 * 272) + koff + kk * 32);
                mma16816(sacc[2 * njp],     qh, kb);
                mma16816(sacc[2 * njp + 1], qh, kb + 2);
            }
        }

        const bool diag = (kt == qt);
#pragma unroll
        for (int nj = 0; nj < 8; nj++) {
            float p0 = __expf(sacc[nj][0] * cSCALE);
            float p1 = __expf(sacc[nj][1] * cSCALE);
            float p2 = __expf(sacc[nj][2] * cSCALE);
            float p3 = __expf(sacc[nj][3] * cSCALE);
            if (diag) {
                const int col0 = nj * 8 + t;
                const int col1 = col0 + 4;
                const int rlo = wr + g, rhi = wr + 8 + g;
                if (col0 > rlo) p0 = 0.f;
                if (col1 > rlo) p1 = 0.f;
                if (col0 > rhi) p2 = 0.f;
                if (col1 > rhi) p3 = 0.f;
            }
            l0 += p0 + p1;
            l1 += p2 + p3;
        }
    }
    CP_WAIT(0);          // drain ledger (incl. empty tail groups)
    __syncthreads();

    l0 += __shfl_xor_sync(0xffffffffu, l0, 1);
    l0 += __shfl_xor_sync(0xffffffffu, l0, 2);
    l1 += __shfl_xor_sync(0xffffffffu, l1, 1);
    l1 += __shfl_xor_sync(0xffffffffu, l1, 2);
    const float inv0 = 1.f / l0;
    const float inv1 = 1.f / l1;

    // =================== PASS 2: weights (normalized) + PV =================
    float oacc[16][4];
#pragma unroll
    for (int i = 0; i < 16; i++)
#pragma unroll
        for (int r = 0; r < 4; r++) oacc[i][r] = 0.f;

    LOAD_K_AT(0, uKV);
    LOAD_V_AT(0, uKV);
    CP_COMMIT();

    for (int kt = 0; kt <= qt; kt++) {
        if (kt < qt) {
            const uint32_t un = uKV + ((kt + 1) & 1) * KVSTAGE;
            LOAD_K_AT(kt + 1, un);
            LOAD_V_AT(kt + 1, un);
            CP_COMMIT();
            CP_WAIT(1);
        } else {
            CP_WAIT(0);
        }
        __syncthreads();

        const uint32_t ust  = uKV + (kt & 1) * KVSTAGE;
        const uint32_t ukhi = ust;
        const uint32_t uklo = ust + KTB;
        const uint32_t uvt  = ust + 2 * KTB;

        float sacc[8][4];
#pragma unroll
        for (int i = 0; i < 8; i++)
#pragma unroll
            for (int r = 0; r < 4; r++) sacc[i][r] = 0.f;

#pragma unroll
        for (int kk = 0; kk < 8; kk++) {
            uint32_t qh[4], ql[4];
            ldm_x4(qh, uQh + qoff + kk * 32);
            ldm_x4(ql, uQl + qoff + kk * 32);
#pragma unroll
            for (int njp = 0; njp < 4; njp++) {
                uint32_t kb[4];
                ldm_x4(kb, ukhi + njp * (16 * 272) + koff + kk * 32);
                mma16816(sacc[2 * njp],     qh, kb);
                mma16816(sacc[2 * njp + 1], qh, kb + 2);
                mma16816(sacc[2 * njp],     ql, kb);
                mma16816(sacc[2 * njp + 1], ql, kb + 2);
            }
#pragma unroll
            for (int njp = 0; njp < 4; njp++) {
                uint32_t kb[4];
                ldm_x4(kb, uklo + njp * (16 * 272) + koff + kk * 32);
                mma16816(sacc[2 * njp],     qh, kb);
                mma16816(sacc[2 * njp + 1], qh, kb + 2);
            }
        }

        const bool diag = (kt == qt);
        uint32_t pt[8][4];
#pragma unroll
        for (int nj = 0; nj < 8; nj++) {
            float p0 = __expf(sacc[nj][0] * cSCALE);
            float p1 = __expf(sacc[nj][1] * cSCALE);
            float p2 = __expf(sacc[nj][2] * cSCALE);
            float p3 = __expf(sacc[nj][3] * cSCALE);
            if (diag) {
                const int col0 = nj * 8 + t;
                const int col1 = col0 + 4;
                const int rlo = wr + g, rhi = wr + 8 + g;
                if (col0 > rlo) p0 = 0.f;
                if (col1 > rlo) p1 = 0.f;
                if (col0 > rhi) p2 = 0.f;
                if (col1 > rhi) p3 = 0.f;
            }
            if (write_w) {
                float* w0 = wout + ((size_t)(b * cNH + h) * cS + q0 + wr + g) * cS
                            + kt * 64 + nj * 8 + t;
                w0[0] = p0 * inv0;
                w0[4] = p1 * inv0;
                float* w1 = w0 + 8 * (size_t)cS;
                w1[0] = p2 * inv1;
                w1[4] = p3 * inv1;
            }
            pt[nj][0] = tf32b(p0);
            pt[nj][1] = tf32b(p2);
            pt[nj][2] = tf32b(p1);
            pt[nj][3] = tf32b(p3);
        }

#pragma unroll
        for (int nj = 0; nj < 8; nj++) {
#pragma unroll
            for (int nd2 = 0; nd2 < 8; nd2++) {
                uint32_t vb[4];
                ldm_x4(vb, uvt + nd2 * (16 * 272) + nj * 32 + voff);
                mma1688_tf32(oacc[2 * nd2],     pt[nj], vb);
                mma1688_tf32(oacc[2 * nd2 + 1], pt[nj], vb + 2);
            }
        }
        __syncthreads();
    }

    // ---- PV output (normalized, tf32-rounded for the Wo GEMM) ----
#pragma unroll
    for (int nd = 0; nd < 16; nd++) {
        const int col = nd * 8 + 2 * t;
        float* o0 = outp + ((size_t)(b * cS + q0 + wr + g) * cNH + h) * cHD + col;
        float* o1 = outp + ((size_t)(b * cS + q0 + wr + 8 + g) * cNH + h) * cHD + col;
        *(float2*)o0 = make_float2(tf32r(oacc[nd][0] * inv0),
                                   tf32r(oacc[nd][1] * inv0));
        *(float2*)o1 = make_float2(tf32r(oacc[nd][2] * inv1),
                                   tf32r(oacc[nd][3] * inv1));
    }

    // ---- zero the upper-triangle tail of this CTA's 128 rows ----
    if (write_w) {
        const int zc = cS - (q0 + 64);
        if (zc > 0) {
            const int z4 = zc >> 2;
            const int tot = 128 * z4;
            const float4 z = make_float4(0.f, 0.f, 0.f, 0.f);
            for (int i = tid; i < tot; i += 256) {
                const int r  = i / z4;
                const int c4 = i - r * z4;
                const int head = r >> 6;
                const int row  = r & 63;
                float* p = wout +
                    ((size_t)(b * cNH + kvh * 2 + head) * cS + q0 + row) * cS +
                    q0 + 64 + c4 * 4;
                *(float4*)p = z;
            }
        }
    }
}

// ---------------------------------------------------------------------------
// Launch (single stream)
// ---------------------------------------------------------------------------
extern "C" void kernel_launch(void* const* d_in, const int* in_sizes, int n_in,
                              void* d_out, int out_size)
{
    const float* hidden = (const float*)d_in[0];
    const float* cosp   = (const float*)d_in[1];
    const float* sinp   = (const float*)d_in[2];
    const float* wq  = (const float*)d_in[4];
    const float* wk  = (const float*)d_in[5];
    const float* wv  = (const float*)d_in[6];
    const float* wo  = (const float*)d_in[7];
    const float* qnw = (const float*)d_in[8];
    const float* knw = (const float*)d_in[9];

    float* out = (float*)d_out;
    const size_t n_attn = (size_t)cM * cHID;
    const size_t n_w    = (size_t)cB * cNH * cS * cS;
    const int write_w   = ((size_t)out_size >= n_attn + n_w) ? 1 : 0;
    float* weights = out + n_attn;

    float *pahf, *pqkv, *pa, *pwt, *pwot, *pvt;
    cudaGetSymbolAddress((void**)&pahf, g_ahf);
    cudaGetSymbolAddress((void**)&pqkv, g_qkv);
    cudaGetSymbolAddress((void**)&pa,   g_att);
    cudaGetSymbolAddress((void**)&pwt,  g_wt);
    cudaGetSymbolAddress((void**)&pwot, g_wot);
    cudaGetSymbolAddress((void**)&pvt,  g_vt);
    __nv_bfloat16 *pqh, *pql, *pkh, *pklo;
    cudaGetSymbolAddress((void**)&pqh,  g_q2hi);
    cudaGetSymbolAddress((void**)&pql,  g_q2lo);
    cudaGetSymbolAddress((void**)&pkh,  g_k2hi);
    cudaGetSymbolAddress((void**)&pklo, g_k2lo);

    static bool attr_done = false;
    if (!attr_done) {
        cudaFuncSetAttribute(gemm_tf32_kernel,
                             cudaFuncAttributeMaxDynamicSharedMemorySize, GEMM_SMEM);
        cudaFuncSetAttribute(attn_mma_kernel,
                             cudaFuncAttributeMaxDynamicSharedMemorySize, ATTN_SMEM);
        attr_done = true;
    }

    // --- prep: tf32-rounded A; all 4 weight transposes in one launch ---
    round_tf32_kernel<<<(cM * cHID / 4) / 256, 256>>>(hidden, pahf);
    {
        WTJob j0 = { wq, pwt,                          2048 };
        WTJob j1 = { wk, pwt + (size_t)2048 * cHID,    1024 };
        WTJob j2 = { wv, pwt + (size_t)3072 * cHID,    1024 };
        WTJob j3 = { wo, pwot,                         2048 };
        cvt_wT4_kernel<<<dim3(64, 64, 4), dim3(32, 8)>>>(j0, j1, j2, j3, cHID);
    }

    // --- fused QKV projection (tf32) ---
    gemm_tf32_kernel<<<dim3(cNQKV / GBN, cM / GBM), 256, GEMM_SMEM>>>(
        pahf, pwt, pqkv, cM, cNQKV, cHID);

    // --- fused post-QKV prep: norm+rope+split AND V^T in ONE launch ---
    postqkv_prep_kernel<<<NRB + NVB, 256>>>(cosp, sinp, qnw, knw, pvt);

    // --- two-pass single-kernel MMA attention (weights written once) ---
    attn_mma_kernel<<<dim3(cB * cNKV, cS / 64), 256, ATTN_SMEM>>>(
        pqh, pql, pkh, pklo, pvt, weights, pa, write_w);

    // --- output projection (tf32) ---
    gemm_tf32_kernel<<<dim3(cHID / GBN, cM / GBM), 256, GEMM_SMEM>>>(
        pa, pwot, out, cM, cHID, cHID);
}

// round 17
// speedup vs baseline: 1.2515x; 1.0004x over previous
#include <cuda_runtime.h>
#include <cuda_bf16.h>
#include <math.h>
#include <stdint.h>

// ---------------------------------------------------------------------------
// Problem constants
// ---------------------------------------------------------------------------
namespace {
constexpr int cB   = 2;
constexpr int cS   = 2048;
constexpr int cHID = 2048;
constexpr int cNH  = 16;
constexpr int cNKV = 8;
constexpr int cHD  = 128;
constexpr float cEPS   = 1e-6f;
constexpr float cSCALE = 0.08838834764831845f;  // 128^-0.5
constexpr int cM   = cB * cS;        // 4096
constexpr int cNQKV = 4096;          // fused QKV output width
}

// ---------------------------------------------------------------------------
// Scratch (device globals -- no runtime allocation allowed)
// ---------------------------------------------------------------------------
__device__ float g_ahf [(size_t)cM * cHID];        // tf32-rounded hidden
__device__ float g_qkv [(size_t)cM * cNQKV];       // fused QKV projection out
__device__ float g_att [(size_t)cM * cNH * cHD];   // attn out pre-Wo (tf32-rounded)
__device__ float g_wt  [(size_t)cNQKV * cHID];     // [wq|wk|wv]^T tf32-rounded
__device__ float g_wot [(size_t)cHID * cHID];      // wo^T tf32-rounded
__device__ float g_vt  [(size_t)cB * cNKV * cHD * cS]; // V^T fp32 [b][kvh][d][s]

// bf16 hi/lo planes for attention QK, head-major layout [b][h][s][d]
__device__ __nv_bfloat16 g_q2hi[(size_t)cB * cNH  * cS * cHD];
__device__ __nv_bfloat16 g_q2lo[(size_t)cB * cNH  * cS * cHD];
__device__ __nv_bfloat16 g_k2hi[(size_t)cB * cNKV * cS * cHD];
__device__ __nv_bfloat16 g_k2lo[(size_t)cB * cNKV * cS * cHD];

// ---------------------------------------------------------------------------
// PTX helpers (portable: sm_80+)
// ---------------------------------------------------------------------------
__device__ __forceinline__ uint32_t smem_u32(const void* p) {
    uint32_t a;
    asm("{ .reg .u64 t; cvta.to.shared.u64 t, %1; cvt.u32.u64 %0, t; }"
        : "=r"(a) : "l"(p));
    return a;
}
__device__ __forceinline__ void cp_async16(uint32_t saddr, const void* gaddr) {
    asm volatile("cp.async.cg.shared.global [%0], [%1], 16;"
                 :: "r"(saddr), "l"(gaddr) : "memory");
}
#define CP_COMMIT()  asm volatile("cp.async.commit_group;" ::: "memory")
#define CP_WAIT(N)   asm volatile("cp.async.wait_group %0;" :: "n"(N) : "memory")

__device__ __forceinline__ void ldm_x4(uint32_t* r, uint32_t addr) {
    asm volatile("ldmatrix.sync.aligned.m8n8.x4.shared.b16 {%0,%1,%2,%3}, [%4];"
                 : "=r"(r[0]), "=r"(r[1]), "=r"(r[2]), "=r"(r[3]) : "r"(addr));
}
__device__ __forceinline__ void mma16816(float* d, const uint32_t* a,
                                         const uint32_t* b) {
    asm volatile(
        "mma.sync.aligned.m16n8k16.row.col.f32.bf16.bf16.f32 "
        "{%0,%1,%2,%3}, {%4,%5,%6,%7}, {%8,%9}, {%0,%1,%2,%3};"
        : "+f"(d[0]), "+f"(d[1]), "+f"(d[2]), "+f"(d[3])
        : "r"(a[0]), "r"(a[1]), "r"(a[2]), "r"(a[3]), "r"(b[0]), "r"(b[1]));
}
__device__ __forceinline__ void mma1688_tf32(float* d, const uint32_t* a,
                                             const uint32_t* b) {
    asm volatile(
        "mma.sync.aligned.m16n8k8.row.col.f32.tf32.tf32.f32 "
        "{%0,%1,%2,%3}, {%4,%5,%6,%7}, {%8,%9}, {%0,%1,%2,%3};"
        : "+f"(d[0]), "+f"(d[1]), "+f"(d[2]), "+f"(d[3])
        : "r"(a[0]), "r"(a[1]), "r"(a[2]), "r"(a[3]), "r"(b[0]), "r"(b[1]));
}
__device__ __forceinline__ uint32_t sw128(uint32_t off) {
    return off ^ ((off >> 3) & 0x70);
}
__device__ __forceinline__ float tf32r(float x) {
    uint32_t u;
    asm("cvt.rna.tf32.f32 %0, %1;" : "=r"(u) : "f"(x));
    return __uint_as_float(u);
}
__device__ __forceinline__ uint32_t tf32b(float x) {
    uint32_t u;
    asm("cvt.rna.tf32.f32 %0, %1;" : "=r"(u) : "f"(x));
    return u;
}

// ---------------------------------------------------------------------------
// FUSED prologue: one launch.
//   blocks [0, RND_B)            : tf32 rounding of hidden -> g_ahf
//   blocks [RND_B, RND_B+WT_B)   : the 4 weight transposes (flattened 64x64x4)
// Each output word produced by instruction sequences identical to the prior
// separate kernels -> bitwise-identical results.
// ---------------------------------------------------------------------------
struct WTJob { const float* W; float* Y; int N; };

namespace {
constexpr int RND_B = (cM * cHID / 4) / 256;   // 8192 rounding blocks
constexpr int WT_B  = 64 * 64 * 4;             // 16384 transpose blocks
}

__global__ __launch_bounds__(256) void prologue_kernel(
    const float* __restrict__ X, float* __restrict__ Y,
    WTJob j0, WTJob j1, WTJob j2, WTJob j3, int K)
{
    if (blockIdx.x < RND_B) {
        size_t e = ((size_t)blockIdx.x * 256 + threadIdx.x) * 4;
        float4 x = *(const float4*)(X + e);
        x.x = tf32r(x.x); x.y = tf32r(x.y); x.z = tf32r(x.z); x.w = tf32r(x.w);
        *(float4*)(Y + e) = x;
    } else {
        const int vb = blockIdx.x - RND_B;
        const int z  = vb >> 12;                 // 0..3 (4096 blocks per job)
        const WTJob j = (z == 0) ? j0 : (z == 1) ? j1 : (z == 2) ? j2 : j3;
        const int n0 = (vb & 63) * 32;
        if (n0 >= j.N) return;
        const int k0 = ((vb >> 6) & 63) * 32;
        const int tx = threadIdx.x & 31;
        const int ty = threadIdx.x >> 5;
        __shared__ float t[32][33];
#pragma unroll
        for (int i = 0; i < 32; i += 8)
            t[ty + i][tx] = j.W[(size_t)(k0 + ty + i) * j.N + n0 + tx];
        __syncthreads();
#pragma unroll
        for (int i = 0; i < 32; i += 8) {
            int n = n0 + ty + i;
            int k = k0 + tx;
            j.Y[(size_t)n * K + k] = tf32r(t[tx][ty + i]);
        }
    }
}

// ---------------------------------------------------------------------------
// FUSED post-QKV prep: one launch.
//   blocks [0, NRB)          : RMSNorm + RoPE + hi/lo bf16 split (warp/head)
//   blocks [NRB, NRB + NVB)  : V^T transpose tiles (tf32-rounded)
// ---------------------------------------------------------------------------
namespace {
constexpr int NRB = cM * 24 / 8;          // 12288 norm/rope blocks
constexpr int NVB = (cS / 32) * (cHD / 32) * (cB * cNKV);  // 4096 vT blocks
}

__global__ __launch_bounds__(256) void postqkv_prep_kernel(
    const float* __restrict__ cosp, const float* __restrict__ sinp,
    const float* __restrict__ qw,   const float* __restrict__ kw,
    float* __restrict__ vt)
{
    if (blockIdx.x < NRB) {
        const int wid  = threadIdx.x >> 5;
        const int lane = threadIdx.x & 31;
        const int gslot = blockIdx.x * 8 + wid;
        const int bs   = gslot / 24;
        const int slot = gslot - bs * 24;
        const int b    = bs >> 11;
        const int s    = bs & 2047;

        const float* src;
        const float* w;
        __nv_bfloat16 *dhi, *dlo;
        if (slot < 16) {
            src = g_qkv + (size_t)bs * cNQKV + slot * cHD;
            w = qw;
            size_t dst = ((size_t)(b * cNH + slot) * cS + s) * cHD;
            dhi = g_q2hi + dst; dlo = g_q2lo + dst;
        } else {
            src = g_qkv + (size_t)bs * cNQKV + 2048 + (slot - 16) * cHD;
            w = kw;
            size_t dst = ((size_t)(b * cNKV + (slot - 16)) * cS + s) * cHD;
            dhi = g_k2hi + dst; dlo = g_k2lo + dst;
        }

        float x[4];
#pragma unroll
        for (int i = 0; i < 4; i++) x[i] = src[lane + 32 * i];

        float v = x[0] * x[0] + x[1] * x[1] + x[2] * x[2] + x[3] * x[3];
#pragma unroll
        for (int o = 16; o; o >>= 1) v += __shfl_xor_sync(0xffffffffu, v, o);
        const float rs = rsqrtf(v * (1.f / cHD) + cEPS);

        float xn[4];
#pragma unroll
        for (int i = 0; i < 4; i++) xn[i] = x[i] * rs * w[lane + 32 * i];

#pragma unroll
        for (int i = 0; i < 4; i++) {
            const int d = lane + 32 * i;
            const float other = (i < 2) ? -xn[i + 2] : xn[i - 2];
            const float cv = cosp[(size_t)bs * cHD + d];
            const float sv = sinp[(size_t)bs * cHD + d];
            const float val = xn[i] * cv + other * sv;
            const __nv_bfloat16 hi = __float2bfloat16(val);
            dhi[d] = hi;
            dlo[d] = __float2bfloat16(val - __bfloat162float(hi));
        }
    } else {
        const int vb = blockIdx.x - NRB;
        const int s0 = (vb & 63) * 32;
        const int d0 = ((vb >> 6) & 3) * 32;
        const int bk = vb >> 8;
        const int b  = bk >> 3;
        const int kvh = bk & 7;
        const int tx = threadIdx.x & 31;
        const int ty = threadIdx.x >> 5;

        __shared__ float t[32][33];
#pragma unroll
        for (int i = 0; i < 32; i += 8)
            t[ty + i][tx] = g_qkv[(size_t)(b * cS + s0 + ty + i) * cNQKV +
                                  3072 + kvh * cHD + d0 + tx];
        __syncthreads();
#pragma unroll
        for (int i = 0; i < 32; i += 8)
            vt[((size_t)bk * cHD + d0 + ty + i) * cS + s0 + tx] =
                tf32r(t[tx][ty + i]);
    }
}

// ---------------------------------------------------------------------------
// TF32 HMMA GEMM: C[M,N] = A[M,K] @ B[N,K]^T (row-major fp32, tf32-prerounded)
// CTA tile 128x256, BK=32, 4-stage cp.async, SW128, warp tile 64x64.
// ---------------------------------------------------------------------------
namespace {
constexpr int GBM = 128, GBN = 256, GBK = 32;
constexpr int NSTAGE = 4;
constexpr int A_BYTES = GBM * GBK * 4;              // 16KB
constexpr int B_BYTES = GBN * GBK * 4;              // 32KB
constexpr int STAGE_BYTES = A_BYTES + B_BYTES;      // 48KB
constexpr int GEMM_SMEM   = NSTAGE * STAGE_BYTES;   // 192KB
}

__device__ __forceinline__ void gemm_load_stage(
    const float* __restrict__ Ag, const float* __restrict__ Bg,
    int K, int it, uint32_t stage_base, int tid)
{
#pragma unroll
    for (int i = 0; i < 4; i++) {
        int idx = tid + (i << 8);
        int row = idx >> 3;
        int c4  = idx & 7;
        uint32_t sw = sw128((uint32_t)(row * 128 + c4 * 16));
        cp_async16(stage_base + sw,
                   Ag + (size_t)row * K + (size_t)it * GBK + c4 * 4);
    }
#pragma unroll
    for (int i = 0; i < 8; i++) {
        int idx = tid + (i << 8);
        int row = idx >> 3;
        int c4  = idx & 7;
        uint32_t sw = sw128((uint32_t)(row * 128 + c4 * 16));
        cp_async16(stage_base + A_BYTES + sw,
                   Bg + (size_t)row * K + (size_t)it * GBK + c4 * 4);
    }
}

__global__ __launch_bounds__(256, 1)
void gemm_tf32_kernel(const float* __restrict__ A,
                      const float* __restrict__ B,
                      float* __restrict__ C, int M, int N, int K)
{
    extern __shared__ char smraw[];
    const uint32_t sbase = smem_u32(smraw);

    const int tid  = threadIdx.x;
    const int wid  = tid >> 5;
    const int lane = tid & 31;
    const int m0 = blockIdx.y * GBM;
    const int n0 = blockIdx.x * GBN;
    const int mw = (wid >> 2) * 64;
    const int nw = (wid & 3) * 64;

    const float* Ag = A + (size_t)m0 * K;
    const float* Bg = B + (size_t)n0 * K;
    const int KITERS = K / GBK;

    float acc[4][8][4];
#pragma unroll
    for (int i = 0; i < 4; i++)
#pragma unroll
        for (int j = 0; j < 8; j++)
#pragma unroll
            for (int r = 0; r < 4; r++) acc[i][j][r] = 0.f;

    const int a_row = lane & 15;
    const int a_cb  = (lane >> 4) * 16;
    const int b_row = (lane & 7) + ((lane >> 4) & 1) * 8;
    const int b_cb  = ((lane >> 3) & 1) * 16;

#pragma unroll
    for (int s = 0; s < NSTAGE - 1; s++) {
        gemm_load_stage(Ag, Bg, K, s, sbase + s * STAGE_BYTES, tid);
        CP_COMMIT();
    }

    for (int it = 0; it < KITERS; ++it) {
        CP_WAIT(NSTAGE - 2);
        __syncthreads();

        int nx = it + NSTAGE - 1;
        if (nx < KITERS)
            gemm_load_stage(Ag, Bg, K, nx,
                            sbase + (nx % NSTAGE) * STAGE_BYTES, tid);
        CP_COMMIT();

        const uint32_t sa = sbase + (it % NSTAGE) * STAGE_BYTES;
        const uint32_t sb = sa + A_BYTES;

#pragma unroll
        for (int ks = 0; ks < 4; ks++) {
            uint32_t af[4][4], bf[4][4];
#pragma unroll
            for (int mi = 0; mi < 4; mi++) {
                uint32_t off = (uint32_t)((mw + 16 * mi + a_row) * 128 +
                                          ks * 32 + a_cb);
                ldm_x4(af[mi], sa + sw128(off));
            }
#pragma unroll
            for (int njp = 0; njp < 4; njp++) {
                uint32_t off = (uint32_t)((nw + 16 * njp + b_row) * 128 +
                                          ks * 32 + b_cb);
                ldm_x4(bf[njp], sb + sw128(off));
            }
#pragma unroll
            for (int mi = 0; mi < 4; mi++)
#pragma unroll
                for (int njp = 0; njp < 4; njp++) {
                    mma1688_tf32(acc[mi][2 * njp],     af[mi], bf[njp]);
                    mma1688_tf32(acc[mi][2 * njp + 1], af[mi], bf[njp] + 2);
                }
        }
    }

    const int g = lane >> 2;
    const int t = lane & 3;
#pragma unroll
    for (int mi = 0; mi < 4; mi++) {
#pragma unroll
        for (int nj = 0; nj < 8; nj++) {
            int r0 = m0 + mw + 16 * mi + g;
            int cc = n0 + nw + 8 * nj + t * 2;
            *(float2*)(C + (size_t)r0 * N + cc) =
                make_float2(acc[mi][nj][0], acc[mi][nj][1]);
            *(float2*)(C + (size_t)(r0 + 8) * N + cc) =
                make_float2(acc[mi][nj][2], acc[mi][nj][3]);
        }
    }
}

// ---------------------------------------------------------------------------
// TWO-PASS single-kernel MMA attention.
// Pass 1: K-only, FOUR-stage pipeline (V space reused), QK + exp, accumulate l.
// Pass 2: K+V two-stage, recompute QK/exp, store normalized weights once,
//         PV tf32 via K-row-permute trick, output scaled by inv.
// ---------------------------------------------------------------------------
namespace {
constexpr int KTB = 64 * 272;
constexpr int VTB = 128 * 272;
constexpr int KVSTAGE = 2 * KTB + VTB;
constexpr int K4STAGE = 2 * KTB;                   // pass-1 K-only stage
constexpr int ATTN_SMEM = 4 * KTB + 2 * KVSTAGE;   // 208896 (4 K4 stages fit)
__device__ __constant__ int c_kperm[8] = {0, 2, 4, 6, 1, 3, 5, 7};
}

__global__ __launch_bounds__(256, 1)
void attn_mma_kernel(const __nv_bfloat16* __restrict__ qhi_g,
                     const __nv_bfloat16* __restrict__ qlo_g,
                     const __nv_bfloat16* __restrict__ khi_g,
                     const __nv_bfloat16* __restrict__ klo_g,
                     const float* __restrict__ vt_g,
                     float* __restrict__ wout,
                     float* __restrict__ outp,
                     int write_w)
{
    extern __shared__ char smraw[];
    const uint32_t uQ  = smem_u32(smraw);
    const uint32_t uKV = uQ + 4 * KTB;

    const int tid  = threadIdx.x;
    const int wid  = tid >> 5;
    const int lane = tid & 31;
    const int qt  = gridDim.y - 1 - blockIdx.y;    // heavy-first
    const int bkv = blockIdx.x;
    const int b   = bkv >> 3;
    const int kvh = bkv & 7;
    const int hs  = wid >> 2;
    const int h   = kvh * 2 + hs;
    const int wr  = (wid & 3) * 16;
    const int q0  = qt * 64;
    const int g   = lane >> 2;
    const int t   = lane & 3;

    // ---- Q tiles (4: h0hi, h0lo, h1hi, h1lo)
    {
        const size_t qrow = ((size_t)(b * cNH + kvh * 2) * cS + q0) * cHD;
        const int row = (tid >> 4);
        const int c   = tid & 15;
#pragma unroll
        for (int i = 0; i < 16; i++) {
            const int tile = i >> 2;
            const int rr = (i & 3) * 16 + row;
            const __nv_bfloat16* base = (tile & 1) ? qlo_g : qhi_g;
            const __nv_bfloat16* src = base + qrow +
                (size_t)(tile >> 1) * cS * cHD + (size_t)rr * cHD + c * 8;
            cp_async16(uQ + tile * KTB + rr * 272 + c * 16, src);
        }
    }
    CP_COMMIT();

    const size_t krow0 = ((size_t)(b * cNKV + kvh) * cS) * cHD;
    const size_t vbase = ((size_t)(b * cNKV + kvh) * cHD) * cS;
    const int lrow = (tid >> 4);
    const int lc   = tid & 15;

#define LOAD_K_AT(kt_, ubase_)                                                \
    do {                                                                      \
        const size_t krow = krow0 + (size_t)((kt_) * 64) * cHD;               \
        _Pragma("unroll")                                                     \
        for (int i = 0; i < 8; i++) {                                         \
            const int tile = i >> 2;                                          \
            const int rr = (i & 3) * 16 + lrow;                               \
            const int srr = (rr & 0x38) | c_kperm[rr & 7];                    \
            const __nv_bfloat16* base = tile ? klo_g : khi_g;                 \
            cp_async16((ubase_) + tile * KTB + srr * 272 + lc * 16,           \
                       base + krow + (size_t)rr * cHD + lc * 8);              \
        }                                                                     \
    } while (0)

#define LOAD_V_AT(kt_, ubase_)                                                \
    do {                                                                      \
        _Pragma("unroll")                                                     \
        for (int i = 0; i < 8; i++) {                                         \
            const int dd = i * 16 + lrow;                                     \
            cp_async16((ubase_) + 2 * KTB + dd * 272 + lc * 16,               \
                       vt_g + vbase + (size_t)dd * cS + (kt_) * 64 + lc * 4); \
        }                                                                     \
    } while (0)

    const uint32_t qoff = (uint32_t)((wr + (lane & 15)) * 272 + (lane >> 4) * 16);
    const uint32_t koff = (uint32_t)(((lane & 7) + ((lane >> 4) & 1) * 8) * 272 +
                                     ((lane >> 3) & 1) * 16);
    const uint32_t voff = (uint32_t)(((lane & 7) + ((lane >> 4) & 1) * 8) * 272 +
                                     ((lane >> 3) & 1) * 16);
    const uint32_t uQh = uQ + hs * 2 * KTB;
    const uint32_t uQl = uQh + KTB;

    float l0 = 0.f, l1 = 0.f;

    // ============ PASS 1: l accumulation (K only, 4-stage pipeline) ========
#pragma unroll
    for (int s = 0; s < 3; s++) {
        if (s <= qt) LOAD_K_AT(s, uKV + s * K4STAGE);
        CP_COMMIT();
    }

    for (int kt = 0; kt <= qt; kt++) {
        CP_WAIT(2);
        __syncthreads();

        const int nx = kt + 3;
        if (nx <= qt) LOAD_K_AT(nx, uKV + (nx & 3) * K4STAGE);
        CP_COMMIT();

        const uint32_t ust  = uKV + (kt & 3) * K4STAGE;
        const uint32_t ukhi = ust;
        const uint32_t uklo = ust + KTB;

        float sacc[8][4];
#pragma unroll
        for (int i = 0; i < 8; i++)
#pragma unroll
            for (int r = 0; r < 4; r++) sacc[i][r] = 0.f;

#pragma unroll
        for (int kk = 0; kk < 8; kk++) {
            uint32_t qh[4], ql[4];
            ldm_x4(qh, uQh + qoff + kk * 32);
            ldm_x4(ql, uQl + qoff + kk * 32);
#pragma unroll
            for (int njp = 0; njp < 4; njp++) {
                uint32_t kb[4];
                ldm_x4(kb, ukhi + njp * (16 * 272) + koff + kk * 32);
                mma16816(sacc[2 * njp],     qh, kb);
                mma16816(sacc[2 * njp + 1], qh, kb + 2);
                mma16816(sacc[2 * njp],     ql, kb);
                mma16816(sacc[2 * njp + 1], ql, kb + 2);
            }
#pragma unroll
            for (int njp = 0; njp < 4; njp++) {
                uint32_t kb[4];
                ldm_x4(kb, uklo + njp * (16 * 272) + koff + kk * 32);
                mma16816(sacc[2 * njp],     qh, kb);
                mma16816(sacc[2 * njp + 1], qh, kb + 2);
            }
        }

        const bool diag = (kt == qt);
#pragma unroll
        for (int nj = 0; nj < 8; nj++) {
            float p0 = __expf(sacc[nj][0] * cSCALE);
            float p1 = __expf(sacc[nj][1] * cSCALE);
            float p2 = __expf(sacc[nj][2] * cSCALE);
            float p3 = __expf(sacc[nj][3] * cSCALE);
            if (diag) {
                const int col0 = nj * 8 + t;
                const int col1 = col0 + 4;
                const int rlo = wr + g, rhi = wr + 8 + g;
                if (col0 > rlo) p0 = 0.f;
                if (col1 > rlo) p1 = 0.f;
                if (col0 > rhi) p2 = 0.f;
                if (col1 > rhi) p3 = 0.f;
            }
            l0 += p0 + p1;
            l1 += p2 + p3;
        }
    }
    CP_WAIT(0);          // drain ledger (incl. empty tail groups)
    __syncthreads();

    l0 += __shfl_xor_sync(0xffffffffu, l0, 1);
    l0 += __shfl_xor_sync(0xffffffffu, l0, 2);
    l1 += __shfl_xor_sync(0xffffffffu, l1, 1);
    l1 += __shfl_xor_sync(0xffffffffu, l1, 2);
    const float inv0 = 1.f / l0;
    const float inv1 = 1.f / l1;

    // =================== PASS 2: weights (normalized) + PV =================
    float oacc[16][4];
#pragma unroll
    for (int i = 0; i < 16; i++)
#pragma unroll
        for (int r = 0; r < 4; r++) oacc[i][r] = 0.f;

    LOAD_K_AT(0, uKV);
    LOAD_V_AT(0, uKV);
    CP_COMMIT();

    for (int kt = 0; kt <= qt; kt++) {
        if (kt < qt) {
            const uint32_t un = uKV + ((kt + 1) & 1) * KVSTAGE;
            LOAD_K_AT(kt + 1, un);
            LOAD_V_AT(kt + 1, un);
            CP_COMMIT();
            CP_WAIT(1);
        } else {
            CP_WAIT(0);
        }
        __syncthreads();

        const uint32_t ust  = uKV + (kt & 1) * KVSTAGE;
        const uint32_t ukhi = ust;
        const uint32_t uklo = ust + KTB;
        const uint32_t uvt  = ust + 2 * KTB;

        float sacc[8][4];
#pragma unroll
        for (int i = 0; i < 8; i++)
#pragma unroll
            for (int r = 0; r < 4; r++) sacc[i][r] = 0.f;

#pragma unroll
        for (int kk = 0; kk < 8; kk++) {
            uint32_t qh[4], ql[4];
            ldm_x4(qh, uQh + qoff + kk * 32);
            ldm_x4(ql, uQl + qoff + kk * 32);
#pragma unroll
            for (int njp = 0; njp < 4; njp++) {
                uint32_t kb[4];
                ldm_x4(kb, ukhi + njp * (16 * 272) + koff + kk * 32);
                mma16816(sacc[2 * njp],     qh, kb);
                mma16816(sacc[2 * njp + 1], qh, kb + 2);
                mma16816(sacc[2 * njp],     ql, kb);
                mma16816(sacc[2 * njp + 1], ql, kb + 2);
            }
#pragma unroll
            for (int njp = 0; njp < 4; njp++) {
                uint32_t kb[4];
                ldm_x4(kb, uklo + njp * (16 * 272) + koff + kk * 32);
                mma16816(sacc[2 * njp],     qh, kb);
                mma16816(sacc[2 * njp + 1], qh, kb + 2);
            }
        }

        const bool diag = (kt == qt);
        uint32_t pt[8][4];
#pragma unroll
        for (int nj = 0; nj < 8; nj++) {
            float p0 = __expf(sacc[nj][0] * cSCALE);
            float p1 = __expf(sacc[nj][1] * cSCALE);
            float p2 = __expf(sacc[nj][2] * cSCALE);
            float p3 = __expf(sacc[nj][3] * cSCALE);
            if (diag) {
                const int col0 = nj * 8 + t;
                const int col1 = col0 + 4;
                const int rlo = wr + g, rhi = wr + 8 + g;
                if (col0 > rlo) p0 = 0.f;
                if (col1 > rlo) p1 = 0.f;
                if (col0 > rhi) p2 = 0.f;
                if (col1 > rhi) p3 = 0.f;
            }
            if (write_w) {
                float* w0 = wout + ((size_t)(b * cNH + h) * cS + q0 + wr + g) * cS
                            + kt * 64 + nj * 8 + t;
                w0[0] = p0 * inv0;
                w0[4] = p1 * inv0;
                float* w1 = w0 + 8 * (size_t)cS;
                w1[0] = p2 * inv1;
                w1[4] = p3 * inv1;
            }
            pt[nj][0] = tf32b(p0);
            pt[nj][1] = tf32b(p2);
            pt[nj][2] = tf32b(p1);
            pt[nj][3] = tf32b(p3);
        }

#pragma unroll
        for (int nj = 0; nj < 8; nj++) {
#pragma unroll
            for (int nd2 = 0; nd2 < 8; nd2++) {
                uint32_t vb[4];
                ldm_x4(vb, uvt + nd2 * (16 * 272) + nj * 32 + voff);
                mma1688_tf32(oacc[2 * nd2],     pt[nj], vb);
                mma1688_tf32(oacc[2 * nd2 + 1], pt[nj], vb + 2);
            }
        }
        __syncthreads();
    }

    // ---- PV output (normalized, tf32-rounded for the Wo GEMM) ----
#pragma unroll
    for (int nd = 0; nd < 16; nd++) {
        const int col = nd * 8 + 2 * t;
        float* o0 = outp + ((size_t)(b * cS + q0 + wr + g) * cNH + h) * cHD + col;
        float* o1 = outp + ((size_t)(b * cS + q0 + wr + 8 + g) * cNH + h) * cHD + col;
        *(float2*)o0 = make_float2(tf32r(oacc[nd][0] * inv0),
                                   tf32r(oacc[nd][1] * inv0));
        *(float2*)o1 = make_float2(tf32r(oacc[nd][2] * inv1),
                                   tf32r(oacc[nd][3] * inv1));
    }

    // ---- zero the upper-triangle tail of this CTA's 128 rows ----
    if (write_w) {
        const int zc = cS - (q0 + 64);
        if (zc > 0) {
            const int z4 = zc >> 2;
            const int tot = 128 * z4;
            const float4 z = make_float4(0.f, 0.f, 0.f, 0.f);
            for (int i = tid; i < tot; i += 256) {
                const int r  = i / z4;
                const int c4 = i - r * z4;
                const int head = r >> 6;
                const int row  = r & 63;
                float* p = wout +
                    ((size_t)(b * cNH + kvh * 2 + head) * cS + q0 + row) * cS +
                    q0 + 64 + c4 * 4;
                *(float4*)p = z;
            }
        }
    }
}

// ---------------------------------------------------------------------------
// Launch (single stream)
// ---------------------------------------------------------------------------
extern "C" void kernel_launch(void* const* d_in, const int* in_sizes, int n_in,
                              void* d_out, int out_size)
{
    const float* hidden = (const float*)d_in[0];
    const float* cosp   = (const float*)d_in[1];
    const float* sinp   = (const float*)d_in[2];
    const float* wq  = (const float*)d_in[4];
    const float* wk  = (const float*)d_in[5];
    const float* wv  = (const float*)d_in[6];
    const float* wo  = (const float*)d_in[7];
    const float* qnw = (const float*)d_in[8];
    const float* knw = (const float*)d_in[9];

    float* out = (float*)d_out;
    const size_t n_attn = (size_t)cM * cHID;
    const size_t n_w    = (size_t)cB * cNH * cS * cS;
    const int write_w   = ((size_t)out_size >= n_attn + n_w) ? 1 : 0;
    float* weights = out + n_attn;

    float *pahf, *pqkv, *pa, *pwt, *pwot, *pvt;
    cudaGetSymbolAddress((void**)&pahf, g_ahf);
    cudaGetSymbolAddress((void**)&pqkv, g_qkv);
    cudaGetSymbolAddress((void**)&pa,   g_att);
    cudaGetSymbolAddress((void**)&pwt,  g_wt);
    cudaGetSymbolAddress((void**)&pwot, g_wot);
    cudaGetSymbolAddress((void**)&pvt,  g_vt);
    __nv_bfloat16 *pqh, *pql, *pkh, *pklo;
    cudaGetSymbolAddress((void**)&pqh,  g_q2hi);
    cudaGetSymbolAddress((void**)&pql,  g_q2lo);
    cudaGetSymbolAddress((void**)&pkh,  g_k2hi);
    cudaGetSymbolAddress((void**)&pklo, g_k2lo);

    static bool attr_done = false;
    if (!attr_done) {
        cudaFuncSetAttribute(gemm_tf32_kernel,
                             cudaFuncAttributeMaxDynamicSharedMemorySize, GEMM_SMEM);
        cudaFuncSetAttribute(attn_mma_kernel,
                             cudaFuncAttributeMaxDynamicSharedMemorySize, ATTN_SMEM);
        attr_done = true;
    }

    // --- fused prologue: tf32-round hidden AND all 4 weight transposes ---
    {
        WTJob j0 = { wq, pwt,                          2048 };
        WTJob j1 = { wk, pwt + (size_t)2048 * cHID,    1024 };
        WTJob j2 = { wv, pwt + (size_t)3072 * cHID,    1024 };
        WTJob j3 = { wo, pwot,                         2048 };
        prologue_kernel<<<RND_B + WT_B, 256>>>(hidden, pahf,
                                               j0, j1, j2, j3, cHID);
    }

    // --- fused QKV projection (tf32) ---
    gemm_tf32_kernel<<<dim3(cNQKV / GBN, cM / GBM), 256, GEMM_SMEM>>>(
        pahf, pwt, pqkv, cM, cNQKV, cHID);

    // --- fused post-QKV prep: norm+rope+split AND V^T in ONE launch ---
    postqkv_prep_kernel<<<NRB + NVB, 256>>>(cosp, sinp, qnw, knw, pvt);

    // --- two-pass single-kernel MMA attention (weights written once) ---
    attn_mma_kernel<<<dim3(cB * cNKV, cS / 64), 256, ATTN_SMEM>>>(
        pqh, pql, pkh, pklo, pvt, weights, pa, write_w);

    // --- output projection (tf32) ---
    gemm_tf32_kernel<<<dim3(cHID / GBN, cM / GBM), 256, GEMM_SMEM>>>(
        pa, pwot, out, cM, cHID, cHID);
}